// round 8
// baseline (speedup 1.0000x reference)
#include <cuda_runtime.h>
#include <cuda_bf16.h>
#include <math.h>
#include <stdint.h>

// ---------------- problem constants ----------------
#define Bq   4
#define Nn_  1024
#define DIM  512
#define Hh   8
#define DH   64
#define MLPD 2048
#define ROWS (Bq * Nn_)            // 4096 token rows
#define HB   (Hh * Bq)             // 32 attention batches
#define EPS  1e-5f
#define MST  80
#define KSPLIT 4

// ---------------- tf32 mma helpers ----------------
__device__ __forceinline__ float t32f(float x){
    unsigned r; asm("cvt.rna.tf32.f32 %0,%1;" : "=r"(r) : "f"(x));
    return __uint_as_float(r);
}
__device__ __forceinline__ void mma8(float* c, const unsigned* a, const unsigned* b){
    asm("mma.sync.aligned.m16n8k8.row.col.f32.tf32.tf32.f32 "
        "{%0,%1,%2,%3},{%4,%5,%6,%7},{%8,%9},{%0,%1,%2,%3};"
        : "+f"(c[0]), "+f"(c[1]), "+f"(c[2]), "+f"(c[3])
        : "r"(a[0]), "r"(a[1]), "r"(a[2]), "r"(a[3]), "r"(b[0]), "r"(b[1]));
}

// ---------------- device scratch (no allocs allowed) ----------------
__device__ float g_xn [3 * ROWS * DIM];
__device__ float g_f  [3 * ROWS * DIM];
__device__ float g_ao [ROWS * DIM];
__device__ float g_q2 [ROWS * DIM];
__device__ float g_xn2[ROWS * DIM];
__device__ float g_u  [ROWS * MLPD];
__device__ float g_Mp [KSPLIT][HB][128][MST];
__device__ float g_Mr [HB][128][MST];
__device__ float g_qinv [HB * Nn_];
__device__ float g_qmean[HB * Nn_];
__device__ float g_qvar [HB * Nn_];
__device__ float g_kinv [HB * Nn_];
__device__ float g_kmean[HB * Nn_];
__device__ float g_kvar [HB * Nn_];
__device__ float g_hg [2 * Hh * DH];
__device__ float g_w3 [Hh * 3];

// ---------------- fused layernorm of q,k,v (also zeroes g_hg) ----------------
__global__ void ln3_kernel(const float* __restrict__ q, const float* __restrict__ k,
                           const float* __restrict__ v, const float* __restrict__ g,
                           const float* __restrict__ bb, float* __restrict__ y)
{
    int row = blockIdx.x;                 // 0 .. 3*ROWS-1
    int tid = threadIdx.x;
    if (blockIdx.x < 4) g_hg[blockIdx.x * 256 + tid] = 0.f;
    int which = row >> 12;
    const float* x = (which == 0) ? q : (which == 1) ? k : v;
    const float* xr = x + (size_t)(row & (ROWS - 1)) * DIM;
    float v0 = xr[tid], v1 = xr[tid + 256];
    float s = v0 + v1, ss = v0 * v0 + v1 * v1;
    __shared__ float rs[256], rss[256];
    rs[tid] = s; rss[tid] = ss;
    __syncthreads();
    for (int off = 128; off > 0; off >>= 1) {
        if (tid < off) { rs[tid] += rs[tid + off]; rss[tid] += rss[tid + off]; }
        __syncthreads();
    }
    float mean = rs[0] * (1.f / DIM);
    float var  = rss[0] * (1.f / DIM) - mean * mean;
    float inv  = rsqrtf(var + EPS);
    float* yr = y + (size_t)row * DIM;
    yr[tid]       = (v0 - mean) * inv * g[tid]       + bb[tid];
    yr[tid + 256] = (v1 - mean) * inv * g[tid + 256] + bb[tid + 256];
}

// ---------------- layernorm (single tensor, for LN2) ----------------
__global__ void ln_kernel(const float* __restrict__ x, const float* __restrict__ g,
                          const float* __restrict__ bb, float* __restrict__ y)
{
    int row = blockIdx.x;
    int tid = threadIdx.x;
    const float* xr = x + (size_t)row * DIM;
    float v0 = xr[tid], v1 = xr[tid + 256];
    float s = v0 + v1, ss = v0 * v0 + v1 * v1;
    __shared__ float rs[256], rss[256];
    rs[tid] = s; rss[tid] = ss;
    __syncthreads();
    for (int off = 128; off > 0; off >>= 1) {
        if (tid < off) { rs[tid] += rs[tid + off]; rss[tid] += rss[tid + off]; }
        __syncthreads();
    }
    float mean = rs[0] * (1.f / DIM);
    float var  = rss[0] * (1.f / DIM) - mean * mean;
    float inv  = rsqrtf(var + EPS);
    float* yr = y + (size_t)row * DIM;
    yr[tid]       = (v0 - mean) * inv * g[tid]       + bb[tid];
    yr[tid + 256] = (v1 - mean) * inv * g[tid + 256] + bb[tid + 256];
}

// ================ tf32 mma GEMM, fragment-layout smem ================
// C = A[M,K] @ W[N,K]^T.  CTA tile (MT*32) x 128, BK=16, double-buffered.
// MODE: 2 +bias+gelu, 3 +bias+residual, 4 plain+tf32-round + fused q/k stats
template <int MODE, int MT>
__global__ void __launch_bounds__(256) tmm2_kernel(
    const float* __restrict__ A, const float* __restrict__ W,
    const float* __restrict__ bias, const float* __restrict__ res,
    float* __restrict__ C, int M, int Nc, int K)
{
    __shared__ __align__(16) float Af[2][MT * 2 * 2 * 128];
    __shared__ __align__(16) float Bf[2][16 * 2 * 64];
    __shared__ float sred[(MODE == 4) ? 8 * MT * 8 * 4 : 4];
    __shared__ float colsum[(MODE == 4) ? 128 : 4];
    const int tid = threadIdx.x;
    const int lane = tid & 31, warp = tid >> 5;
    const int wm = (warp >> 2) * (MT * 16);
    const int wn = (warp & 3) * 32;
    const int m0 = blockIdx.y * (MT * 32), n0 = blockIdx.x * 128;
    const int g = lane >> 2, q4 = lane & 3;

    if (MODE == 4 && tid < 128) colsum[tid] = 0.f;

    float acc[MT][4][4];
#pragma unroll
    for (int i = 0; i < MT; i++)
#pragma unroll
        for (int j = 0; j < 4; j++)
#pragma unroll
            for (int c = 0; c < 4; c++) acc[i][j][c] = 0.f;

    // ---- staging thread mappings ----
    const int bsrow = tid >> 1, bkc = tid & 1;
    const float* Wp = W + (size_t)(n0 + bsrow) * K + bkc * 8;
    const int bnt = bsrow >> 3, bg = bsrow & 7;
    const int asrow = (MT == 4) ? (tid >> 1) : (tid >> 2);
    const int akoff = (MT == 4) ? ((tid & 1) * 8) : ((tid & 3) * 4);
    const float* Ap = A + (size_t)(m0 + asrow) * K + akoff;
    const int amt = asrow >> 4, arl = asrow & 15, ag = arl & 7, arb = arl >> 3;
    const int akc = akoff >> 3;
    const int akh = (akoff & 7) >> 2;

    float4 av0, av1, wv0, wv1;

    av0 = *(const float4*)(Ap);
    if (MT == 4) av1 = *(const float4*)(Ap + 4);
    wv0 = *(const float4*)(Wp);
    wv1 = *(const float4*)(Wp + 4);
    {
        float* ab = &Af[0][(amt * 2 + akc) * 128];
        if (MT == 4) {
            float va[8] = {av0.x, av0.y, av0.z, av0.w, av1.x, av1.y, av1.z, av1.w};
#pragma unroll
            for (int t = 0; t < 8; t++) {
                int kk = (t + ag) & 7;
                ab[(ag * 4 + (kk & 3)) * 4 + arb + 2 * (kk >> 2)] = t32f(va[kk]);
            }
        } else {
            float va[4] = {av0.x, av0.y, av0.z, av0.w};
#pragma unroll
            for (int t = 0; t < 4; t++) {
                int qq = (t + ag) & 3;
                ab[(ag * 4 + qq) * 4 + arb + 2 * akh] = t32f(va[qq]);
            }
        }
        float* bb2 = &Bf[0][(bnt * 2 + bkc) * 64 + bg * 8];
        *(float4*)&bb2[0] = make_float4(t32f(wv0.x), t32f(wv1.x), t32f(wv0.y), t32f(wv1.y));
        *(float4*)&bb2[4] = make_float4(t32f(wv0.z), t32f(wv1.z), t32f(wv0.w), t32f(wv1.w));
    }

    int buf = 0;
    for (int k0 = 16; k0 <= K; k0 += 16) {
        __syncthreads();
        const bool more = (k0 < K);
        if (more) {
            av0 = *(const float4*)(Ap + k0);
            if (MT == 4) av1 = *(const float4*)(Ap + k0 + 4);
            wv0 = *(const float4*)(Wp + k0);
            wv1 = *(const float4*)(Wp + k0 + 4);
        }
#pragma unroll
        for (int kc = 0; kc < 2; kc++) {
            float4 afv[MT]; float2 bfv[4];
#pragma unroll
            for (int mt = 0; mt < MT; mt++)
                afv[mt] = *(const float4*)&Af[buf][((((wm >> 4) + mt) * 2 + kc) * 128) + lane * 4];
#pragma unroll
            for (int nt = 0; nt < 4; nt++)
                bfv[nt] = *(const float2*)&Bf[buf][((((wn >> 3) + nt) * 2 + kc) * 64) + lane * 2];
#pragma unroll
            for (int mt = 0; mt < MT; mt++)
#pragma unroll
                for (int nt = 0; nt < 4; nt++)
                    mma8(acc[mt][nt], (const unsigned*)&afv[mt], (const unsigned*)&bfv[nt]);
        }
        if (more) {
            const int nb = buf ^ 1;
            float* ab = &Af[nb][(amt * 2 + akc) * 128];
            if (MT == 4) {
                float va[8] = {av0.x, av0.y, av0.z, av0.w, av1.x, av1.y, av1.z, av1.w};
#pragma unroll
                for (int t = 0; t < 8; t++) {
                    int kk = (t + ag) & 7;
                    ab[(ag * 4 + (kk & 3)) * 4 + arb + 2 * (kk >> 2)] = t32f(va[kk]);
                }
            } else {
                float va[4] = {av0.x, av0.y, av0.z, av0.w};
#pragma unroll
                for (int t = 0; t < 4; t++) {
                    int qq = (t + ag) & 3;
                    ab[(ag * 4 + qq) * 4 + arb + 2 * akh] = t32f(va[qq]);
                }
            }
            float* bb2 = &Bf[nb][(bnt * 2 + bkc) * 64 + bg * 8];
            *(float4*)&bb2[0] = make_float4(t32f(wv0.x), t32f(wv1.x), t32f(wv0.y), t32f(wv1.y));
            *(float4*)&bb2[4] = make_float4(t32f(wv0.z), t32f(wv1.z), t32f(wv0.w), t32f(wv1.w));
        }
        buf ^= 1;
    }

    const int which = m0 >> 12;   // proj only: 0=q, 1=k, 2=v

    // ---- epilogue ----
#pragma unroll
    for (int mt = 0; mt < MT; mt++) {
        const int row0 = m0 + wm + mt * 16 + g;
        float s0 = 0.f, ss0 = 0.f, s1 = 0.f, ss1 = 0.f;
#pragma unroll
        for (int nt = 0; nt < 4; nt++) {
            const int col = n0 + wn + nt * 8 + 2 * q4;
            float v0 = acc[mt][nt][0], v1 = acc[mt][nt][1];
            float v2 = acc[mt][nt][2], v3 = acc[mt][nt][3];
            if (MODE == 2 || MODE == 3) {
                float2 bv = *(const float2*)&bias[col];
                v0 += bv.x; v1 += bv.y; v2 += bv.x; v3 += bv.y;
            }
            if (MODE == 2) {
                v0 = 0.5f * v0 * (1.f + erff(v0 * 0.70710678118654752f));
                v1 = 0.5f * v1 * (1.f + erff(v1 * 0.70710678118654752f));
                v2 = 0.5f * v2 * (1.f + erff(v2 * 0.70710678118654752f));
                v3 = 0.5f * v3 * (1.f + erff(v3 * 0.70710678118654752f));
            }
            if (MODE == 3) {
                float2 r0 = *(const float2*)(res + (size_t)row0 * Nc + col);
                float2 r1 = *(const float2*)(res + (size_t)(row0 + 8) * Nc + col);
                v0 += r0.x; v1 += r0.y; v2 += r1.x; v3 += r1.y;
            }
            if (MODE == 4) {
                v0 = t32f(v0); v1 = t32f(v1); v2 = t32f(v2); v3 = t32f(v3);
                s0 += v0 + v1; ss0 += v0 * v0 + v1 * v1;
                s1 += v2 + v3; ss1 += v2 * v2 + v3 * v3;
                if (which < 2) {
                    atomicAdd(&colsum[wn + nt * 8 + 2 * q4],     v0 + v2);
                    atomicAdd(&colsum[wn + nt * 8 + 2 * q4 + 1], v1 + v3);
                }
            }
            *(float2*)(C + (size_t)row0 * Nc + col)       = make_float2(v0, v1);
            *(float2*)(C + (size_t)(row0 + 8) * Nc + col) = make_float2(v2, v3);
        }
        if (MODE == 4) {
            s0 += __shfl_xor_sync(0xffffffffu, s0, 1);  s0 += __shfl_xor_sync(0xffffffffu, s0, 2);
            ss0 += __shfl_xor_sync(0xffffffffu, ss0, 1); ss0 += __shfl_xor_sync(0xffffffffu, ss0, 2);
            s1 += __shfl_xor_sync(0xffffffffu, s1, 1);  s1 += __shfl_xor_sync(0xffffffffu, s1, 2);
            ss1 += __shfl_xor_sync(0xffffffffu, ss1, 1); ss1 += __shfl_xor_sync(0xffffffffu, ss1, 2);
            if (q4 == 0) {
                float* sp = &sred[((warp * MT + mt) * 8 + g) * 4];
                sp[0] = s0; sp[1] = ss0; sp[2] = s1; sp[3] = ss1;
            }
        }
    }

    if (MODE == 4) {
        __syncthreads();
        if (which < 2) {
            if (tid < 128) atomicAdd(&g_hg[which * 512 + n0 + tid], colsum[tid]);
            // 256 row-stat entries: pair p (warps 2p,2p+1), mt, g, row-half rr
            const int p   = tid >> 6;
            const int mt2 = (tid >> 4) & 3;
            const int g2  = (tid >> 1) & 7;
            const int rr  = tid & 1;
            const int w0 = 2 * p;
            const float* e0 = &sred[((w0 * MT + mt2) * 8 + g2) * 4];
            const float* e1 = &sred[(((w0 + 1) * MT + mt2) * 8 + g2) * 4];
            float sA  = e0[2 * rr]     + e1[2 * rr];
            float ssA = e0[2 * rr + 1] + e1[2 * rr + 1];
            int row = m0 + (p >> 1) * 64 + mt2 * 16 + g2 + rr * 8;
            int lr2 = row & (ROWS - 1);
            int b3 = lr2 >> 10, n3 = lr2 & 1023;
            int head = (n0 >> 6) + (p & 1);
            int idx = (head * 4 + b3) * 1024 + n3;
            float mean = sA * (1.f / 64.f);
            float var  = (ssA - sA * sA * (1.f / 64.f)) * (1.f / 63.f);
            float inv  = rsqrtf(ssA);
            if (which == 0) { g_qinv[idx] = inv; g_qmean[idx] = mean; g_qvar[idx] = var; }
            else            { g_kinv[idx] = inv; g_kmean[idx] = mean; g_kvar[idx] = var; }
        }
    }
}

// ================ mbuild: Mcat[d'=128][e=72] = Vx^T @ Ax per hb (split-K) ======
__global__ void __launch_bounds__(256) mbuild_kernel()
{
    __shared__ float As[2][16][136];
    __shared__ float Bs[2][16][72];
    const int tid = threadIdx.x, lane = tid & 31, warp = tid >> 5;
    const int ks = blockIdx.x, hb = blockIdx.y, h = hb >> 2, b = hb & 3;
    const int base = hb * Nn_;
    const int g = lane >> 2, q4 = lane & 3;
    const int m0 = ks * (Nn_ / KSPLIT);

    const float* fk = g_f + (size_t)ROWS * DIM;
    const float* fv = g_f + 2 * (size_t)ROWS * DIM;

    float acc[9][4];
#pragma unroll
    for (int j = 0; j < 9; j++)
#pragma unroll
        for (int c = 0; c < 4; c++) acc[j][c] = 0.f;

    const int srow = tid >> 4;
    const int dc = (tid & 15) * 4;

    {
        int m = m0 + srow;
        float ki = g_kinv[base + m];
        float4 vv = *(const float4*)(fv + (size_t)(b*Nn_ + m)*DIM + h*DH + dc);
        float4 kk = *(const float4*)(fk + (size_t)(b*Nn_ + m)*DIM + h*DH + dc);
        float* ar = &As[0][srow][2*dc];
        ar[0] = vv.x; ar[1] = t32f(ki*vv.x);
        ar[2] = vv.y; ar[3] = t32f(ki*vv.y);
        ar[4] = vv.z; ar[5] = t32f(ki*vv.z);
        ar[6] = vv.w; ar[7] = t32f(ki*vv.w);
        *(float4*)&Bs[0][srow][dc] = kk;
        if (tid < 128) {
            int r = tid >> 3, s = tid & 7;
            int mm = m0 + r;
            float v = 0.f;
            if (s == 0) v = t32f(g_kvar [base + mm]);
            else if (s == 1) v = t32f(g_kmean[base + mm]);
            Bs[0][r][64 + s] = v;
        }
    }

    int buf = 0;
    const int KC = Nn_ / KSPLIT;
    for (int k0 = 16; k0 <= KC; k0 += 16) {
        __syncthreads();
        const bool more = (k0 < KC);
        float4 vv, kk; float ki = 0.f, xv = 0.f;
        if (more) {
            int m = m0 + k0 + srow;
            vv = *(const float4*)(fv + (size_t)(b*Nn_ + m)*DIM + h*DH + dc);
            kk = *(const float4*)(fk + (size_t)(b*Nn_ + m)*DIM + h*DH + dc);
            ki = g_kinv[base + m];
            if (tid < 128) {
                int r = tid >> 3, s = tid & 7;
                int mm = m0 + k0 + r;
                if (s == 0) xv = t32f(g_kvar [base + mm]);
                else if (s == 1) xv = t32f(g_kmean[base + mm]);
            }
        }
#pragma unroll
        for (int ks8 = 0; ks8 < 16; ks8 += 8) {
            unsigned af[4];
            const int mr = warp * 16 + g;
            af[0] = __float_as_uint(As[buf][ks8 + q4][mr]);
            af[1] = __float_as_uint(As[buf][ks8 + q4][mr + 8]);
            af[2] = __float_as_uint(As[buf][ks8 + 4 + q4][mr]);
            af[3] = __float_as_uint(As[buf][ks8 + 4 + q4][mr + 8]);
#pragma unroll
            for (int nt = 0; nt < 9; nt++) {
                unsigned bf[2];
                bf[0] = __float_as_uint(Bs[buf][ks8 + q4][nt * 8 + g]);
                bf[1] = __float_as_uint(Bs[buf][ks8 + 4 + q4][nt * 8 + g]);
                mma8(acc[nt], af, bf);
            }
        }
        if (more) {
            int nb = buf ^ 1;
            float* ar = &As[nb][srow][2*dc];
            ar[0] = vv.x; ar[1] = t32f(ki*vv.x);
            ar[2] = vv.y; ar[3] = t32f(ki*vv.y);
            ar[4] = vv.z; ar[5] = t32f(ki*vv.z);
            ar[6] = vv.w; ar[7] = t32f(ki*vv.w);
            *(float4*)&Bs[nb][srow][dc] = kk;
            if (tid < 128) {
                int r = tid >> 3, s = tid & 7;
                Bs[nb][r][64 + s] = xv;
            }
        }
        buf ^= 1;
    }

    const int row0 = warp * 16 + g;
#pragma unroll
    for (int nt = 0; nt < 9; nt++) {
        const int col = nt * 8 + 2 * q4;
        *(float2*)&g_Mp[ks][hb][row0][col]     = make_float2(acc[nt][0], acc[nt][1]);
        *(float2*)&g_Mp[ks][hb][row0 + 8][col] = make_float2(acc[nt][2], acc[nt][3]);
    }
}

// ---------------- reduce split-K partials ----------------
__global__ void mreduce_kernel()
{
    const int i = blockIdx.x * 256 + threadIdx.x;
    const float4* p0 = (const float4*)&g_Mp[0][0][0][0];
    const float4* p1 = (const float4*)&g_Mp[1][0][0][0];
    const float4* p2 = (const float4*)&g_Mp[2][0][0][0];
    const float4* p3 = (const float4*)&g_Mp[3][0][0][0];
    float4 a = p0[i], b = p1[i], c = p2[i], d = p3[i];
    ((float4*)&g_Mr[0][0][0])[i] = make_float4(a.x+b.x+c.x+d.x, a.y+b.y+c.y+d.y,
                                               a.z+b.z+c.z+d.z, a.w+b.w+c.w+d.w);
}

// ================ pgemm: O = combine(fq @ Mcat^T) per hb ================
__global__ void __launch_bounds__(256) pgemm_kernel()
{
    __shared__ float As[2][16][136];
    __shared__ float Bs[2][16][136];
    const int tid = threadIdx.x;
    const int lane = tid & 31, warp = tid >> 5;
    const int wm = (warp >> 2) * 64, wn = (warp & 3) * 32;
    const int hb = blockIdx.y, h = hb >> 2, b = hb & 3;
    const int q0 = blockIdx.x * 128;
    const int base = hb * Nn_;
    const int g = lane >> 2, q4 = lane & 3;

    const float* fq = g_f;

    float acc[4][4][4];
#pragma unroll
    for (int i = 0; i < 4; i++)
#pragma unroll
        for (int j = 0; j < 4; j++)
#pragma unroll
            for (int c = 0; c < 4; c++) acc[i][j][c] = 0.f;

    const int srow = tid >> 1, skc = (tid & 1) * 8;
    const float* Apt = fq + (size_t)(b * Nn_ + q0 + srow) * DIM + h * DH + skc;
    const float* Wpt = &g_Mr[hb][srow][skc];

    {
        float4 a0 = *(const float4*)(Apt);
        float4 a1 = *(const float4*)(Apt + 4);
        float4 w0 = *(const float4*)(Wpt);
        float4 w1 = *(const float4*)(Wpt + 4);
        As[0][skc+0][srow] = a0.x; As[0][skc+1][srow] = a0.y;
        As[0][skc+2][srow] = a0.z; As[0][skc+3][srow] = a0.w;
        As[0][skc+4][srow] = a1.x; As[0][skc+5][srow] = a1.y;
        As[0][skc+6][srow] = a1.z; As[0][skc+7][srow] = a1.w;
        Bs[0][skc+0][srow] = t32f(w0.x); Bs[0][skc+1][srow] = t32f(w0.y);
        Bs[0][skc+2][srow] = t32f(w0.z); Bs[0][skc+3][srow] = t32f(w0.w);
        Bs[0][skc+4][srow] = t32f(w1.x); Bs[0][skc+5][srow] = t32f(w1.y);
        Bs[0][skc+6][srow] = t32f(w1.z); Bs[0][skc+7][srow] = t32f(w1.w);
    }

    int buf = 0;
    for (int k0 = 16; k0 <= DH; k0 += 16) {
        __syncthreads();
        const bool more = (k0 < DH);
        float4 a0, a1, w0, w1;
        if (more) {
            a0 = *(const float4*)(Apt + k0);
            a1 = *(const float4*)(Apt + k0 + 4);
            w0 = *(const float4*)(Wpt + k0);
            w1 = *(const float4*)(Wpt + k0 + 4);
        }
#pragma unroll
        for (int ks = 0; ks < 16; ks += 8) {
            unsigned af[4][4], bf[4][2];
#pragma unroll
            for (int mt = 0; mt < 4; mt++) {
                int mr = wm + mt * 16 + g;
                af[mt][0] = __float_as_uint(As[buf][ks + q4][mr]);
                af[mt][1] = __float_as_uint(As[buf][ks + q4][mr + 8]);
                af[mt][2] = __float_as_uint(As[buf][ks + 4 + q4][mr]);
                af[mt][3] = __float_as_uint(As[buf][ks + 4 + q4][mr + 8]);
            }
#pragma unroll
            for (int nt = 0; nt < 4; nt++) {
                int nc = wn + nt * 8 + g;
                bf[nt][0] = __float_as_uint(Bs[buf][ks + q4][nc]);
                bf[nt][1] = __float_as_uint(Bs[buf][ks + 4 + q4][nc]);
            }
#pragma unroll
            for (int mt = 0; mt < 4; mt++)
#pragma unroll
                for (int nt = 0; nt < 4; nt++)
                    mma8(acc[mt][nt], af[mt], bf[nt]);
        }
        if (more) {
            int nb = buf ^ 1;
            As[nb][skc+0][srow] = a0.x; As[nb][skc+1][srow] = a0.y;
            As[nb][skc+2][srow] = a0.z; As[nb][skc+3][srow] = a0.w;
            As[nb][skc+4][srow] = a1.x; As[nb][skc+5][srow] = a1.y;
            As[nb][skc+6][srow] = a1.z; As[nb][skc+7][srow] = a1.w;
            Bs[nb][skc+0][srow] = t32f(w0.x); Bs[nb][skc+1][srow] = t32f(w0.y);
            Bs[nb][skc+2][srow] = t32f(w0.z); Bs[nb][skc+3][srow] = t32f(w0.w);
            Bs[nb][skc+4][srow] = t32f(w1.x); Bs[nb][skc+5][srow] = t32f(w1.y);
            Bs[nb][skc+6][srow] = t32f(w1.z); Bs[nb][skc+7][srow] = t32f(w1.w);
        }
        buf ^= 1;
    }

    const float cw = g_w3[h * 3 + 0], covw = g_w3[h * 3 + 1], vw = g_w3[h * 3 + 2];
#pragma unroll
    for (int mt = 0; mt < 4; mt++) {
        const int row0 = q0 + wm + mt * 16 + g;
        const float qi0 = g_qinv[base + row0],     qm0 = g_qmean[base + row0],     qv0 = g_qvar[base + row0];
        const float qi1 = g_qinv[base + row0 + 8], qm1 = g_qmean[base + row0 + 8], qv1 = g_qvar[base + row0 + 8];
#pragma unroll
        for (int nt = 0; nt < 4; nt++) {
            const int col = wn + nt * 8 + 2 * q4;
            const int d = col >> 1;
            const float Skv = g_Mr[hb][col][64];
            const float Skm = g_Mr[hb][col][65];
            float o0 = cw * qi0 * acc[mt][nt][1] + (covw / DH) * acc[mt][nt][0]
                     + (vw / DH) * qv0 * Skv - covw * qm0 * Skm;
            float o1 = cw * qi1 * acc[mt][nt][3] + (covw / DH) * acc[mt][nt][2]
                     + (vw / DH) * qv1 * Skv - covw * qm1 * Skm;
            g_ao[(size_t)(b * Nn_ + row0) * DIM + h * DH + d]     = o0;
            g_ao[(size_t)(b * Nn_ + row0 + 8) * DIM + h * DH + d] = o1;
        }
    }
}

// ---------------- gating MLP (g_hg holds SUMS; scale by 1/ROWS) ----------------
__global__ void mlp_kernel(const float* __restrict__ W1, const float* __restrict__ b1,
                           const float* __restrict__ gg, const float* __restrict__ gb,
                           const float* __restrict__ W2, const float* __restrict__ b2)
{
    int h = threadIdx.x >> 5;
    int lane = threadIdx.x & 31;
    const float invR = 1.f / (float)ROWS;
    float h1[2];
#pragma unroll
    for (int t = 0; t < 2; t++) {
        int j = lane + t * 32;
        const float* wr = W1 + j * 128;
        float dot = 0.f;
        for (int i = 0; i < 64; i++) dot += g_hg[h * 64 + i] * wr[i];
        for (int i = 0; i < 64; i++) dot += g_hg[512 + h * 64 + i] * wr[64 + i];
        h1[t] = b1[j] + dot * invR;
    }
    float s = h1[0] + h1[1], ss = h1[0] * h1[0] + h1[1] * h1[1];
#pragma unroll
    for (int off = 16; off; off >>= 1) {
        s  += __shfl_xor_sync(0xffffffffu, s, off);
        ss += __shfl_xor_sync(0xffffffffu, ss, off);
    }
    float mean = s * (1.f / 64.f);
    float var  = ss * (1.f / 64.f) - mean * mean;
    float inv  = rsqrtf(var + EPS);
    float hh[2];
#pragma unroll
    for (int t = 0; t < 2; t++) {
        int j = lane + t * 32;
        float v = (h1[t] - mean) * inv * gg[j] + gb[j];
        hh[t] = fmaxf(v, 0.f);
    }
    float lg[3];
#pragma unroll
    for (int c = 0; c < 3; c++) {
        float acc = hh[0] * W2[c * 64 + lane] + hh[1] * W2[c * 64 + lane + 32];
#pragma unroll
        for (int off = 16; off; off >>= 1) acc += __shfl_xor_sync(0xffffffffu, acc, off);
        lg[c] = acc + b2[c];
    }
    if (lane == 0) {
        float m = fmaxf(lg[0], fmaxf(lg[1], lg[2]));
        float e0 = expf(lg[0] - m), e1 = expf(lg[1] - m), e2 = expf(lg[2] - m);
        float inv_s = 1.f / (e0 + e1 + e2);
        g_w3[h * 3 + 0] = e0 * inv_s;
        g_w3[h * 3 + 1] = e1 * inv_s;
        g_w3[h * 3 + 2] = e2 * inv_s;
    }
}

// ---------------- launch ----------------
extern "C" void kernel_launch(void* const* d_in, const int* in_sizes, int n_in,
                              void* d_out, int out_size)
{
    const float* q    = (const float*)d_in[0];
    const float* k    = (const float*)d_in[1];
    const float* v    = (const float*)d_in[2];
    const float* Win  = (const float*)d_in[3];
    const float* Wout = (const float*)d_in[4];
    const float* bout = (const float*)d_in[5];
    const float* g1   = (const float*)d_in[6];
    const float* b1n  = (const float*)d_in[7];
    const float* g2   = (const float*)d_in[8];
    const float* b2n  = (const float*)d_in[9];
    const float* Wup  = (const float*)d_in[10];
    const float* bup  = (const float*)d_in[11];
    const float* Wdn  = (const float*)d_in[12];
    const float* bdn  = (const float*)d_in[13];
    const float* wpW1 = (const float*)d_in[14];
    const float* wpb1 = (const float*)d_in[15];
    const float* wpg  = (const float*)d_in[16];
    const float* wpb  = (const float*)d_in[17];
    const float* wpW2 = (const float*)d_in[18];
    const float* wpb2 = (const float*)d_in[19];
    float* out = (float*)d_out;

    float* xn;  cudaGetSymbolAddress((void**)&xn,  g_xn);
    float* f;   cudaGetSymbolAddress((void**)&f,   g_f);
    float* ao;  cudaGetSymbolAddress((void**)&ao,  g_ao);
    float* q2;  cudaGetSymbolAddress((void**)&q2,  g_q2);
    float* xn2; cudaGetSymbolAddress((void**)&xn2, g_xn2);
    float* u;   cudaGetSymbolAddress((void**)&u,   g_u);

    // 1. fused LN of q,k,v (also zeroes g_hg)
    ln3_kernel<<<3 * ROWS, 256>>>(q, k, v, g1, b1n, xn);

    // 2. fused projection + per-row stats + per-head column sums
    tmm2_kernel<4, 4><<<dim3(DIM / 128, 3 * ROWS / 128), 256>>>(
        xn, Win, nullptr, nullptr, f, 3 * ROWS, DIM, DIM);

    // 3. gating MLP
    mlp_kernel<<<1, 256>>>(wpW1, wpb1, wpg, wpb, wpW2, wpb2);

    // 4. attention via linear collapse
    mbuild_kernel<<<dim3(KSPLIT, HB), 256>>>();
    mreduce_kernel<<<(HB * 128 * MST) / (4 * 256), 256>>>();
    pgemm_kernel<<<dim3(Nn_ / 128, HB), 256>>>();

    // 5. attn out proj + residual -> q2  (M64 tile)
    tmm2_kernel<3, 2><<<dim3(DIM / 128, ROWS / 64), 256>>>(
        ao, Wout, bout, q, q2, ROWS, DIM, DIM);

    // 6. LN2
    ln_kernel<<<ROWS, 256>>>(q2, g2, b2n, xn2);

    // 7. MLP up + gelu  (M64 tile probe: 1024 CTAs)
    tmm2_kernel<2, 2><<<dim3(MLPD / 128, ROWS / 64), 256>>>(
        xn2, Wup, bup, nullptr, u, ROWS, MLPD, DIM);

    // 8. MLP down + residual -> out  (M64 tile)
    tmm2_kernel<3, 2><<<dim3(DIM / 128, ROWS / 64), 256>>>(
        u, Wdn, bdn, q2, out, ROWS, DIM, MLPD);
}

// round 9
// speedup vs baseline: 1.0699x; 1.0699x over previous
#include <cuda_runtime.h>
#include <cuda_bf16.h>
#include <math.h>
#include <stdint.h>

// ---------------- problem constants ----------------
#define Bq   4
#define Nn_  1024
#define DIM  512
#define Hh   8
#define DH   64
#define MLPD 2048
#define ROWS (Bq * Nn_)            // 4096 token rows
#define HB   (Hh * Bq)             // 32 attention batches
#define EPS  1e-5f
#define MST  80
#define KSPLIT 8

// ---------------- tf32 mma helpers ----------------
__device__ __forceinline__ float t32f(float x){
    unsigned r; asm("cvt.rna.tf32.f32 %0,%1;" : "=r"(r) : "f"(x));
    return __uint_as_float(r);
}
__device__ __forceinline__ void mma8(float* c, const unsigned* a, const unsigned* b){
    asm("mma.sync.aligned.m16n8k8.row.col.f32.tf32.tf32.f32 "
        "{%0,%1,%2,%3},{%4,%5,%6,%7},{%8,%9},{%0,%1,%2,%3};"
        : "+f"(c[0]), "+f"(c[1]), "+f"(c[2]), "+f"(c[3])
        : "r"(a[0]), "r"(a[1]), "r"(a[2]), "r"(a[3]), "r"(b[0]), "r"(b[1]));
}

// ---------------- device scratch (no allocs allowed) ----------------
__device__ float g_xn [3 * ROWS * DIM];
__device__ float g_f  [3 * ROWS * DIM];
__device__ float g_ao [ROWS * DIM];
__device__ float g_q2 [ROWS * DIM];
__device__ float g_xn2[ROWS * DIM];
__device__ float g_u  [ROWS * MLPD];
__device__ float g_Mp [KSPLIT][HB][128][MST];
__device__ float g_Mr [HB][128][MST];
__device__ float g_qinv [HB * Nn_];
__device__ float g_qmean[HB * Nn_];
__device__ float g_qvar [HB * Nn_];
__device__ float g_kinv [HB * Nn_];
__device__ float g_kmean[HB * Nn_];
__device__ float g_kvar [HB * Nn_];
__device__ float g_hg [2 * Hh * DH];
__device__ float g_w3 [Hh * 3];

// ---------------- fused layernorm of q,k,v (also zeroes g_hg) ----------------
__global__ void ln3_kernel(const float* __restrict__ q, const float* __restrict__ k,
                           const float* __restrict__ v, const float* __restrict__ g,
                           const float* __restrict__ bb, float* __restrict__ y)
{
    int row = blockIdx.x;                 // 0 .. 3*ROWS-1
    int tid = threadIdx.x;
    if (blockIdx.x < 4) g_hg[blockIdx.x * 256 + tid] = 0.f;
    int which = row >> 12;
    const float* x = (which == 0) ? q : (which == 1) ? k : v;
    const float* xr = x + (size_t)(row & (ROWS - 1)) * DIM;
    float v0 = xr[tid], v1 = xr[tid + 256];
    float s = v0 + v1, ss = v0 * v0 + v1 * v1;
    __shared__ float rs[256], rss[256];
    rs[tid] = s; rss[tid] = ss;
    __syncthreads();
    for (int off = 128; off > 0; off >>= 1) {
        if (tid < off) { rs[tid] += rs[tid + off]; rss[tid] += rss[tid + off]; }
        __syncthreads();
    }
    float mean = rs[0] * (1.f / DIM);
    float var  = rss[0] * (1.f / DIM) - mean * mean;
    float inv  = rsqrtf(var + EPS);
    float* yr = y + (size_t)row * DIM;
    yr[tid]       = (v0 - mean) * inv * g[tid]       + bb[tid];
    yr[tid + 256] = (v1 - mean) * inv * g[tid + 256] + bb[tid + 256];
}

// ---------------- layernorm (single tensor, for LN2) ----------------
__global__ void ln_kernel(const float* __restrict__ x, const float* __restrict__ g,
                          const float* __restrict__ bb, float* __restrict__ y)
{
    int row = blockIdx.x;
    int tid = threadIdx.x;
    const float* xr = x + (size_t)row * DIM;
    float v0 = xr[tid], v1 = xr[tid + 256];
    float s = v0 + v1, ss = v0 * v0 + v1 * v1;
    __shared__ float rs[256], rss[256];
    rs[tid] = s; rss[tid] = ss;
    __syncthreads();
    for (int off = 128; off > 0; off >>= 1) {
        if (tid < off) { rs[tid] += rs[tid + off]; rss[tid] += rss[tid + off]; }
        __syncthreads();
    }
    float mean = rs[0] * (1.f / DIM);
    float var  = rss[0] * (1.f / DIM) - mean * mean;
    float inv  = rsqrtf(var + EPS);
    float* yr = y + (size_t)row * DIM;
    yr[tid]       = (v0 - mean) * inv * g[tid]       + bb[tid];
    yr[tid + 256] = (v1 - mean) * inv * g[tid + 256] + bb[tid + 256];
}

// ================ tf32 mma GEMM, fragment-layout smem ================
// C = A[M,K] @ W[N,K]^T.  CTA tile (MT*32) x 128, BK=16, double-buffered.
// MODE: 2 +bias+gelu, 3 +bias+residual, 4 plain+tf32-round + fused q/k stats
template <int MODE, int MT>
__global__ void __launch_bounds__(256) tmm2_kernel(
    const float* __restrict__ A, const float* __restrict__ W,
    const float* __restrict__ bias, const float* __restrict__ res,
    float* __restrict__ C, int M, int Nc, int K)
{
    __shared__ __align__(16) float Af[2][MT * 2 * 2 * 128];
    __shared__ __align__(16) float Bf[2][16 * 2 * 64];
    __shared__ float sred[(MODE == 4) ? 8 * MT * 8 * 4 : 4];
    __shared__ float colsum[(MODE == 4) ? 128 : 4];
    const int tid = threadIdx.x;
    const int lane = tid & 31, warp = tid >> 5;
    const int wm = (warp >> 2) * (MT * 16);
    const int wn = (warp & 3) * 32;
    const int m0 = blockIdx.y * (MT * 32), n0 = blockIdx.x * 128;
    const int g = lane >> 2, q4 = lane & 3;

    if (MODE == 4 && tid < 128) colsum[tid] = 0.f;

    float acc[MT][4][4];
#pragma unroll
    for (int i = 0; i < MT; i++)
#pragma unroll
        for (int j = 0; j < 4; j++)
#pragma unroll
            for (int c = 0; c < 4; c++) acc[i][j][c] = 0.f;

    // ---- staging thread mappings ----
    const int bsrow = tid >> 1, bkc = tid & 1;
    const float* Wp = W + (size_t)(n0 + bsrow) * K + bkc * 8;
    const int bnt = bsrow >> 3, bg = bsrow & 7;
    const int asrow = (MT == 4) ? (tid >> 1) : (tid >> 2);
    const int akoff = (MT == 4) ? ((tid & 1) * 8) : ((tid & 3) * 4);
    const float* Ap = A + (size_t)(m0 + asrow) * K + akoff;
    const int amt = asrow >> 4, arl = asrow & 15, ag = arl & 7, arb = arl >> 3;
    const int akc = akoff >> 3;
    const int akh = (akoff & 7) >> 2;

    float4 av0, av1, wv0, wv1;

    av0 = *(const float4*)(Ap);
    if (MT == 4) av1 = *(const float4*)(Ap + 4);
    wv0 = *(const float4*)(Wp);
    wv1 = *(const float4*)(Wp + 4);
    {
        float* ab = &Af[0][(amt * 2 + akc) * 128];
        if (MT == 4) {
            float va[8] = {av0.x, av0.y, av0.z, av0.w, av1.x, av1.y, av1.z, av1.w};
#pragma unroll
            for (int t = 0; t < 8; t++) {
                int kk = (t + ag) & 7;
                ab[(ag * 4 + (kk & 3)) * 4 + arb + 2 * (kk >> 2)] = t32f(va[kk]);
            }
        } else {
            float va[4] = {av0.x, av0.y, av0.z, av0.w};
#pragma unroll
            for (int t = 0; t < 4; t++) {
                int qq = (t + ag) & 3;
                ab[(ag * 4 + qq) * 4 + arb + 2 * akh] = t32f(va[qq]);
            }
        }
        float* bb2 = &Bf[0][(bnt * 2 + bkc) * 64 + bg * 8];
        *(float4*)&bb2[0] = make_float4(t32f(wv0.x), t32f(wv1.x), t32f(wv0.y), t32f(wv1.y));
        *(float4*)&bb2[4] = make_float4(t32f(wv0.z), t32f(wv1.z), t32f(wv0.w), t32f(wv1.w));
    }

    int buf = 0;
    for (int k0 = 16; k0 <= K; k0 += 16) {
        __syncthreads();
        const bool more = (k0 < K);
        if (more) {
            av0 = *(const float4*)(Ap + k0);
            if (MT == 4) av1 = *(const float4*)(Ap + k0 + 4);
            wv0 = *(const float4*)(Wp + k0);
            wv1 = *(const float4*)(Wp + k0 + 4);
        }
#pragma unroll
        for (int kc = 0; kc < 2; kc++) {
            float4 afv[MT]; float2 bfv[4];
#pragma unroll
            for (int mt = 0; mt < MT; mt++)
                afv[mt] = *(const float4*)&Af[buf][((((wm >> 4) + mt) * 2 + kc) * 128) + lane * 4];
#pragma unroll
            for (int nt = 0; nt < 4; nt++)
                bfv[nt] = *(const float2*)&Bf[buf][((((wn >> 3) + nt) * 2 + kc) * 64) + lane * 2];
#pragma unroll
            for (int mt = 0; mt < MT; mt++)
#pragma unroll
                for (int nt = 0; nt < 4; nt++)
                    mma8(acc[mt][nt], (const unsigned*)&afv[mt], (const unsigned*)&bfv[nt]);
        }
        if (more) {
            const int nb = buf ^ 1;
            float* ab = &Af[nb][(amt * 2 + akc) * 128];
            if (MT == 4) {
                float va[8] = {av0.x, av0.y, av0.z, av0.w, av1.x, av1.y, av1.z, av1.w};
#pragma unroll
                for (int t = 0; t < 8; t++) {
                    int kk = (t + ag) & 7;
                    ab[(ag * 4 + (kk & 3)) * 4 + arb + 2 * (kk >> 2)] = t32f(va[kk]);
                }
            } else {
                float va[4] = {av0.x, av0.y, av0.z, av0.w};
#pragma unroll
                for (int t = 0; t < 4; t++) {
                    int qq = (t + ag) & 3;
                    ab[(ag * 4 + qq) * 4 + arb + 2 * akh] = t32f(va[qq]);
                }
            }
            float* bb2 = &Bf[nb][(bnt * 2 + bkc) * 64 + bg * 8];
            *(float4*)&bb2[0] = make_float4(t32f(wv0.x), t32f(wv1.x), t32f(wv0.y), t32f(wv1.y));
            *(float4*)&bb2[4] = make_float4(t32f(wv0.z), t32f(wv1.z), t32f(wv0.w), t32f(wv1.w));
        }
        buf ^= 1;
    }

    const int which = m0 >> 12;   // proj only: 0=q, 1=k, 2=v

    // per-column partial sums (registers; reduced once at the end)
    float csA[4], csB[4];
#pragma unroll
    for (int nt = 0; nt < 4; nt++) { csA[nt] = 0.f; csB[nt] = 0.f; }

    // ---- epilogue ----
#pragma unroll
    for (int mt = 0; mt < MT; mt++) {
        const int row0 = m0 + wm + mt * 16 + g;
        float s0 = 0.f, ss0 = 0.f, s1 = 0.f, ss1 = 0.f;
#pragma unroll
        for (int nt = 0; nt < 4; nt++) {
            const int col = n0 + wn + nt * 8 + 2 * q4;
            float v0 = acc[mt][nt][0], v1 = acc[mt][nt][1];
            float v2 = acc[mt][nt][2], v3 = acc[mt][nt][3];
            if (MODE == 2 || MODE == 3) {
                float2 bv = *(const float2*)&bias[col];
                v0 += bv.x; v1 += bv.y; v2 += bv.x; v3 += bv.y;
            }
            if (MODE == 2) {
                v0 = 0.5f * v0 * (1.f + erff(v0 * 0.70710678118654752f));
                v1 = 0.5f * v1 * (1.f + erff(v1 * 0.70710678118654752f));
                v2 = 0.5f * v2 * (1.f + erff(v2 * 0.70710678118654752f));
                v3 = 0.5f * v3 * (1.f + erff(v3 * 0.70710678118654752f));
            }
            if (MODE == 3) {
                float2 r0 = *(const float2*)(res + (size_t)row0 * Nc + col);
                float2 r1 = *(const float2*)(res + (size_t)(row0 + 8) * Nc + col);
                v0 += r0.x; v1 += r0.y; v2 += r1.x; v3 += r1.y;
            }
            if (MODE == 4) {
                v0 = t32f(v0); v1 = t32f(v1); v2 = t32f(v2); v3 = t32f(v3);
                s0 += v0 + v1; ss0 += v0 * v0 + v1 * v1;
                s1 += v2 + v3; ss1 += v2 * v2 + v3 * v3;
                csA[nt] += v0 + v2;
                csB[nt] += v1 + v3;
            }
            *(float2*)(C + (size_t)row0 * Nc + col)       = make_float2(v0, v1);
            *(float2*)(C + (size_t)(row0 + 8) * Nc + col) = make_float2(v2, v3);
        }
        if (MODE == 4) {
            s0 += __shfl_xor_sync(0xffffffffu, s0, 1);  s0 += __shfl_xor_sync(0xffffffffu, s0, 2);
            ss0 += __shfl_xor_sync(0xffffffffu, ss0, 1); ss0 += __shfl_xor_sync(0xffffffffu, ss0, 2);
            s1 += __shfl_xor_sync(0xffffffffu, s1, 1);  s1 += __shfl_xor_sync(0xffffffffu, s1, 2);
            ss1 += __shfl_xor_sync(0xffffffffu, ss1, 1); ss1 += __shfl_xor_sync(0xffffffffu, ss1, 2);
            if (q4 == 0) {
                float* sp = &sred[((warp * MT + mt) * 8 + g) * 4];
                sp[0] = s0; sp[1] = ss0; sp[2] = s1; sp[3] = ss1;
            }
        }
    }

    if (MODE == 4) {
        if (which < 2) {
            // reduce csA/csB over g-lanes (offsets 4,8,16), single atomic per column
#pragma unroll
            for (int nt = 0; nt < 4; nt++) {
                csA[nt] += __shfl_xor_sync(0xffffffffu, csA[nt], 4);
                csA[nt] += __shfl_xor_sync(0xffffffffu, csA[nt], 8);
                csA[nt] += __shfl_xor_sync(0xffffffffu, csA[nt], 16);
                csB[nt] += __shfl_xor_sync(0xffffffffu, csB[nt], 4);
                csB[nt] += __shfl_xor_sync(0xffffffffu, csB[nt], 8);
                csB[nt] += __shfl_xor_sync(0xffffffffu, csB[nt], 16);
                if (g == 0) {
                    atomicAdd(&colsum[wn + nt * 8 + 2 * q4],     csA[nt]);
                    atomicAdd(&colsum[wn + nt * 8 + 2 * q4 + 1], csB[nt]);
                }
            }
        }
        __syncthreads();
        if (which < 2) {
            if (tid < 128) atomicAdd(&g_hg[which * 512 + n0 + tid], colsum[tid]);
            const int p   = tid >> 6;
            const int mt2 = (tid >> 4) & 3;
            const int g2  = (tid >> 1) & 7;
            const int rr  = tid & 1;
            const int w0 = 2 * p;
            const float* e0 = &sred[((w0 * MT + mt2) * 8 + g2) * 4];
            const float* e1 = &sred[(((w0 + 1) * MT + mt2) * 8 + g2) * 4];
            float sA  = e0[2 * rr]     + e1[2 * rr];
            float ssA = e0[2 * rr + 1] + e1[2 * rr + 1];
            int row = m0 + (p >> 1) * 64 + mt2 * 16 + g2 + rr * 8;
            int lr2 = row & (ROWS - 1);
            int b3 = lr2 >> 10, n3 = lr2 & 1023;
            int head = (n0 >> 6) + (p & 1);
            int idx = (head * 4 + b3) * 1024 + n3;
            float mean = sA * (1.f / 64.f);
            float var  = (ssA - sA * sA * (1.f / 64.f)) * (1.f / 63.f);
            float inv  = rsqrtf(ssA);
            if (which == 0) { g_qinv[idx] = inv; g_qmean[idx] = mean; g_qvar[idx] = var; }
            else            { g_kinv[idx] = inv; g_kmean[idx] = mean; g_kvar[idx] = var; }
        }
    }
}

// ================ mbuild: Mcat[d'=128][e=72] = Vx^T @ Ax per hb (split-K) ======
__global__ void __launch_bounds__(256) mbuild_kernel()
{
    __shared__ float As[2][16][136];
    __shared__ float Bs[2][16][72];
    const int tid = threadIdx.x, lane = tid & 31, warp = tid >> 5;
    const int ks = blockIdx.x, hb = blockIdx.y, h = hb >> 2, b = hb & 3;
    const int base = hb * Nn_;
    const int g = lane >> 2, q4 = lane & 3;
    const int m0 = ks * (Nn_ / KSPLIT);

    const float* fk = g_f + (size_t)ROWS * DIM;
    const float* fv = g_f + 2 * (size_t)ROWS * DIM;

    float acc[9][4];
#pragma unroll
    for (int j = 0; j < 9; j++)
#pragma unroll
        for (int c = 0; c < 4; c++) acc[j][c] = 0.f;

    const int srow = tid >> 4;
    const int dc = (tid & 15) * 4;

    {
        int m = m0 + srow;
        float ki = g_kinv[base + m];
        float4 vv = *(const float4*)(fv + (size_t)(b*Nn_ + m)*DIM + h*DH + dc);
        float4 kk = *(const float4*)(fk + (size_t)(b*Nn_ + m)*DIM + h*DH + dc);
        float* ar = &As[0][srow][2*dc];
        ar[0] = vv.x; ar[1] = t32f(ki*vv.x);
        ar[2] = vv.y; ar[3] = t32f(ki*vv.y);
        ar[4] = vv.z; ar[5] = t32f(ki*vv.z);
        ar[6] = vv.w; ar[7] = t32f(ki*vv.w);
        *(float4*)&Bs[0][srow][dc] = kk;
        if (tid < 128) {
            int r = tid >> 3, s = tid & 7;
            int mm = m0 + r;
            float v = 0.f;
            if (s == 0) v = t32f(g_kvar [base + mm]);
            else if (s == 1) v = t32f(g_kmean[base + mm]);
            Bs[0][r][64 + s] = v;
        }
    }

    int buf = 0;
    const int KC = Nn_ / KSPLIT;
    for (int k0 = 16; k0 <= KC; k0 += 16) {
        __syncthreads();
        const bool more = (k0 < KC);
        float4 vv, kk; float ki = 0.f, xv = 0.f;
        if (more) {
            int m = m0 + k0 + srow;
            vv = *(const float4*)(fv + (size_t)(b*Nn_ + m)*DIM + h*DH + dc);
            kk = *(const float4*)(fk + (size_t)(b*Nn_ + m)*DIM + h*DH + dc);
            ki = g_kinv[base + m];
            if (tid < 128) {
                int r = tid >> 3, s = tid & 7;
                int mm = m0 + k0 + r;
                if (s == 0) xv = t32f(g_kvar [base + mm]);
                else if (s == 1) xv = t32f(g_kmean[base + mm]);
            }
        }
#pragma unroll
        for (int ks8 = 0; ks8 < 16; ks8 += 8) {
            unsigned af[4];
            const int mr = warp * 16 + g;
            af[0] = __float_as_uint(As[buf][ks8 + q4][mr]);
            af[1] = __float_as_uint(As[buf][ks8 + q4][mr + 8]);
            af[2] = __float_as_uint(As[buf][ks8 + 4 + q4][mr]);
            af[3] = __float_as_uint(As[buf][ks8 + 4 + q4][mr + 8]);
#pragma unroll
            for (int nt = 0; nt < 9; nt++) {
                unsigned bf[2];
                bf[0] = __float_as_uint(Bs[buf][ks8 + q4][nt * 8 + g]);
                bf[1] = __float_as_uint(Bs[buf][ks8 + 4 + q4][nt * 8 + g]);
                mma8(acc[nt], af, bf);
            }
        }
        if (more) {
            int nb = buf ^ 1;
            float* ar = &As[nb][srow][2*dc];
            ar[0] = vv.x; ar[1] = t32f(ki*vv.x);
            ar[2] = vv.y; ar[3] = t32f(ki*vv.y);
            ar[4] = vv.z; ar[5] = t32f(ki*vv.z);
            ar[6] = vv.w; ar[7] = t32f(ki*vv.w);
            *(float4*)&Bs[nb][srow][dc] = kk;
            if (tid < 128) {
                int r = tid >> 3, s = tid & 7;
                Bs[nb][r][64 + s] = xv;
            }
        }
        buf ^= 1;
    }

    const int row0 = warp * 16 + g;
#pragma unroll
    for (int nt = 0; nt < 9; nt++) {
        const int col = nt * 8 + 2 * q4;
        *(float2*)&g_Mp[ks][hb][row0][col]     = make_float2(acc[nt][0], acc[nt][1]);
        *(float2*)&g_Mp[ks][hb][row0 + 8][col] = make_float2(acc[nt][2], acc[nt][3]);
    }
}

// ---------------- reduce split-K partials ----------------
__global__ void mreduce_kernel()
{
    const int i = blockIdx.x * 256 + threadIdx.x;
    float4 r = make_float4(0.f, 0.f, 0.f, 0.f);
#pragma unroll
    for (int s = 0; s < KSPLIT; s++) {
        float4 a = ((const float4*)&g_Mp[s][0][0][0])[i];
        r.x += a.x; r.y += a.y; r.z += a.z; r.w += a.w;
    }
    ((float4*)&g_Mr[0][0][0])[i] = r;
}

// ================ pgemm: O = combine(fq @ Mcat^T) per hb ================
__global__ void __launch_bounds__(256) pgemm_kernel()
{
    __shared__ float As[2][16][136];
    __shared__ float Bs[2][16][136];
    const int tid = threadIdx.x;
    const int lane = tid & 31, warp = tid >> 5;
    const int wm = (warp >> 2) * 64, wn = (warp & 3) * 32;
    const int hb = blockIdx.y, h = hb >> 2, b = hb & 3;
    const int q0 = blockIdx.x * 128;
    const int base = hb * Nn_;
    const int g = lane >> 2, q4 = lane & 3;

    const float* fq = g_f;

    float acc[4][4][4];
#pragma unroll
    for (int i = 0; i < 4; i++)
#pragma unroll
        for (int j = 0; j < 4; j++)
#pragma unroll
            for (int c = 0; c < 4; c++) acc[i][j][c] = 0.f;

    const int srow = tid >> 1, skc = (tid & 1) * 8;
    const float* Apt = fq + (size_t)(b * Nn_ + q0 + srow) * DIM + h * DH + skc;
    const float* Wpt = &g_Mr[hb][srow][skc];

    {
        float4 a0 = *(const float4*)(Apt);
        float4 a1 = *(const float4*)(Apt + 4);
        float4 w0 = *(const float4*)(Wpt);
        float4 w1 = *(const float4*)(Wpt + 4);
        As[0][skc+0][srow] = a0.x; As[0][skc+1][srow] = a0.y;
        As[0][skc+2][srow] = a0.z; As[0][skc+3][srow] = a0.w;
        As[0][skc+4][srow] = a1.x; As[0][skc+5][srow] = a1.y;
        As[0][skc+6][srow] = a1.z; As[0][skc+7][srow] = a1.w;
        Bs[0][skc+0][srow] = t32f(w0.x); Bs[0][skc+1][srow] = t32f(w0.y);
        Bs[0][skc+2][srow] = t32f(w0.z); Bs[0][skc+3][srow] = t32f(w0.w);
        Bs[0][skc+4][srow] = t32f(w1.x); Bs[0][skc+5][srow] = t32f(w1.y);
        Bs[0][skc+6][srow] = t32f(w1.z); Bs[0][skc+7][srow] = t32f(w1.w);
    }

    int buf = 0;
    for (int k0 = 16; k0 <= DH; k0 += 16) {
        __syncthreads();
        const bool more = (k0 < DH);
        float4 a0, a1, w0, w1;
        if (more) {
            a0 = *(const float4*)(Apt + k0);
            a1 = *(const float4*)(Apt + k0 + 4);
            w0 = *(const float4*)(Wpt + k0);
            w1 = *(const float4*)(Wpt + k0 + 4);
        }
#pragma unroll
        for (int ks = 0; ks < 16; ks += 8) {
            unsigned af[4][4], bf[4][2];
#pragma unroll
            for (int mt = 0; mt < 4; mt++) {
                int mr = wm + mt * 16 + g;
                af[mt][0] = __float_as_uint(As[buf][ks + q4][mr]);
                af[mt][1] = __float_as_uint(As[buf][ks + q4][mr + 8]);
                af[mt][2] = __float_as_uint(As[buf][ks + 4 + q4][mr]);
                af[mt][3] = __float_as_uint(As[buf][ks + 4 + q4][mr + 8]);
            }
#pragma unroll
            for (int nt = 0; nt < 4; nt++) {
                int nc = wn + nt * 8 + g;
                bf[nt][0] = __float_as_uint(Bs[buf][ks + q4][nc]);
                bf[nt][1] = __float_as_uint(Bs[buf][ks + 4 + q4][nc]);
            }
#pragma unroll
            for (int mt = 0; mt < 4; mt++)
#pragma unroll
                for (int nt = 0; nt < 4; nt++)
                    mma8(acc[mt][nt], af[mt], bf[nt]);
        }
        if (more) {
            int nb = buf ^ 1;
            As[nb][skc+0][srow] = a0.x; As[nb][skc+1][srow] = a0.y;
            As[nb][skc+2][srow] = a0.z; As[nb][skc+3][srow] = a0.w;
            As[nb][skc+4][srow] = a1.x; As[nb][skc+5][srow] = a1.y;
            As[nb][skc+6][srow] = a1.z; As[nb][skc+7][srow] = a1.w;
            Bs[nb][skc+0][srow] = t32f(w0.x); Bs[nb][skc+1][srow] = t32f(w0.y);
            Bs[nb][skc+2][srow] = t32f(w0.z); Bs[nb][skc+3][srow] = t32f(w0.w);
            Bs[nb][skc+4][srow] = t32f(w1.x); Bs[nb][skc+5][srow] = t32f(w1.y);
            Bs[nb][skc+6][srow] = t32f(w1.z); Bs[nb][skc+7][srow] = t32f(w1.w);
        }
        buf ^= 1;
    }

    const float cw = g_w3[h * 3 + 0], covw = g_w3[h * 3 + 1], vw = g_w3[h * 3 + 2];
#pragma unroll
    for (int mt = 0; mt < 4; mt++) {
        const int row0 = q0 + wm + mt * 16 + g;
        const float qi0 = g_qinv[base + row0],     qm0 = g_qmean[base + row0],     qv0 = g_qvar[base + row0];
        const float qi1 = g_qinv[base + row0 + 8], qm1 = g_qmean[base + row0 + 8], qv1 = g_qvar[base + row0 + 8];
#pragma unroll
        for (int nt = 0; nt < 4; nt++) {
            const int col = wn + nt * 8 + 2 * q4;
            const int d = col >> 1;
            const float Skv = g_Mr[hb][col][64];
            const float Skm = g_Mr[hb][col][65];
            float o0 = cw * qi0 * acc[mt][nt][1] + (covw / DH) * acc[mt][nt][0]
                     + (vw / DH) * qv0 * Skv - covw * qm0 * Skm;
            float o1 = cw * qi1 * acc[mt][nt][3] + (covw / DH) * acc[mt][nt][2]
                     + (vw / DH) * qv1 * Skv - covw * qm1 * Skm;
            g_ao[(size_t)(b * Nn_ + row0) * DIM + h * DH + d]     = o0;
            g_ao[(size_t)(b * Nn_ + row0 + 8) * DIM + h * DH + d] = o1;
        }
    }
}

// ---------------- gating MLP (g_hg holds SUMS; scale by 1/ROWS) ----------------
__global__ void mlp_kernel(const float* __restrict__ W1, const float* __restrict__ b1,
                           const float* __restrict__ gg, const float* __restrict__ gb,
                           const float* __restrict__ W2, const float* __restrict__ b2)
{
    int h = threadIdx.x >> 5;
    int lane = threadIdx.x & 31;
    const float invR = 1.f / (float)ROWS;
    float h1[2];
#pragma unroll
    for (int t = 0; t < 2; t++) {
        int j = lane + t * 32;
        const float* wr = W1 + j * 128;
        float dot = 0.f;
        for (int i = 0; i < 64; i++) dot += g_hg[h * 64 + i] * wr[i];
        for (int i = 0; i < 64; i++) dot += g_hg[512 + h * 64 + i] * wr[64 + i];
        h1[t] = b1[j] + dot * invR;
    }
    float s = h1[0] + h1[1], ss = h1[0] * h1[0] + h1[1] * h1[1];
#pragma unroll
    for (int off = 16; off; off >>= 1) {
        s  += __shfl_xor_sync(0xffffffffu, s, off);
        ss += __shfl_xor_sync(0xffffffffu, ss, off);
    }
    float mean = s * (1.f / 64.f);
    float var  = ss * (1.f / 64.f) - mean * mean;
    float inv  = rsqrtf(var + EPS);
    float hh[2];
#pragma unroll
    for (int t = 0; t < 2; t++) {
        int j = lane + t * 32;
        float v = (h1[t] - mean) * inv * gg[j] + gb[j];
        hh[t] = fmaxf(v, 0.f);
    }
    float lg[3];
#pragma unroll
    for (int c = 0; c < 3; c++) {
        float acc = hh[0] * W2[c * 64 + lane] + hh[1] * W2[c * 64 + lane + 32];
#pragma unroll
        for (int off = 16; off; off >>= 1) acc += __shfl_xor_sync(0xffffffffu, acc, off);
        lg[c] = acc + b2[c];
    }
    if (lane == 0) {
        float m = fmaxf(lg[0], fmaxf(lg[1], lg[2]));
        float e0 = expf(lg[0] - m), e1 = expf(lg[1] - m), e2 = expf(lg[2] - m);
        float inv_s = 1.f / (e0 + e1 + e2);
        g_w3[h * 3 + 0] = e0 * inv_s;
        g_w3[h * 3 + 1] = e1 * inv_s;
        g_w3[h * 3 + 2] = e2 * inv_s;
    }
}

// ---------------- launch ----------------
extern "C" void kernel_launch(void* const* d_in, const int* in_sizes, int n_in,
                              void* d_out, int out_size)
{
    const float* q    = (const float*)d_in[0];
    const float* k    = (const float*)d_in[1];
    const float* v    = (const float*)d_in[2];
    const float* Win  = (const float*)d_in[3];
    const float* Wout = (const float*)d_in[4];
    const float* bout = (const float*)d_in[5];
    const float* g1   = (const float*)d_in[6];
    const float* b1n  = (const float*)d_in[7];
    const float* g2   = (const float*)d_in[8];
    const float* b2n  = (const float*)d_in[9];
    const float* Wup  = (const float*)d_in[10];
    const float* bup  = (const float*)d_in[11];
    const float* Wdn  = (const float*)d_in[12];
    const float* bdn  = (const float*)d_in[13];
    const float* wpW1 = (const float*)d_in[14];
    const float* wpb1 = (const float*)d_in[15];
    const float* wpg  = (const float*)d_in[16];
    const float* wpb  = (const float*)d_in[17];
    const float* wpW2 = (const float*)d_in[18];
    const float* wpb2 = (const float*)d_in[19];
    float* out = (float*)d_out;

    float* xn;  cudaGetSymbolAddress((void**)&xn,  g_xn);
    float* f;   cudaGetSymbolAddress((void**)&f,   g_f);
    float* ao;  cudaGetSymbolAddress((void**)&ao,  g_ao);
    float* q2;  cudaGetSymbolAddress((void**)&q2,  g_q2);
    float* xn2; cudaGetSymbolAddress((void**)&xn2, g_xn2);
    float* u;   cudaGetSymbolAddress((void**)&u,   g_u);

    // 1. fused LN of q,k,v (also zeroes g_hg)
    ln3_kernel<<<3 * ROWS, 256>>>(q, k, v, g1, b1n, xn);

    // 2. fused projection + per-row stats + per-head column sums
    tmm2_kernel<4, 4><<<dim3(DIM / 128, 3 * ROWS / 128), 256>>>(
        xn, Win, nullptr, nullptr, f, 3 * ROWS, DIM, DIM);

    // 3. gating MLP
    mlp_kernel<<<1, 256>>>(wpW1, wpb1, wpg, wpb, wpW2, wpb2);

    // 4. attention via linear collapse (KSPLIT=8 -> 256 CTAs)
    mbuild_kernel<<<dim3(KSPLIT, HB), 256>>>();
    mreduce_kernel<<<(HB * 128 * MST) / (4 * 256), 256>>>();
    pgemm_kernel<<<dim3(Nn_ / 128, HB), 256>>>();

    // 5. attn out proj + residual -> q2  (M64 tile)
    tmm2_kernel<3, 2><<<dim3(DIM / 128, ROWS / 64), 256>>>(
        ao, Wout, bout, q, q2, ROWS, DIM, DIM);

    // 6. LN2
    ln_kernel<<<ROWS, 256>>>(q2, g2, b2n, xn2);

    // 7. MLP up + gelu  (back to MT=4: 512 CTAs)
    tmm2_kernel<2, 4><<<dim3(MLPD / 128, ROWS / 128), 256>>>(
        xn2, Wup, bup, nullptr, u, ROWS, MLPD, DIM);

    // 8. MLP down + residual -> out  (M64 tile)
    tmm2_kernel<3, 2><<<dim3(DIM / 128, ROWS / 64), 256>>>(
        u, Wdn, bdn, q2, out, ROWS, DIM, MLPD);
}

// round 10
// speedup vs baseline: 1.3138x; 1.2280x over previous
#include <cuda_runtime.h>
#include <cuda_bf16.h>
#include <math.h>
#include <stdint.h>

// ---------------- problem constants ----------------
#define Bq   4
#define Nn_  1024
#define DIM  512
#define Hh   8
#define DH   64
#define MLPD 2048
#define ROWS (Bq * Nn_)            // 4096 token rows
#define HB   (Hh * Bq)             // 32 attention batches
#define EPS  1e-5f
#define MST  80
#define KSPLIT 8

// ---------------- tf32 mma helpers ----------------
__device__ __forceinline__ float t32f(float x){
    unsigned r; asm("cvt.rna.tf32.f32 %0,%1;" : "=r"(r) : "f"(x));
    return __uint_as_float(r);
}
__device__ __forceinline__ void mma8(float* c, const unsigned* a, const unsigned* b){
    asm("mma.sync.aligned.m16n8k8.row.col.f32.tf32.tf32.f32 "
        "{%0,%1,%2,%3},{%4,%5,%6,%7},{%8,%9},{%0,%1,%2,%3};"
        : "+f"(c[0]), "+f"(c[1]), "+f"(c[2]), "+f"(c[3])
        : "r"(a[0]), "r"(a[1]), "r"(a[2]), "r"(a[3]), "r"(b[0]), "r"(b[1]));
}
__device__ __forceinline__ unsigned smem_u32(const void* p){
    return (unsigned)__cvta_generic_to_shared((void*)p);
}
__device__ __forceinline__ void cpa16(unsigned dst, const float* src){
    asm volatile("cp.async.cg.shared.global [%0], [%1], 16;" :: "r"(dst), "l"(src) : "memory");
}
__device__ __forceinline__ void cp_commit(){
    asm volatile("cp.async.commit_group;" ::: "memory");
}
__device__ __forceinline__ void cp_wait2(){
    asm volatile("cp.async.wait_group 2;" ::: "memory");
}

// ---------------- device scratch (no allocs allowed) ----------------
__device__ float g_xn [3 * ROWS * DIM];
__device__ float g_f  [3 * ROWS * DIM];
__device__ float g_ao [ROWS * DIM];
__device__ float g_q2 [ROWS * DIM];
__device__ float g_xn2[ROWS * DIM];
__device__ float g_u  [ROWS * MLPD];
__device__ float g_Mp [KSPLIT][HB][128][MST];
__device__ float g_Mr [HB][128][MST];
__device__ float g_qinv [HB * Nn_];
__device__ float g_qmean[HB * Nn_];
__device__ float g_qvar [HB * Nn_];
__device__ float g_kinv [HB * Nn_];
__device__ float g_kmean[HB * Nn_];
__device__ float g_kvar [HB * Nn_];
__device__ float g_hg [2 * Hh * DH];
__device__ float g_w3 [Hh * 3];

// ---------------- fused layernorm of q,k,v (also zeroes g_hg) ----------------
__global__ void ln3_kernel(const float* __restrict__ q, const float* __restrict__ k,
                           const float* __restrict__ v, const float* __restrict__ g,
                           const float* __restrict__ bb, float* __restrict__ y)
{
    int row = blockIdx.x;                 // 0 .. 3*ROWS-1
    int tid = threadIdx.x;
    if (blockIdx.x < 4) g_hg[blockIdx.x * 256 + tid] = 0.f;
    int which = row >> 12;
    const float* x = (which == 0) ? q : (which == 1) ? k : v;
    const float* xr = x + (size_t)(row & (ROWS - 1)) * DIM;
    float v0 = xr[tid], v1 = xr[tid + 256];
    float s = v0 + v1, ss = v0 * v0 + v1 * v1;
    __shared__ float rs[256], rss[256];
    rs[tid] = s; rss[tid] = ss;
    __syncthreads();
    for (int off = 128; off > 0; off >>= 1) {
        if (tid < off) { rs[tid] += rs[tid + off]; rss[tid] += rss[tid + off]; }
        __syncthreads();
    }
    float mean = rs[0] * (1.f / DIM);
    float var  = rss[0] * (1.f / DIM) - mean * mean;
    float inv  = rsqrtf(var + EPS);
    float* yr = y + (size_t)row * DIM;
    yr[tid]       = (v0 - mean) * inv * g[tid]       + bb[tid];
    yr[tid + 256] = (v1 - mean) * inv * g[tid + 256] + bb[tid + 256];
}

// ---------------- layernorm (single tensor, for LN2) ----------------
__global__ void ln_kernel(const float* __restrict__ x, const float* __restrict__ g,
                          const float* __restrict__ bb, float* __restrict__ y)
{
    int row = blockIdx.x;
    int tid = threadIdx.x;
    const float* xr = x + (size_t)row * DIM;
    float v0 = xr[tid], v1 = xr[tid + 256];
    float s = v0 + v1, ss = v0 * v0 + v1 * v1;
    __shared__ float rs[256], rss[256];
    rs[tid] = s; rss[tid] = ss;
    __syncthreads();
    for (int off = 128; off > 0; off >>= 1) {
        if (tid < off) { rs[tid] += rs[tid + off]; rss[tid] += rss[tid + off]; }
        __syncthreads();
    }
    float mean = rs[0] * (1.f / DIM);
    float var  = rss[0] * (1.f / DIM) - mean * mean;
    float inv  = rsqrtf(var + EPS);
    float* yr = y + (size_t)row * DIM;
    yr[tid]       = (v0 - mean) * inv * g[tid]       + bb[tid];
    yr[tid + 256] = (v1 - mean) * inv * g[tid + 256] + bb[tid + 256];
}

// ================ tf32 mma GEMM, 4-stage cp.async pipeline ================
// C = A[M,K] @ W[N,K]^T.  CTA tile (MT*32) x 128, BK=16, S=4 stages.
// smem layout: As[S][MT*32][20], Bs[S][128][20] (dynamic).
// MODE: 2 +bias+gelu, 3 +bias+residual, 4 plain+tf32-round + fused q/k stats
#define TS 4

template <int MODE, int MT>
__global__ void __launch_bounds__(256) tmm3_kernel(
    const float* __restrict__ A, const float* __restrict__ W,
    const float* __restrict__ bias, const float* __restrict__ res,
    float* __restrict__ C, int M, int Nc, int K)
{
    constexpr int AR = MT * 32;
    extern __shared__ float sm[];
    float* Asm = sm;                        // [TS][AR][20]
    float* Bsm = sm + TS * AR * 20;         // [TS][128][20]
    __shared__ float sred[(MODE == 4) ? 8 * 4 * 8 * 4 : 4];
    __shared__ float colsum[(MODE == 4) ? 128 : 4];

    const int tid = threadIdx.x;
    const int lane = tid & 31, warp = tid >> 5;
    const int wm = (warp >> 2) * (MT * 16);
    const int wn = (warp & 3) * 32;
    const int m0 = blockIdx.y * AR, n0 = blockIdx.x * 128;
    const int g = lane >> 2, q4 = lane & 3;

    if (MODE == 4 && tid < 128) colsum[tid] = 0.f;

    float acc[MT][4][4];
#pragma unroll
    for (int i = 0; i < MT; i++)
#pragma unroll
        for (int j = 0; j < 4; j++)
#pragma unroll
            for (int c = 0; c < 4; c++) acc[i][j][c] = 0.f;

    const unsigned sAu = smem_u32(Asm);
    const unsigned sBu = smem_u32(Bsm);

    // copy mappings
    const int crow = tid >> 1, cko = (tid & 1) * 8;       // A(MT4) and B: 2x16B
    const int arow2 = tid >> 2, ako2 = (tid & 3) * 4;     // A(MT2): 1x16B

    auto issue = [&](int s, int k0) {
        if (MT == 4) {
            unsigned d = sAu + (unsigned)(((s * 128 + crow) * 20 + cko) * 4);
            const float* p = A + (size_t)(m0 + crow) * K + k0 + cko;
            cpa16(d, p); cpa16(d + 16, p + 4);
        } else {
            unsigned d = sAu + (unsigned)(((s * 64 + arow2) * 20 + ako2) * 4);
            cpa16(d, A + (size_t)(m0 + arow2) * K + k0 + ako2);
        }
        unsigned d = sBu + (unsigned)(((s * 128 + crow) * 20 + cko) * 4);
        const float* p = W + (size_t)(n0 + crow) * K + k0 + cko;
        cpa16(d, p); cpa16(d + 16, p + 4);
    };

    // prologue: stages 0..2 = chunks 0..2
    issue(0, 0);  cp_commit();
    issue(1, 16); cp_commit();
    issue(2, 32); cp_commit();

    const int L = K / 16;
    int s = 0;
    for (int j = 0; j < L; j++) {
        cp_wait2();            // chunk j's group complete
        __syncthreads();
        // ---- compute stage s ----
#pragma unroll
        for (int kc = 0; kc < 16; kc += 8) {
            unsigned af[MT][4], bf[4][2];
#pragma unroll
            for (int mt = 0; mt < MT; mt++) {
                const float* ar = &Asm[(s * AR + wm + mt * 16 + g) * 20 + kc + q4];
                af[mt][0] = __float_as_uint(ar[0]);
                af[mt][1] = __float_as_uint(ar[160]);     // +8 rows
                af[mt][2] = __float_as_uint(ar[4]);
                af[mt][3] = __float_as_uint(ar[164]);
            }
#pragma unroll
            for (int nt = 0; nt < 4; nt++) {
                const float* br = &Bsm[(s * 128 + wn + nt * 8 + g) * 20 + kc + q4];
                bf[nt][0] = __float_as_uint(br[0]);
                bf[nt][1] = __float_as_uint(br[4]);
            }
#pragma unroll
            for (int mt = 0; mt < MT; mt++)
#pragma unroll
                for (int nt = 0; nt < 4; nt++)
                    mma8(acc[mt][nt], af[mt], bf[nt]);
        }
        // ---- issue chunk j+3 into stage (s+3)%4 (the stage computed last iter) ----
        if (j + 3 < L) {
            int ws = s + 3; if (ws >= TS) ws -= TS;
            issue(ws, (j + 3) * 16);
        }
        cp_commit();           // commit every iter (empty groups keep the count)
        s++; if (s == TS) s = 0;
    }

    const int which = m0 >> 12;   // proj only: 0=q, 1=k, 2=v

    float csA[4], csB[4];
#pragma unroll
    for (int nt = 0; nt < 4; nt++) { csA[nt] = 0.f; csB[nt] = 0.f; }

    // ---- epilogue ----
#pragma unroll
    for (int mt = 0; mt < MT; mt++) {
        const int row0 = m0 + wm + mt * 16 + g;
        float s0 = 0.f, ss0 = 0.f, s1 = 0.f, ss1 = 0.f;
#pragma unroll
        for (int nt = 0; nt < 4; nt++) {
            const int col = n0 + wn + nt * 8 + 2 * q4;
            float v0 = acc[mt][nt][0], v1 = acc[mt][nt][1];
            float v2 = acc[mt][nt][2], v3 = acc[mt][nt][3];
            if (MODE == 2 || MODE == 3) {
                float2 bv = *(const float2*)&bias[col];
                v0 += bv.x; v1 += bv.y; v2 += bv.x; v3 += bv.y;
            }
            if (MODE == 2) {
                v0 = 0.5f * v0 * (1.f + erff(v0 * 0.70710678118654752f));
                v1 = 0.5f * v1 * (1.f + erff(v1 * 0.70710678118654752f));
                v2 = 0.5f * v2 * (1.f + erff(v2 * 0.70710678118654752f));
                v3 = 0.5f * v3 * (1.f + erff(v3 * 0.70710678118654752f));
            }
            if (MODE == 3) {
                float2 r0 = *(const float2*)(res + (size_t)row0 * Nc + col);
                float2 r1 = *(const float2*)(res + (size_t)(row0 + 8) * Nc + col);
                v0 += r0.x; v1 += r0.y; v2 += r1.x; v3 += r1.y;
            }
            if (MODE == 4) {
                v0 = t32f(v0); v1 = t32f(v1); v2 = t32f(v2); v3 = t32f(v3);
                s0 += v0 + v1; ss0 += v0 * v0 + v1 * v1;
                s1 += v2 + v3; ss1 += v2 * v2 + v3 * v3;
                csA[nt] += v0 + v2;
                csB[nt] += v1 + v3;
            }
            *(float2*)(C + (size_t)row0 * Nc + col)       = make_float2(v0, v1);
            *(float2*)(C + (size_t)(row0 + 8) * Nc + col) = make_float2(v2, v3);
        }
        if (MODE == 4) {
            s0 += __shfl_xor_sync(0xffffffffu, s0, 1);  s0 += __shfl_xor_sync(0xffffffffu, s0, 2);
            ss0 += __shfl_xor_sync(0xffffffffu, ss0, 1); ss0 += __shfl_xor_sync(0xffffffffu, ss0, 2);
            s1 += __shfl_xor_sync(0xffffffffu, s1, 1);  s1 += __shfl_xor_sync(0xffffffffu, s1, 2);
            ss1 += __shfl_xor_sync(0xffffffffu, ss1, 1); ss1 += __shfl_xor_sync(0xffffffffu, ss1, 2);
            if (q4 == 0) {
                float* sp = &sred[((warp * MT + mt) * 8 + g) * 4];
                sp[0] = s0; sp[1] = ss0; sp[2] = s1; sp[3] = ss1;
            }
        }
    }

    if (MODE == 4) {
        if (which < 2) {
#pragma unroll
            for (int nt = 0; nt < 4; nt++) {
                csA[nt] += __shfl_xor_sync(0xffffffffu, csA[nt], 4);
                csA[nt] += __shfl_xor_sync(0xffffffffu, csA[nt], 8);
                csA[nt] += __shfl_xor_sync(0xffffffffu, csA[nt], 16);
                csB[nt] += __shfl_xor_sync(0xffffffffu, csB[nt], 4);
                csB[nt] += __shfl_xor_sync(0xffffffffu, csB[nt], 8);
                csB[nt] += __shfl_xor_sync(0xffffffffu, csB[nt], 16);
                if (g == 0) {
                    atomicAdd(&colsum[wn + nt * 8 + 2 * q4],     csA[nt]);
                    atomicAdd(&colsum[wn + nt * 8 + 2 * q4 + 1], csB[nt]);
                }
            }
        }
        __syncthreads();
        if (which < 2) {
            if (tid < 128) atomicAdd(&g_hg[which * 512 + n0 + tid], colsum[tid]);
            const int p   = tid >> 6;
            const int mt2 = (tid >> 4) & 3;
            const int g2  = (tid >> 1) & 7;
            const int rr  = tid & 1;
            const int w0 = 2 * p;
            const float* e0 = &sred[((w0 * MT + mt2) * 8 + g2) * 4];
            const float* e1 = &sred[(((w0 + 1) * MT + mt2) * 8 + g2) * 4];
            float sA  = e0[2 * rr]     + e1[2 * rr];
            float ssA = e0[2 * rr + 1] + e1[2 * rr + 1];
            int row = m0 + (p >> 1) * 64 + mt2 * 16 + g2 + rr * 8;
            int lr2 = row & (ROWS - 1);
            int b3 = lr2 >> 10, n3 = lr2 & 1023;
            int head = (n0 >> 6) + (p & 1);
            int idx = (head * 4 + b3) * 1024 + n3;
            float mean = sA * (1.f / 64.f);
            float var  = (ssA - sA * sA * (1.f / 64.f)) * (1.f / 63.f);
            float inv  = rsqrtf(ssA);
            if (which == 0) { g_qinv[idx] = inv; g_qmean[idx] = mean; g_qvar[idx] = var; }
            else            { g_kinv[idx] = inv; g_kmean[idx] = mean; g_kvar[idx] = var; }
        }
    }
}

// ================ mbuild: Mcat[d'=128][e=72] = Vx^T @ Ax per hb (split-K) ======
__global__ void __launch_bounds__(256) mbuild_kernel()
{
    __shared__ float As[2][16][136];
    __shared__ float Bs[2][16][72];
    const int tid = threadIdx.x, lane = tid & 31, warp = tid >> 5;
    const int ks = blockIdx.x, hb = blockIdx.y, h = hb >> 2, b = hb & 3;
    const int base = hb * Nn_;
    const int g = lane >> 2, q4 = lane & 3;
    const int m0 = ks * (Nn_ / KSPLIT);

    const float* fk = g_f + (size_t)ROWS * DIM;
    const float* fv = g_f + 2 * (size_t)ROWS * DIM;

    float acc[9][4];
#pragma unroll
    for (int j = 0; j < 9; j++)
#pragma unroll
        for (int c = 0; c < 4; c++) acc[j][c] = 0.f;

    const int srow = tid >> 4;
    const int dc = (tid & 15) * 4;

    {
        int m = m0 + srow;
        float ki = g_kinv[base + m];
        float4 vv = *(const float4*)(fv + (size_t)(b*Nn_ + m)*DIM + h*DH + dc);
        float4 kk = *(const float4*)(fk + (size_t)(b*Nn_ + m)*DIM + h*DH + dc);
        float* ar = &As[0][srow][2*dc];
        ar[0] = vv.x; ar[1] = t32f(ki*vv.x);
        ar[2] = vv.y; ar[3] = t32f(ki*vv.y);
        ar[4] = vv.z; ar[5] = t32f(ki*vv.z);
        ar[6] = vv.w; ar[7] = t32f(ki*vv.w);
        *(float4*)&Bs[0][srow][dc] = kk;
        if (tid < 128) {
            int r = tid >> 3, s = tid & 7;
            int mm = m0 + r;
            float v = 0.f;
            if (s == 0) v = t32f(g_kvar [base + mm]);
            else if (s == 1) v = t32f(g_kmean[base + mm]);
            Bs[0][r][64 + s] = v;
        }
    }

    int buf = 0;
    const int KC = Nn_ / KSPLIT;
    for (int k0 = 16; k0 <= KC; k0 += 16) {
        __syncthreads();
        const bool more = (k0 < KC);
        float4 vv, kk; float ki = 0.f, xv = 0.f;
        if (more) {
            int m = m0 + k0 + srow;
            vv = *(const float4*)(fv + (size_t)(b*Nn_ + m)*DIM + h*DH + dc);
            kk = *(const float4*)(fk + (size_t)(b*Nn_ + m)*DIM + h*DH + dc);
            ki = g_kinv[base + m];
            if (tid < 128) {
                int r = tid >> 3, s = tid & 7;
                int mm = m0 + k0 + r;
                if (s == 0) xv = t32f(g_kvar [base + mm]);
                else if (s == 1) xv = t32f(g_kmean[base + mm]);
            }
        }
#pragma unroll
        for (int ks8 = 0; ks8 < 16; ks8 += 8) {
            unsigned af[4];
            const int mr = warp * 16 + g;
            af[0] = __float_as_uint(As[buf][ks8 + q4][mr]);
            af[1] = __float_as_uint(As[buf][ks8 + q4][mr + 8]);
            af[2] = __float_as_uint(As[buf][ks8 + 4 + q4][mr]);
            af[3] = __float_as_uint(As[buf][ks8 + 4 + q4][mr + 8]);
#pragma unroll
            for (int nt = 0; nt < 9; nt++) {
                unsigned bf[2];
                bf[0] = __float_as_uint(Bs[buf][ks8 + q4][nt * 8 + g]);
                bf[1] = __float_as_uint(Bs[buf][ks8 + 4 + q4][nt * 8 + g]);
                mma8(acc[nt], af, bf);
            }
        }
        if (more) {
            int nb = buf ^ 1;
            float* ar = &As[nb][srow][2*dc];
            ar[0] = vv.x; ar[1] = t32f(ki*vv.x);
            ar[2] = vv.y; ar[3] = t32f(ki*vv.y);
            ar[4] = vv.z; ar[5] = t32f(ki*vv.z);
            ar[6] = vv.w; ar[7] = t32f(ki*vv.w);
            *(float4*)&Bs[nb][srow][dc] = kk;
            if (tid < 128) {
                int r = tid >> 3, s = tid & 7;
                Bs[nb][r][64 + s] = xv;
            }
        }
        buf ^= 1;
    }

    const int row0 = warp * 16 + g;
#pragma unroll
    for (int nt = 0; nt < 9; nt++) {
        const int col = nt * 8 + 2 * q4;
        *(float2*)&g_Mp[ks][hb][row0][col]     = make_float2(acc[nt][0], acc[nt][1]);
        *(float2*)&g_Mp[ks][hb][row0 + 8][col] = make_float2(acc[nt][2], acc[nt][3]);
    }
}

// ---------------- reduce split-K partials ----------------
__global__ void mreduce_kernel()
{
    const int i = blockIdx.x * 256 + threadIdx.x;
    float4 r = make_float4(0.f, 0.f, 0.f, 0.f);
#pragma unroll
    for (int s = 0; s < KSPLIT; s++) {
        float4 a = ((const float4*)&g_Mp[s][0][0][0])[i];
        r.x += a.x; r.y += a.y; r.z += a.z; r.w += a.w;
    }
    ((float4*)&g_Mr[0][0][0])[i] = r;
}

// ================ pgemm: O = combine(fq @ Mcat^T) per hb ================
__global__ void __launch_bounds__(256) pgemm_kernel()
{
    __shared__ float As[2][16][136];
    __shared__ float Bs[2][16][136];
    const int tid = threadIdx.x;
    const int lane = tid & 31, warp = tid >> 5;
    const int wm = (warp >> 2) * 64, wn = (warp & 3) * 32;
    const int hb = blockIdx.y, h = hb >> 2, b = hb & 3;
    const int q0 = blockIdx.x * 128;
    const int base = hb * Nn_;
    const int g = lane >> 2, q4 = lane & 3;

    const float* fq = g_f;

    float acc[4][4][4];
#pragma unroll
    for (int i = 0; i < 4; i++)
#pragma unroll
        for (int j = 0; j < 4; j++)
#pragma unroll
            for (int c = 0; c < 4; c++) acc[i][j][c] = 0.f;

    const int srow = tid >> 1, skc = (tid & 1) * 8;
    const float* Apt = fq + (size_t)(b * Nn_ + q0 + srow) * DIM + h * DH + skc;
    const float* Wpt = &g_Mr[hb][srow][skc];

    {
        float4 a0 = *(const float4*)(Apt);
        float4 a1 = *(const float4*)(Apt + 4);
        float4 w0 = *(const float4*)(Wpt);
        float4 w1 = *(const float4*)(Wpt + 4);
        As[0][skc+0][srow] = a0.x; As[0][skc+1][srow] = a0.y;
        As[0][skc+2][srow] = a0.z; As[0][skc+3][srow] = a0.w;
        As[0][skc+4][srow] = a1.x; As[0][skc+5][srow] = a1.y;
        As[0][skc+6][srow] = a1.z; As[0][skc+7][srow] = a1.w;
        Bs[0][skc+0][srow] = t32f(w0.x); Bs[0][skc+1][srow] = t32f(w0.y);
        Bs[0][skc+2][srow] = t32f(w0.z); Bs[0][skc+3][srow] = t32f(w0.w);
        Bs[0][skc+4][srow] = t32f(w1.x); Bs[0][skc+5][srow] = t32f(w1.y);
        Bs[0][skc+6][srow] = t32f(w1.z); Bs[0][skc+7][srow] = t32f(w1.w);
    }

    int buf = 0;
    for (int k0 = 16; k0 <= DH; k0 += 16) {
        __syncthreads();
        const bool more = (k0 < DH);
        float4 a0, a1, w0, w1;
        if (more) {
            a0 = *(const float4*)(Apt + k0);
            a1 = *(const float4*)(Apt + k0 + 4);
            w0 = *(const float4*)(Wpt + k0);
            w1 = *(const float4*)(Wpt + k0 + 4);
        }
#pragma unroll
        for (int ks = 0; ks < 16; ks += 8) {
            unsigned af[4][4], bf[4][2];
#pragma unroll
            for (int mt = 0; mt < 4; mt++) {
                int mr = wm + mt * 16 + g;
                af[mt][0] = __float_as_uint(As[buf][ks + q4][mr]);
                af[mt][1] = __float_as_uint(As[buf][ks + q4][mr + 8]);
                af[mt][2] = __float_as_uint(As[buf][ks + 4 + q4][mr]);
                af[mt][3] = __float_as_uint(As[buf][ks + 4 + q4][mr + 8]);
            }
#pragma unroll
            for (int nt = 0; nt < 4; nt++) {
                int nc = wn + nt * 8 + g;
                bf[nt][0] = __float_as_uint(Bs[buf][ks + q4][nc]);
                bf[nt][1] = __float_as_uint(Bs[buf][ks + 4 + q4][nc]);
            }
#pragma unroll
            for (int mt = 0; mt < 4; mt++)
#pragma unroll
                for (int nt = 0; nt < 4; nt++)
                    mma8(acc[mt][nt], af[mt], bf[nt]);
        }
        if (more) {
            int nb = buf ^ 1;
            As[nb][skc+0][srow] = a0.x; As[nb][skc+1][srow] = a0.y;
            As[nb][skc+2][srow] = a0.z; As[nb][skc+3][srow] = a0.w;
            As[nb][skc+4][srow] = a1.x; As[nb][skc+5][srow] = a1.y;
            As[nb][skc+6][srow] = a1.z; As[nb][skc+7][srow] = a1.w;
            Bs[nb][skc+0][srow] = t32f(w0.x); Bs[nb][skc+1][srow] = t32f(w0.y);
            Bs[nb][skc+2][srow] = t32f(w0.z); Bs[nb][skc+3][srow] = t32f(w0.w);
            Bs[nb][skc+4][srow] = t32f(w1.x); Bs[nb][skc+5][srow] = t32f(w1.y);
            Bs[nb][skc+6][srow] = t32f(w1.z); Bs[nb][skc+7][srow] = t32f(w1.w);
        }
        buf ^= 1;
    }

    const float cw = g_w3[h * 3 + 0], covw = g_w3[h * 3 + 1], vw = g_w3[h * 3 + 2];
#pragma unroll
    for (int mt = 0; mt < 4; mt++) {
        const int row0 = q0 + wm + mt * 16 + g;
        const float qi0 = g_qinv[base + row0],     qm0 = g_qmean[base + row0],     qv0 = g_qvar[base + row0];
        const float qi1 = g_qinv[base + row0 + 8], qm1 = g_qmean[base + row0 + 8], qv1 = g_qvar[base + row0 + 8];
#pragma unroll
        for (int nt = 0; nt < 4; nt++) {
            const int col = wn + nt * 8 + 2 * q4;
            const int d = col >> 1;
            const float Skv = g_Mr[hb][col][64];
            const float Skm = g_Mr[hb][col][65];
            float o0 = cw * qi0 * acc[mt][nt][1] + (covw / DH) * acc[mt][nt][0]
                     + (vw / DH) * qv0 * Skv - covw * qm0 * Skm;
            float o1 = cw * qi1 * acc[mt][nt][3] + (covw / DH) * acc[mt][nt][2]
                     + (vw / DH) * qv1 * Skv - covw * qm1 * Skm;
            g_ao[(size_t)(b * Nn_ + row0) * DIM + h * DH + d]     = o0;
            g_ao[(size_t)(b * Nn_ + row0 + 8) * DIM + h * DH + d] = o1;
        }
    }
}

// ---------------- gating MLP (g_hg holds SUMS; scale by 1/ROWS) ----------------
__global__ void mlp_kernel(const float* __restrict__ W1, const float* __restrict__ b1,
                           const float* __restrict__ gg, const float* __restrict__ gb,
                           const float* __restrict__ W2, const float* __restrict__ b2)
{
    int h = threadIdx.x >> 5;
    int lane = threadIdx.x & 31;
    const float invR = 1.f / (float)ROWS;
    float h1[2];
#pragma unroll
    for (int t = 0; t < 2; t++) {
        int j = lane + t * 32;
        const float* wr = W1 + j * 128;
        float dot = 0.f;
        for (int i = 0; i < 64; i++) dot += g_hg[h * 64 + i] * wr[i];
        for (int i = 0; i < 64; i++) dot += g_hg[512 + h * 64 + i] * wr[64 + i];
        h1[t] = b1[j] + dot * invR;
    }
    float s = h1[0] + h1[1], ss = h1[0] * h1[0] + h1[1] * h1[1];
#pragma unroll
    for (int off = 16; off; off >>= 1) {
        s  += __shfl_xor_sync(0xffffffffu, s, off);
        ss += __shfl_xor_sync(0xffffffffu, ss, off);
    }
    float mean = s * (1.f / 64.f);
    float var  = ss * (1.f / 64.f) - mean * mean;
    float inv  = rsqrtf(var + EPS);
    float hh[2];
#pragma unroll
    for (int t = 0; t < 2; t++) {
        int j = lane + t * 32;
        float v = (h1[t] - mean) * inv * gg[j] + gb[j];
        hh[t] = fmaxf(v, 0.f);
    }
    float lg[3];
#pragma unroll
    for (int c = 0; c < 3; c++) {
        float acc = hh[0] * W2[c * 64 + lane] + hh[1] * W2[c * 64 + lane + 32];
#pragma unroll
        for (int off = 16; off; off >>= 1) acc += __shfl_xor_sync(0xffffffffu, acc, off);
        lg[c] = acc + b2[c];
    }
    if (lane == 0) {
        float m = fmaxf(lg[0], fmaxf(lg[1], lg[2]));
        float e0 = expf(lg[0] - m), e1 = expf(lg[1] - m), e2 = expf(lg[2] - m);
        float inv_s = 1.f / (e0 + e1 + e2);
        g_w3[h * 3 + 0] = e0 * inv_s;
        g_w3[h * 3 + 1] = e1 * inv_s;
        g_w3[h * 3 + 2] = e2 * inv_s;
    }
}

// ---------------- launch ----------------
extern "C" void kernel_launch(void* const* d_in, const int* in_sizes, int n_in,
                              void* d_out, int out_size)
{
    const float* q    = (const float*)d_in[0];
    const float* k    = (const float*)d_in[1];
    const float* v    = (const float*)d_in[2];
    const float* Win  = (const float*)d_in[3];
    const float* Wout = (const float*)d_in[4];
    const float* bout = (const float*)d_in[5];
    const float* g1   = (const float*)d_in[6];
    const float* b1n  = (const float*)d_in[7];
    const float* g2   = (const float*)d_in[8];
    const float* b2n  = (const float*)d_in[9];
    const float* Wup  = (const float*)d_in[10];
    const float* bup  = (const float*)d_in[11];
    const float* Wdn  = (const float*)d_in[12];
    const float* bdn  = (const float*)d_in[13];
    const float* wpW1 = (const float*)d_in[14];
    const float* wpb1 = (const float*)d_in[15];
    const float* wpg  = (const float*)d_in[16];
    const float* wpb  = (const float*)d_in[17];
    const float* wpW2 = (const float*)d_in[18];
    const float* wpb2 = (const float*)d_in[19];
    float* out = (float*)d_out;

    float* xn;  cudaGetSymbolAddress((void**)&xn,  g_xn);
    float* f;   cudaGetSymbolAddress((void**)&f,   g_f);
    float* ao;  cudaGetSymbolAddress((void**)&ao,  g_ao);
    float* q2;  cudaGetSymbolAddress((void**)&q2,  g_q2);
    float* xn2; cudaGetSymbolAddress((void**)&xn2, g_xn2);
    float* u;   cudaGetSymbolAddress((void**)&u,   g_u);

    const int smem4 = TS * (128 + 128) * 20 * 4;   // 81920 B (MT=4)
    const int smem2 = TS * (64 + 128) * 20 * 4;    // 61440 B (MT=2)
    cudaFuncSetAttribute(tmm3_kernel<4,4>, cudaFuncAttributeMaxDynamicSharedMemorySize, smem4);
    cudaFuncSetAttribute(tmm3_kernel<2,4>, cudaFuncAttributeMaxDynamicSharedMemorySize, smem4);
    cudaFuncSetAttribute(tmm3_kernel<3,2>, cudaFuncAttributeMaxDynamicSharedMemorySize, smem2);

    // 1. fused LN of q,k,v (also zeroes g_hg)
    ln3_kernel<<<3 * ROWS, 256>>>(q, k, v, g1, b1n, xn);

    // 2. fused projection + per-row stats + per-head column sums
    tmm3_kernel<4, 4><<<dim3(DIM / 128, 3 * ROWS / 128), 256, smem4>>>(
        xn, Win, nullptr, nullptr, f, 3 * ROWS, DIM, DIM);

    // 3. gating MLP
    mlp_kernel<<<1, 256>>>(wpW1, wpb1, wpg, wpb, wpW2, wpb2);

    // 4. attention via linear collapse
    mbuild_kernel<<<dim3(KSPLIT, HB), 256>>>();
    mreduce_kernel<<<(HB * 128 * MST) / (4 * 256), 256>>>();
    pgemm_kernel<<<dim3(Nn_ / 128, HB), 256>>>();

    // 5. attn out proj + residual -> q2
    tmm3_kernel<3, 2><<<dim3(DIM / 128, ROWS / 64), 256, smem2>>>(
        ao, Wout, bout, q, q2, ROWS, DIM, DIM);

    // 6. LN2
    ln_kernel<<<ROWS, 256>>>(q2, g2, b2n, xn2);

    // 7. MLP up + gelu
    tmm3_kernel<2, 4><<<dim3(MLPD / 128, ROWS / 128), 256, smem4>>>(
        xn2, Wup, bup, nullptr, u, ROWS, MLPD, DIM);

    // 8. MLP down + residual -> out
    tmm3_kernel<3, 2><<<dim3(DIM / 128, ROWS / 64), 256, smem2>>>(
        u, Wdn, bdn, q2, out, ROWS, DIM, MLPD);
}

// round 11
// speedup vs baseline: 1.3677x; 1.0410x over previous
#include <cuda_runtime.h>
#include <cuda_bf16.h>
#include <math.h>
#include <stdint.h>

// ---------------- problem constants ----------------
#define Bq   4
#define Nn_  1024
#define DIM  512
#define Hh   8
#define DH   64
#define MLPD 2048
#define ROWS (Bq * Nn_)            // 4096 token rows
#define HB   (Hh * Bq)             // 32 attention batches
#define EPS  1e-5f
#define MST  80
#define KSPLIT 8

// ---------------- tf32 mma helpers ----------------
__device__ __forceinline__ float t32f(float x){
    unsigned r; asm("cvt.rna.tf32.f32 %0,%1;" : "=r"(r) : "f"(x));
    return __uint_as_float(r);
}
__device__ __forceinline__ void mma8(float* c, const unsigned* a, const unsigned* b){
    asm("mma.sync.aligned.m16n8k8.row.col.f32.tf32.tf32.f32 "
        "{%0,%1,%2,%3},{%4,%5,%6,%7},{%8,%9},{%0,%1,%2,%3};"
        : "+f"(c[0]), "+f"(c[1]), "+f"(c[2]), "+f"(c[3])
        : "r"(a[0]), "r"(a[1]), "r"(a[2]), "r"(a[3]), "r"(b[0]), "r"(b[1]));
}
__device__ __forceinline__ unsigned smem_u32(const void* p){
    return (unsigned)__cvta_generic_to_shared((void*)p);
}
__device__ __forceinline__ void cpa16(unsigned dst, const float* src){
    asm volatile("cp.async.cg.shared.global [%0], [%1], 16;" :: "r"(dst), "l"(src) : "memory");
}
__device__ __forceinline__ void cp_commit(){
    asm volatile("cp.async.commit_group;" ::: "memory");
}
__device__ __forceinline__ void cp_wait2(){
    asm volatile("cp.async.wait_group 2;" ::: "memory");
}

// ---------------- device scratch (no allocs allowed) ----------------
__device__ float g_xn [3 * ROWS * DIM];
__device__ float g_f  [3 * ROWS * DIM];
__device__ float g_ao [ROWS * DIM];
__device__ float g_q2 [ROWS * DIM];
__device__ float g_xn2[ROWS * DIM];
__device__ float g_u  [ROWS * MLPD];
__device__ float g_wr [2621440];                 // tf32-rounded weights
__device__ float g_Mr [HB][128][MST];            // Mcat (atomic-accumulated)
__device__ float g_qinv [HB * Nn_];
__device__ float g_qmean[HB * Nn_];
__device__ float g_qvar [HB * Nn_];
__device__ float g_kinv [HB * Nn_];
__device__ float g_kmean[HB * Nn_];
__device__ float g_kvar [HB * Nn_];
__device__ float g_hg [2 * Hh * DH];
__device__ float g_w3 [Hh * 3];

// rounded-weight offsets (floats)
#define WR_WIN  0
#define WR_WOUT 262144
#define WR_WUP  524288
#define WR_WDN  1572864

// ---------------- weight pre-round: g_wr = tf32(W) ----------------
__global__ void wprep_kernel(const float* __restrict__ Win, const float* __restrict__ Wout,
                             const float* __restrict__ Wup, const float* __restrict__ Wdn)
{
    int i = blockIdx.x * 256 + threadIdx.x;     // float4 index, 655360 total
    const float* src; int dst;
    if (i < 65536)       { src = Win  + (size_t)i * 4;            dst = WR_WIN  + i * 4; }
    else if (i < 131072) { src = Wout + (size_t)(i - 65536) * 4;  dst = WR_WOUT + (i - 65536) * 4; }
    else if (i < 393216) { src = Wup  + (size_t)(i - 131072) * 4; dst = WR_WUP  + (i - 131072) * 4; }
    else                 { src = Wdn  + (size_t)(i - 393216) * 4; dst = WR_WDN  + (i - 393216) * 4; }
    float4 v = *(const float4*)src;
    *(float4*)&g_wr[dst] = make_float4(t32f(v.x), t32f(v.y), t32f(v.z), t32f(v.w));
}

// ---------------- warp-per-row LN of q,k,v (+ zero g_hg, g_Mr); tf32 output ----
__global__ void ln3_kernel(const float* __restrict__ q, const float* __restrict__ k,
                           const float* __restrict__ v, const float* __restrict__ g,
                           const float* __restrict__ bb, float* __restrict__ y)
{
    const int tid = threadIdx.x, lane = tid & 31, wid = tid >> 5;
    // side jobs: block 0 zeroes g_hg; blocks 1..320 zero g_Mr
    if (blockIdx.x == 0) {
        *(float4*)&g_hg[tid * 4] = make_float4(0.f, 0.f, 0.f, 0.f);
    } else if (blockIdx.x <= 320) {
        float* mr = &g_Mr[0][0][0];
        *(float4*)&mr[(blockIdx.x - 1) * 1024 + tid * 4] = make_float4(0.f, 0.f, 0.f, 0.f);
    }
    const int row = blockIdx.x * 8 + wid;           // 0 .. 12287
    const int which = row >> 12;
    const float* x = (which == 0) ? q : (which == 1) ? k : v;
    const float* xr = x + (size_t)(row & (ROWS - 1)) * DIM;
    float4 a[4];
    float s = 0.f, ss = 0.f;
#pragma unroll
    for (int c = 0; c < 4; c++) {
        a[c] = *(const float4*)(xr + c * 128 + lane * 4);
        s  += a[c].x + a[c].y + a[c].z + a[c].w;
        ss += a[c].x * a[c].x + a[c].y * a[c].y + a[c].z * a[c].z + a[c].w * a[c].w;
    }
#pragma unroll
    for (int off = 16; off; off >>= 1) {
        s  += __shfl_xor_sync(0xffffffffu, s, off);
        ss += __shfl_xor_sync(0xffffffffu, ss, off);
    }
    const float mean = s * (1.f / DIM);
    const float var  = ss * (1.f / DIM) - mean * mean;
    const float inv  = rsqrtf(var + EPS);
    float* yr = y + (size_t)row * DIM;
#pragma unroll
    for (int c = 0; c < 4; c++) {
        float4 gv = *(const float4*)(g  + c * 128 + lane * 4);
        float4 bv = *(const float4*)(bb + c * 128 + lane * 4);
        float4 o;
        o.x = t32f((a[c].x - mean) * inv * gv.x + bv.x);
        o.y = t32f((a[c].y - mean) * inv * gv.y + bv.y);
        o.z = t32f((a[c].z - mean) * inv * gv.z + bv.z);
        o.w = t32f((a[c].w - mean) * inv * gv.w + bv.w);
        *(float4*)(yr + c * 128 + lane * 4) = o;
    }
}

// ---------------- warp-per-row LN (single tensor, LN2); tf32 output ----------
__global__ void ln_kernel(const float* __restrict__ x, const float* __restrict__ g,
                          const float* __restrict__ bb, float* __restrict__ y)
{
    const int tid = threadIdx.x, lane = tid & 31, wid = tid >> 5;
    const int row = blockIdx.x * 8 + wid;
    const float* xr = x + (size_t)row * DIM;
    float4 a[4];
    float s = 0.f, ss = 0.f;
#pragma unroll
    for (int c = 0; c < 4; c++) {
        a[c] = *(const float4*)(xr + c * 128 + lane * 4);
        s  += a[c].x + a[c].y + a[c].z + a[c].w;
        ss += a[c].x * a[c].x + a[c].y * a[c].y + a[c].z * a[c].z + a[c].w * a[c].w;
    }
#pragma unroll
    for (int off = 16; off; off >>= 1) {
        s  += __shfl_xor_sync(0xffffffffu, s, off);
        ss += __shfl_xor_sync(0xffffffffu, ss, off);
    }
    const float mean = s * (1.f / DIM);
    const float var  = ss * (1.f / DIM) - mean * mean;
    const float inv  = rsqrtf(var + EPS);
    float* yr = y + (size_t)row * DIM;
#pragma unroll
    for (int c = 0; c < 4; c++) {
        float4 gv = *(const float4*)(g  + c * 128 + lane * 4);
        float4 bv = *(const float4*)(bb + c * 128 + lane * 4);
        float4 o;
        o.x = t32f((a[c].x - mean) * inv * gv.x + bv.x);
        o.y = t32f((a[c].y - mean) * inv * gv.y + bv.y);
        o.z = t32f((a[c].z - mean) * inv * gv.z + bv.z);
        o.w = t32f((a[c].w - mean) * inv * gv.w + bv.w);
        *(float4*)(yr + c * 128 + lane * 4) = o;
    }
}

// ================ tf32 mma GEMM, 4-stage cp.async pipeline ================
// C = A[M,K] @ W[N,K]^T.  CTA tile (MT*32) x 128, BK=16, S=4 stages.
// A and W must be pre-rounded to tf32 (producers / wprep).
// MODE: 2 +bias+gelu(out rounded), 3 +bias+residual, 4 plain+round + fused stats
#define TS 4

template <int MODE, int MT>
__global__ void __launch_bounds__(256) tmm3_kernel(
    const float* __restrict__ A, const float* __restrict__ W,
    const float* __restrict__ bias, const float* __restrict__ res,
    float* __restrict__ C, int M, int Nc, int K)
{
    constexpr int AR = MT * 32;
    extern __shared__ float sm[];
    float* Asm = sm;                        // [TS][AR][20]
    float* Bsm = sm + TS * AR * 20;         // [TS][128][20]
    __shared__ float sred[(MODE == 4) ? 8 * 4 * 8 * 4 : 4];
    __shared__ float colsum[(MODE == 4) ? 128 : 4];

    const int tid = threadIdx.x;
    const int lane = tid & 31, warp = tid >> 5;
    const int wm = (warp >> 2) * (MT * 16);
    const int wn = (warp & 3) * 32;
    const int m0 = blockIdx.y * AR, n0 = blockIdx.x * 128;
    const int g = lane >> 2, q4 = lane & 3;

    if (MODE == 4 && tid < 128) colsum[tid] = 0.f;

    float acc[MT][4][4];
#pragma unroll
    for (int i = 0; i < MT; i++)
#pragma unroll
        for (int j = 0; j < 4; j++)
#pragma unroll
            for (int c = 0; c < 4; c++) acc[i][j][c] = 0.f;

    const unsigned sAu = smem_u32(Asm);
    const unsigned sBu = smem_u32(Bsm);

    const int crow = tid >> 1, cko = (tid & 1) * 8;
    const int arow2 = tid >> 2, ako2 = (tid & 3) * 4;

    auto issue = [&](int s, int k0) {
        if (MT == 4) {
            unsigned d = sAu + (unsigned)(((s * 128 + crow) * 20 + cko) * 4);
            const float* p = A + (size_t)(m0 + crow) * K + k0 + cko;
            cpa16(d, p); cpa16(d + 16, p + 4);
        } else {
            unsigned d = sAu + (unsigned)(((s * 64 + arow2) * 20 + ako2) * 4);
            cpa16(d, A + (size_t)(m0 + arow2) * K + k0 + ako2);
        }
        unsigned d = sBu + (unsigned)(((s * 128 + crow) * 20 + cko) * 4);
        const float* p = W + (size_t)(n0 + crow) * K + k0 + cko;
        cpa16(d, p); cpa16(d + 16, p + 4);
    };

    issue(0, 0);  cp_commit();
    issue(1, 16); cp_commit();
    issue(2, 32); cp_commit();

    const int L = K / 16;
    int s = 0;
    for (int j = 0; j < L; j++) {
        cp_wait2();
        __syncthreads();
#pragma unroll
        for (int kc = 0; kc < 16; kc += 8) {
            unsigned af[MT][4], bf[4][2];
#pragma unroll
            for (int mt = 0; mt < MT; mt++) {
                const float* ar = &Asm[(s * AR + wm + mt * 16 + g) * 20 + kc + q4];
                af[mt][0] = __float_as_uint(ar[0]);
                af[mt][1] = __float_as_uint(ar[160]);
                af[mt][2] = __float_as_uint(ar[4]);
                af[mt][3] = __float_as_uint(ar[164]);
            }
#pragma unroll
            for (int nt = 0; nt < 4; nt++) {
                const float* br = &Bsm[(s * 128 + wn + nt * 8 + g) * 20 + kc + q4];
                bf[nt][0] = __float_as_uint(br[0]);
                bf[nt][1] = __float_as_uint(br[4]);
            }
#pragma unroll
            for (int mt = 0; mt < MT; mt++)
#pragma unroll
                for (int nt = 0; nt < 4; nt++)
                    mma8(acc[mt][nt], af[mt], bf[nt]);
        }
        if (j + 3 < L) {
            int ws = s + 3; if (ws >= TS) ws -= TS;
            issue(ws, (j + 3) * 16);
        }
        cp_commit();
        s++; if (s == TS) s = 0;
    }

    const int which = m0 >> 12;

    float csA[4], csB[4];
#pragma unroll
    for (int nt = 0; nt < 4; nt++) { csA[nt] = 0.f; csB[nt] = 0.f; }

#pragma unroll
    for (int mt = 0; mt < MT; mt++) {
        const int row0 = m0 + wm + mt * 16 + g;
        float s0 = 0.f, ss0 = 0.f, s1 = 0.f, ss1 = 0.f;
#pragma unroll
        for (int nt = 0; nt < 4; nt++) {
            const int col = n0 + wn + nt * 8 + 2 * q4;
            float v0 = acc[mt][nt][0], v1 = acc[mt][nt][1];
            float v2 = acc[mt][nt][2], v3 = acc[mt][nt][3];
            if (MODE == 2 || MODE == 3) {
                float2 bv = *(const float2*)&bias[col];
                v0 += bv.x; v1 += bv.y; v2 += bv.x; v3 += bv.y;
            }
            if (MODE == 2) {
                v0 = t32f(0.5f * v0 * (1.f + erff(v0 * 0.70710678118654752f)));
                v1 = t32f(0.5f * v1 * (1.f + erff(v1 * 0.70710678118654752f)));
                v2 = t32f(0.5f * v2 * (1.f + erff(v2 * 0.70710678118654752f)));
                v3 = t32f(0.5f * v3 * (1.f + erff(v3 * 0.70710678118654752f)));
            }
            if (MODE == 3) {
                float2 r0 = *(const float2*)(res + (size_t)row0 * Nc + col);
                float2 r1 = *(const float2*)(res + (size_t)(row0 + 8) * Nc + col);
                v0 += r0.x; v1 += r0.y; v2 += r1.x; v3 += r1.y;
            }
            if (MODE == 4) {
                v0 = t32f(v0); v1 = t32f(v1); v2 = t32f(v2); v3 = t32f(v3);
                s0 += v0 + v1; ss0 += v0 * v0 + v1 * v1;
                s1 += v2 + v3; ss1 += v2 * v2 + v3 * v3;
                csA[nt] += v0 + v2;
                csB[nt] += v1 + v3;
            }
            *(float2*)(C + (size_t)row0 * Nc + col)       = make_float2(v0, v1);
            *(float2*)(C + (size_t)(row0 + 8) * Nc + col) = make_float2(v2, v3);
        }
        if (MODE == 4) {
            s0 += __shfl_xor_sync(0xffffffffu, s0, 1);  s0 += __shfl_xor_sync(0xffffffffu, s0, 2);
            ss0 += __shfl_xor_sync(0xffffffffu, ss0, 1); ss0 += __shfl_xor_sync(0xffffffffu, ss0, 2);
            s1 += __shfl_xor_sync(0xffffffffu, s1, 1);  s1 += __shfl_xor_sync(0xffffffffu, s1, 2);
            ss1 += __shfl_xor_sync(0xffffffffu, ss1, 1); ss1 += __shfl_xor_sync(0xffffffffu, ss1, 2);
            if (q4 == 0) {
                float* sp = &sred[((warp * MT + mt) * 8 + g) * 4];
                sp[0] = s0; sp[1] = ss0; sp[2] = s1; sp[3] = ss1;
            }
        }
    }

    if (MODE == 4) {
        if (which < 2) {
#pragma unroll
            for (int nt = 0; nt < 4; nt++) {
                csA[nt] += __shfl_xor_sync(0xffffffffu, csA[nt], 4);
                csA[nt] += __shfl_xor_sync(0xffffffffu, csA[nt], 8);
                csA[nt] += __shfl_xor_sync(0xffffffffu, csA[nt], 16);
                csB[nt] += __shfl_xor_sync(0xffffffffu, csB[nt], 4);
                csB[nt] += __shfl_xor_sync(0xffffffffu, csB[nt], 8);
                csB[nt] += __shfl_xor_sync(0xffffffffu, csB[nt], 16);
                if (g == 0) {
                    atomicAdd(&colsum[wn + nt * 8 + 2 * q4],     csA[nt]);
                    atomicAdd(&colsum[wn + nt * 8 + 2 * q4 + 1], csB[nt]);
                }
            }
        }
        __syncthreads();
        if (which < 2) {
            if (tid < 128) atomicAdd(&g_hg[which * 512 + n0 + tid], colsum[tid]);
            const int p   = tid >> 6;
            const int mt2 = (tid >> 4) & 3;
            const int g2  = (tid >> 1) & 7;
            const int rr  = tid & 1;
            const int w0 = 2 * p;
            const float* e0 = &sred[((w0 * MT + mt2) * 8 + g2) * 4];
            const float* e1 = &sred[(((w0 + 1) * MT + mt2) * 8 + g2) * 4];
            float sA  = e0[2 * rr]     + e1[2 * rr];
            float ssA = e0[2 * rr + 1] + e1[2 * rr + 1];
            int row = m0 + (p >> 1) * 64 + mt2 * 16 + g2 + rr * 8;
            int lr2 = row & (ROWS - 1);
            int b3 = lr2 >> 10, n3 = lr2 & 1023;
            int head = (n0 >> 6) + (p & 1);
            int idx = (head * 4 + b3) * 1024 + n3;
            float mean = sA * (1.f / 64.f);
            float var  = (ssA - sA * sA * (1.f / 64.f)) * (1.f / 63.f);
            float inv  = rsqrtf(ssA);
            if (which == 0) { g_qinv[idx] = inv; g_qmean[idx] = mean; g_qvar[idx] = var; }
            else            { g_kinv[idx] = inv; g_kmean[idx] = mean; g_kvar[idx] = var; }
        }
    }
}

// ================ mbuild: Mcat partials atomically accumulated into g_Mr ======
__global__ void __launch_bounds__(256) mbuild_kernel()
{
    __shared__ float As[2][16][136];
    __shared__ float Bs[2][16][72];
    const int tid = threadIdx.x, lane = tid & 31, warp = tid >> 5;
    const int ks = blockIdx.x, hb = blockIdx.y, h = hb >> 2, b = hb & 3;
    const int base = hb * Nn_;
    const int g = lane >> 2, q4 = lane & 3;
    const int m0 = ks * (Nn_ / KSPLIT);

    const float* fk = g_f + (size_t)ROWS * DIM;
    const float* fv = g_f + 2 * (size_t)ROWS * DIM;

    float acc[9][4];
#pragma unroll
    for (int j = 0; j < 9; j++)
#pragma unroll
        for (int c = 0; c < 4; c++) acc[j][c] = 0.f;

    const int srow = tid >> 4;
    const int dc = (tid & 15) * 4;

    {
        int m = m0 + srow;
        float ki = g_kinv[base + m];
        float4 vv = *(const float4*)(fv + (size_t)(b*Nn_ + m)*DIM + h*DH + dc);
        float4 kk = *(const float4*)(fk + (size_t)(b*Nn_ + m)*DIM + h*DH + dc);
        float* ar = &As[0][srow][2*dc];
        ar[0] = vv.x; ar[1] = t32f(ki*vv.x);
        ar[2] = vv.y; ar[3] = t32f(ki*vv.y);
        ar[4] = vv.z; ar[5] = t32f(ki*vv.z);
        ar[6] = vv.w; ar[7] = t32f(ki*vv.w);
        *(float4*)&Bs[0][srow][dc] = kk;
        if (tid < 128) {
            int r = tid >> 3, s = tid & 7;
            int mm = m0 + r;
            float v = 0.f;
            if (s == 0) v = t32f(g_kvar [base + mm]);
            else if (s == 1) v = t32f(g_kmean[base + mm]);
            Bs[0][r][64 + s] = v;
        }
    }

    int buf = 0;
    const int KC = Nn_ / KSPLIT;
    for (int k0 = 16; k0 <= KC; k0 += 16) {
        __syncthreads();
        const bool more = (k0 < KC);
        float4 vv, kk; float ki = 0.f, xv = 0.f;
        if (more) {
            int m = m0 + k0 + srow;
            vv = *(const float4*)(fv + (size_t)(b*Nn_ + m)*DIM + h*DH + dc);
            kk = *(const float4*)(fk + (size_t)(b*Nn_ + m)*DIM + h*DH + dc);
            ki = g_kinv[base + m];
            if (tid < 128) {
                int r = tid >> 3, s = tid & 7;
                int mm = m0 + k0 + r;
                if (s == 0) xv = t32f(g_kvar [base + mm]);
                else if (s == 1) xv = t32f(g_kmean[base + mm]);
            }
        }
#pragma unroll
        for (int ks8 = 0; ks8 < 16; ks8 += 8) {
            unsigned af[4];
            const int mr = warp * 16 + g;
            af[0] = __float_as_uint(As[buf][ks8 + q4][mr]);
            af[1] = __float_as_uint(As[buf][ks8 + q4][mr + 8]);
            af[2] = __float_as_uint(As[buf][ks8 + 4 + q4][mr]);
            af[3] = __float_as_uint(As[buf][ks8 + 4 + q4][mr + 8]);
#pragma unroll
            for (int nt = 0; nt < 9; nt++) {
                unsigned bf[2];
                bf[0] = __float_as_uint(Bs[buf][ks8 + q4][nt * 8 + g]);
                bf[1] = __float_as_uint(Bs[buf][ks8 + 4 + q4][nt * 8 + g]);
                mma8(acc[nt], af, bf);
            }
        }
        if (more) {
            int nb = buf ^ 1;
            float* ar = &As[nb][srow][2*dc];
            ar[0] = vv.x; ar[1] = t32f(ki*vv.x);
            ar[2] = vv.y; ar[3] = t32f(ki*vv.y);
            ar[4] = vv.z; ar[5] = t32f(ki*vv.z);
            ar[6] = vv.w; ar[7] = t32f(ki*vv.w);
            *(float4*)&Bs[nb][srow][dc] = kk;
            if (tid < 128) {
                int r = tid >> 3, s = tid & 7;
                Bs[nb][r][64 + s] = xv;
            }
        }
        buf ^= 1;
    }

    const int row0 = warp * 16 + g;
#pragma unroll
    for (int nt = 0; nt < 9; nt++) {
        const int col = nt * 8 + 2 * q4;
        atomicAdd(&g_Mr[hb][row0][col],         acc[nt][0]);
        atomicAdd(&g_Mr[hb][row0][col + 1],     acc[nt][1]);
        atomicAdd(&g_Mr[hb][row0 + 8][col],     acc[nt][2]);
        atomicAdd(&g_Mr[hb][row0 + 8][col + 1], acc[nt][3]);
    }
}

// ================ pgemm: O = combine(fq @ Mcat^T) per hb; output tf32 ========
__global__ void __launch_bounds__(256) pgemm_kernel()
{
    __shared__ float As[2][16][136];
    __shared__ float Bs[2][16][136];
    const int tid = threadIdx.x;
    const int lane = tid & 31, warp = tid >> 5;
    const int wm = (warp >> 2) * 64, wn = (warp & 3) * 32;
    const int hb = blockIdx.y, h = hb >> 2, b = hb & 3;
    const int q0 = blockIdx.x * 128;
    const int base = hb * Nn_;
    const int g = lane >> 2, q4 = lane & 3;

    const float* fq = g_f;

    float acc[4][4][4];
#pragma unroll
    for (int i = 0; i < 4; i++)
#pragma unroll
        for (int j = 0; j < 4; j++)
#pragma unroll
            for (int c = 0; c < 4; c++) acc[i][j][c] = 0.f;

    const int srow = tid >> 1, skc = (tid & 1) * 8;
    const float* Apt = fq + (size_t)(b * Nn_ + q0 + srow) * DIM + h * DH + skc;
    const float* Wpt = &g_Mr[hb][srow][skc];

    {
        float4 a0 = *(const float4*)(Apt);
        float4 a1 = *(const float4*)(Apt + 4);
        float4 w0 = *(const float4*)(Wpt);
        float4 w1 = *(const float4*)(Wpt + 4);
        As[0][skc+0][srow] = a0.x; As[0][skc+1][srow] = a0.y;
        As[0][skc+2][srow] = a0.z; As[0][skc+3][srow] = a0.w;
        As[0][skc+4][srow] = a1.x; As[0][skc+5][srow] = a1.y;
        As[0][skc+6][srow] = a1.z; As[0][skc+7][srow] = a1.w;
        Bs[0][skc+0][srow] = t32f(w0.x); Bs[0][skc+1][srow] = t32f(w0.y);
        Bs[0][skc+2][srow] = t32f(w0.z); Bs[0][skc+3][srow] = t32f(w0.w);
        Bs[0][skc+4][srow] = t32f(w1.x); Bs[0][skc+5][srow] = t32f(w1.y);
        Bs[0][skc+6][srow] = t32f(w1.z); Bs[0][skc+7][srow] = t32f(w1.w);
    }

    int buf = 0;
    for (int k0 = 16; k0 <= DH; k0 += 16) {
        __syncthreads();
        const bool more = (k0 < DH);
        float4 a0, a1, w0, w1;
        if (more) {
            a0 = *(const float4*)(Apt + k0);
            a1 = *(const float4*)(Apt + k0 + 4);
            w0 = *(const float4*)(Wpt + k0);
            w1 = *(const float4*)(Wpt + k0 + 4);
        }
#pragma unroll
        for (int ks = 0; ks < 16; ks += 8) {
            unsigned af[4][4], bf[4][2];
#pragma unroll
            for (int mt = 0; mt < 4; mt++) {
                int mr = wm + mt * 16 + g;
                af[mt][0] = __float_as_uint(As[buf][ks + q4][mr]);
                af[mt][1] = __float_as_uint(As[buf][ks + q4][mr + 8]);
                af[mt][2] = __float_as_uint(As[buf][ks + 4 + q4][mr]);
                af[mt][3] = __float_as_uint(As[buf][ks + 4 + q4][mr + 8]);
            }
#pragma unroll
            for (int nt = 0; nt < 4; nt++) {
                int nc = wn + nt * 8 + g;
                bf[nt][0] = __float_as_uint(Bs[buf][ks + q4][nc]);
                bf[nt][1] = __float_as_uint(Bs[buf][ks + 4 + q4][nc]);
            }
#pragma unroll
            for (int mt = 0; mt < 4; mt++)
#pragma unroll
                for (int nt = 0; nt < 4; nt++)
                    mma8(acc[mt][nt], af[mt], bf[nt]);
        }
        if (more) {
            int nb = buf ^ 1;
            As[nb][skc+0][srow] = a0.x; As[nb][skc+1][srow] = a0.y;
            As[nb][skc+2][srow] = a0.z; As[nb][skc+3][srow] = a0.w;
            As[nb][skc+4][srow] = a1.x; As[nb][skc+5][srow] = a1.y;
            As[nb][skc+6][srow] = a1.z; As[nb][skc+7][srow] = a1.w;
            Bs[nb][skc+0][srow] = t32f(w0.x); Bs[nb][skc+1][srow] = t32f(w0.y);
            Bs[nb][skc+2][srow] = t32f(w0.z); Bs[nb][skc+3][srow] = t32f(w0.w);
            Bs[nb][skc+4][srow] = t32f(w1.x); Bs[nb][skc+5][srow] = t32f(w1.y);
            Bs[nb][skc+6][srow] = t32f(w1.z); Bs[nb][skc+7][srow] = t32f(w1.w);
        }
        buf ^= 1;
    }

    const float cw = g_w3[h * 3 + 0], covw = g_w3[h * 3 + 1], vw = g_w3[h * 3 + 2];
#pragma unroll
    for (int mt = 0; mt < 4; mt++) {
        const int row0 = q0 + wm + mt * 16 + g;
        const float qi0 = g_qinv[base + row0],     qm0 = g_qmean[base + row0],     qv0 = g_qvar[base + row0];
        const float qi1 = g_qinv[base + row0 + 8], qm1 = g_qmean[base + row0 + 8], qv1 = g_qvar[base + row0 + 8];
#pragma unroll
        for (int nt = 0; nt < 4; nt++) {
            const int col = wn + nt * 8 + 2 * q4;
            const int d = col >> 1;
            const float Skv = g_Mr[hb][col][64];
            const float Skm = g_Mr[hb][col][65];
            float o0 = cw * qi0 * acc[mt][nt][1] + (covw / DH) * acc[mt][nt][0]
                     + (vw / DH) * qv0 * Skv - covw * qm0 * Skm;
            float o1 = cw * qi1 * acc[mt][nt][3] + (covw / DH) * acc[mt][nt][2]
                     + (vw / DH) * qv1 * Skv - covw * qm1 * Skm;
            g_ao[(size_t)(b * Nn_ + row0) * DIM + h * DH + d]     = t32f(o0);
            g_ao[(size_t)(b * Nn_ + row0 + 8) * DIM + h * DH + d] = t32f(o1);
        }
    }
}

// ---------------- gating MLP (g_hg holds SUMS; scale by 1/ROWS) ----------------
__global__ void mlp_kernel(const float* __restrict__ W1, const float* __restrict__ b1,
                           const float* __restrict__ gg, const float* __restrict__ gb,
                           const float* __restrict__ W2, const float* __restrict__ b2)
{
    int h = threadIdx.x >> 5;
    int lane = threadIdx.x & 31;
    const float invR = 1.f / (float)ROWS;
    float h1[2];
#pragma unroll
    for (int t = 0; t < 2; t++) {
        int j = lane + t * 32;
        const float* wr = W1 + j * 128;
        float dot = 0.f;
        for (int i = 0; i < 64; i++) dot += g_hg[h * 64 + i] * wr[i];
        for (int i = 0; i < 64; i++) dot += g_hg[512 + h * 64 + i] * wr[64 + i];
        h1[t] = b1[j] + dot * invR;
    }
    float s = h1[0] + h1[1], ss = h1[0] * h1[0] + h1[1] * h1[1];
#pragma unroll
    for (int off = 16; off; off >>= 1) {
        s  += __shfl_xor_sync(0xffffffffu, s, off);
        ss += __shfl_xor_sync(0xffffffffu, ss, off);
    }
    float mean = s * (1.f / 64.f);
    float var  = ss * (1.f / 64.f) - mean * mean;
    float inv  = rsqrtf(var + EPS);
    float hh[2];
#pragma unroll
    for (int t = 0; t < 2; t++) {
        int j = lane + t * 32;
        float v = (h1[t] - mean) * inv * gg[j] + gb[j];
        hh[t] = fmaxf(v, 0.f);
    }
    float lg[3];
#pragma unroll
    for (int c = 0; c < 3; c++) {
        float acc = hh[0] * W2[c * 64 + lane] + hh[1] * W2[c * 64 + lane + 32];
#pragma unroll
        for (int off = 16; off; off >>= 1) acc += __shfl_xor_sync(0xffffffffu, acc, off);
        lg[c] = acc + b2[c];
    }
    if (lane == 0) {
        float m = fmaxf(lg[0], fmaxf(lg[1], lg[2]));
        float e0 = expf(lg[0] - m), e1 = expf(lg[1] - m), e2 = expf(lg[2] - m);
        float inv_s = 1.f / (e0 + e1 + e2);
        g_w3[h * 3 + 0] = e0 * inv_s;
        g_w3[h * 3 + 1] = e1 * inv_s;
        g_w3[h * 3 + 2] = e2 * inv_s;
    }
}

// ---------------- launch ----------------
extern "C" void kernel_launch(void* const* d_in, const int* in_sizes, int n_in,
                              void* d_out, int out_size)
{
    const float* q    = (const float*)d_in[0];
    const float* k    = (const float*)d_in[1];
    const float* v    = (const float*)d_in[2];
    const float* Win  = (const float*)d_in[3];
    const float* Wout = (const float*)d_in[4];
    const float* bout = (const float*)d_in[5];
    const float* g1   = (const float*)d_in[6];
    const float* b1n  = (const float*)d_in[7];
    const float* g2   = (const float*)d_in[8];
    const float* b2n  = (const float*)d_in[9];
    const float* Wup  = (const float*)d_in[10];
    const float* bup  = (const float*)d_in[11];
    const float* Wdn  = (const float*)d_in[12];
    const float* bdn  = (const float*)d_in[13];
    const float* wpW1 = (const float*)d_in[14];
    const float* wpb1 = (const float*)d_in[15];
    const float* wpg  = (const float*)d_in[16];
    const float* wpb  = (const float*)d_in[17];
    const float* wpW2 = (const float*)d_in[18];
    const float* wpb2 = (const float*)d_in[19];
    float* out = (float*)d_out;

    float* xn;  cudaGetSymbolAddress((void**)&xn,  g_xn);
    float* f;   cudaGetSymbolAddress((void**)&f,   g_f);
    float* ao;  cudaGetSymbolAddress((void**)&ao,  g_ao);
    float* q2;  cudaGetSymbolAddress((void**)&q2,  g_q2);
    float* xn2; cudaGetSymbolAddress((void**)&xn2, g_xn2);
    float* u;   cudaGetSymbolAddress((void**)&u,   g_u);
    float* wr;  cudaGetSymbolAddress((void**)&wr,  g_wr);

    const int smem4 = TS * (128 + 128) * 20 * 4;   // 81920 B (MT=4)
    const int smem2 = TS * (64 + 128) * 20 * 4;    // 61440 B (MT=2)
    cudaFuncSetAttribute(tmm3_kernel<4,4>, cudaFuncAttributeMaxDynamicSharedMemorySize, smem4);
    cudaFuncSetAttribute(tmm3_kernel<2,4>, cudaFuncAttributeMaxDynamicSharedMemorySize, smem4);
    cudaFuncSetAttribute(tmm3_kernel<3,2>, cudaFuncAttributeMaxDynamicSharedMemorySize, smem2);

    // 0. pre-round weights to tf32
    wprep_kernel<<<2560, 256>>>(Win, Wout, Wup, Wdn);

    // 1. fused LN of q,k,v (tf32 out; also zeroes g_hg + g_Mr)
    ln3_kernel<<<3 * ROWS / 8, 256>>>(q, k, v, g1, b1n, xn);

    // 2. fused projection + per-row stats + per-head column sums
    tmm3_kernel<4, 4><<<dim3(DIM / 128, 3 * ROWS / 128), 256, smem4>>>(
        xn, wr + WR_WIN, nullptr, nullptr, f, 3 * ROWS, DIM, DIM);

    // 3. gating MLP
    mlp_kernel<<<1, 256>>>(wpW1, wpb1, wpg, wpb, wpW2, wpb2);

    // 4. attention via linear collapse (mbuild accumulates g_Mr atomically)
    mbuild_kernel<<<dim3(KSPLIT, HB), 256>>>();
    pgemm_kernel<<<dim3(Nn_ / 128, HB), 256>>>();

    // 5. attn out proj + residual -> q2
    tmm3_kernel<3, 2><<<dim3(DIM / 128, ROWS / 64), 256, smem2>>>(
        ao, wr + WR_WOUT, bout, q, q2, ROWS, DIM, DIM);

    // 6. LN2 (tf32 out)
    ln_kernel<<<ROWS / 8, 256>>>(q2, g2, b2n, xn2);

    // 7. MLP up + gelu (tf32 out)
    tmm3_kernel<2, 4><<<dim3(MLPD / 128, ROWS / 128), 256, smem4>>>(
        xn2, wr + WR_WUP, bup, nullptr, u, ROWS, MLPD, DIM);

    // 8. MLP down + residual -> out
    tmm3_kernel<3, 2><<<dim3(DIM / 128, ROWS / 64), 256, smem2>>>(
        u, wr + WR_WDN, bdn, q2, out, ROWS, DIM, MLPD);
}

// round 12
// speedup vs baseline: 1.4183x; 1.0370x over previous
#include <cuda_runtime.h>
#include <cuda_bf16.h>
#include <math.h>
#include <stdint.h>

// ---------------- problem constants ----------------
#define Bq   4
#define Nn_  1024
#define DIM  512
#define Hh   8
#define DH   64
#define MLPD 2048
#define ROWS (Bq * Nn_)            // 4096 token rows
#define HB   (Hh * Bq)             // 32 attention batches
#define EPS  1e-5f
#define MST  80
#define KSPLIT 8

// ---------------- tf32 mma helpers ----------------
__device__ __forceinline__ float t32f(float x){
    unsigned r; asm("cvt.rna.tf32.f32 %0,%1;" : "=r"(r) : "f"(x));
    return __uint_as_float(r);
}
__device__ __forceinline__ void mma8(float* c, const unsigned* a, const unsigned* b){
    asm("mma.sync.aligned.m16n8k8.row.col.f32.tf32.tf32.f32 "
        "{%0,%1,%2,%3},{%4,%5,%6,%7},{%8,%9},{%0,%1,%2,%3};"
        : "+f"(c[0]), "+f"(c[1]), "+f"(c[2]), "+f"(c[3])
        : "r"(a[0]), "r"(a[1]), "r"(a[2]), "r"(a[3]), "r"(b[0]), "r"(b[1]));
}
__device__ __forceinline__ unsigned smem_u32(const void* p){
    return (unsigned)__cvta_generic_to_shared((void*)p);
}
__device__ __forceinline__ void cpa16(unsigned dst, const float* src){
    asm volatile("cp.async.cg.shared.global [%0], [%1], 16;" :: "r"(dst), "l"(src) : "memory");
}
__device__ __forceinline__ void cp_commit(){
    asm volatile("cp.async.commit_group;" ::: "memory");
}
__device__ __forceinline__ void cp_wait2(){
    asm volatile("cp.async.wait_group 2;" ::: "memory");
}

// ---------------- device scratch (no allocs allowed) ----------------
__device__ float g_xn [3 * ROWS * DIM];
__device__ float g_f  [3 * ROWS * DIM];
__device__ float g_ao [ROWS * DIM];
__device__ float g_q2 [ROWS * DIM];
__device__ float g_xn2[ROWS * DIM];
__device__ float g_u  [ROWS * MLPD];
__device__ float g_wr [2621440];                 // tf32-rounded weights
__device__ float g_Mr [HB][128][MST];            // Mcat (atomic-accumulated)
__device__ float g_qinv [HB * Nn_];
__device__ float g_qmean[HB * Nn_];
__device__ float g_qvar [HB * Nn_];
__device__ float g_kinv [HB * Nn_];
__device__ float g_kmean[HB * Nn_];
__device__ float g_kvar [HB * Nn_];
__device__ float g_hg [2 * Hh * DH];
__device__ float g_w3 [Hh * 3];

// rounded-weight offsets (floats)
#define WR_WIN  0
#define WR_WOUT 262144
#define WR_WUP  524288
#define WR_WDN  1572864

// ---------------- weight pre-round: g_wr = tf32(W) ----------------
__global__ void wprep_kernel(const float* __restrict__ Win, const float* __restrict__ Wout,
                             const float* __restrict__ Wup, const float* __restrict__ Wdn)
{
    int i = blockIdx.x * 256 + threadIdx.x;     // float4 index, 655360 total
    const float* src; int dst;
    if (i < 65536)       { src = Win  + (size_t)i * 4;            dst = WR_WIN  + i * 4; }
    else if (i < 131072) { src = Wout + (size_t)(i - 65536) * 4;  dst = WR_WOUT + (i - 65536) * 4; }
    else if (i < 393216) { src = Wup  + (size_t)(i - 131072) * 4; dst = WR_WUP  + (i - 131072) * 4; }
    else                 { src = Wdn  + (size_t)(i - 393216) * 4; dst = WR_WDN  + (i - 393216) * 4; }
    float4 v = *(const float4*)src;
    *(float4*)&g_wr[dst] = make_float4(t32f(v.x), t32f(v.y), t32f(v.z), t32f(v.w));
}

// ---------------- warp-per-row LN of q,k,v (+ zero g_hg, g_Mr); tf32 output ----
__global__ void ln3_kernel(const float* __restrict__ q, const float* __restrict__ k,
                           const float* __restrict__ v, const float* __restrict__ g,
                           const float* __restrict__ bb, float* __restrict__ y)
{
    const int tid = threadIdx.x, lane = tid & 31, wid = tid >> 5;
    if (blockIdx.x == 0) {
        *(float4*)&g_hg[tid * 4] = make_float4(0.f, 0.f, 0.f, 0.f);
    } else if (blockIdx.x <= 320) {
        float* mr = &g_Mr[0][0][0];
        *(float4*)&mr[(blockIdx.x - 1) * 1024 + tid * 4] = make_float4(0.f, 0.f, 0.f, 0.f);
    }
    const int row = blockIdx.x * 8 + wid;
    const int which = row >> 12;
    const float* x = (which == 0) ? q : (which == 1) ? k : v;
    const float* xr = x + (size_t)(row & (ROWS - 1)) * DIM;
    float4 a[4];
    float s = 0.f, ss = 0.f;
#pragma unroll
    for (int c = 0; c < 4; c++) {
        a[c] = *(const float4*)(xr + c * 128 + lane * 4);
        s  += a[c].x + a[c].y + a[c].z + a[c].w;
        ss += a[c].x * a[c].x + a[c].y * a[c].y + a[c].z * a[c].z + a[c].w * a[c].w;
    }
#pragma unroll
    for (int off = 16; off; off >>= 1) {
        s  += __shfl_xor_sync(0xffffffffu, s, off);
        ss += __shfl_xor_sync(0xffffffffu, ss, off);
    }
    const float mean = s * (1.f / DIM);
    const float var  = ss * (1.f / DIM) - mean * mean;
    const float inv  = rsqrtf(var + EPS);
    float* yr = y + (size_t)row * DIM;
#pragma unroll
    for (int c = 0; c < 4; c++) {
        float4 gv = *(const float4*)(g  + c * 128 + lane * 4);
        float4 bv = *(const float4*)(bb + c * 128 + lane * 4);
        float4 o;
        o.x = t32f((a[c].x - mean) * inv * gv.x + bv.x);
        o.y = t32f((a[c].y - mean) * inv * gv.y + bv.y);
        o.z = t32f((a[c].z - mean) * inv * gv.z + bv.z);
        o.w = t32f((a[c].w - mean) * inv * gv.w + bv.w);
        *(float4*)(yr + c * 128 + lane * 4) = o;
    }
}

// ---------------- warp-per-row LN (single tensor, LN2); tf32 output ----------
__global__ void ln_kernel(const float* __restrict__ x, const float* __restrict__ g,
                          const float* __restrict__ bb, float* __restrict__ y)
{
    const int tid = threadIdx.x, lane = tid & 31, wid = tid >> 5;
    const int row = blockIdx.x * 8 + wid;
    const float* xr = x + (size_t)row * DIM;
    float4 a[4];
    float s = 0.f, ss = 0.f;
#pragma unroll
    for (int c = 0; c < 4; c++) {
        a[c] = *(const float4*)(xr + c * 128 + lane * 4);
        s  += a[c].x + a[c].y + a[c].z + a[c].w;
        ss += a[c].x * a[c].x + a[c].y * a[c].y + a[c].z * a[c].z + a[c].w * a[c].w;
    }
#pragma unroll
    for (int off = 16; off; off >>= 1) {
        s  += __shfl_xor_sync(0xffffffffu, s, off);
        ss += __shfl_xor_sync(0xffffffffu, ss, off);
    }
    const float mean = s * (1.f / DIM);
    const float var  = ss * (1.f / DIM) - mean * mean;
    const float inv  = rsqrtf(var + EPS);
    float* yr = y + (size_t)row * DIM;
#pragma unroll
    for (int c = 0; c < 4; c++) {
        float4 gv = *(const float4*)(g  + c * 128 + lane * 4);
        float4 bv = *(const float4*)(bb + c * 128 + lane * 4);
        float4 o;
        o.x = t32f((a[c].x - mean) * inv * gv.x + bv.x);
        o.y = t32f((a[c].y - mean) * inv * gv.y + bv.y);
        o.z = t32f((a[c].z - mean) * inv * gv.z + bv.z);
        o.w = t32f((a[c].w - mean) * inv * gv.w + bv.w);
        *(float4*)(yr + c * 128 + lane * 4) = o;
    }
}

// ================ tf32 mma GEMM, 4-stage cp.async pipeline ================
#define TS 4

template <int MODE, int MT>
__global__ void __launch_bounds__(256) tmm3_kernel(
    const float* __restrict__ A, const float* __restrict__ W,
    const float* __restrict__ bias, const float* __restrict__ res,
    float* __restrict__ C, int M, int Nc, int K)
{
    constexpr int AR = MT * 32;
    extern __shared__ float sm[];
    float* Asm = sm;                        // [TS][AR][20]
    float* Bsm = sm + TS * AR * 20;         // [TS][128][20]
    __shared__ float sred[(MODE == 4) ? 8 * 4 * 8 * 4 : 4];
    __shared__ float colsum[(MODE == 4) ? 128 : 4];

    const int tid = threadIdx.x;
    const int lane = tid & 31, warp = tid >> 5;
    const int wm = (warp >> 2) * (MT * 16);
    const int wn = (warp & 3) * 32;
    const int m0 = blockIdx.y * AR, n0 = blockIdx.x * 128;
    const int g = lane >> 2, q4 = lane & 3;

    if (MODE == 4 && tid < 128) colsum[tid] = 0.f;

    float acc[MT][4][4];
#pragma unroll
    for (int i = 0; i < MT; i++)
#pragma unroll
        for (int j = 0; j < 4; j++)
#pragma unroll
            for (int c = 0; c < 4; c++) acc[i][j][c] = 0.f;

    const unsigned sAu = smem_u32(Asm);
    const unsigned sBu = smem_u32(Bsm);

    const int crow = tid >> 1, cko = (tid & 1) * 8;
    const int arow2 = tid >> 2, ako2 = (tid & 3) * 4;

    auto issue = [&](int s, int k0) {
        if (MT == 4) {
            unsigned d = sAu + (unsigned)(((s * 128 + crow) * 20 + cko) * 4);
            const float* p = A + (size_t)(m0 + crow) * K + k0 + cko;
            cpa16(d, p); cpa16(d + 16, p + 4);
        } else {
            unsigned d = sAu + (unsigned)(((s * 64 + arow2) * 20 + ako2) * 4);
            cpa16(d, A + (size_t)(m0 + arow2) * K + k0 + ako2);
        }
        unsigned d = sBu + (unsigned)(((s * 128 + crow) * 20 + cko) * 4);
        const float* p = W + (size_t)(n0 + crow) * K + k0 + cko;
        cpa16(d, p); cpa16(d + 16, p + 4);
    };

    issue(0, 0);  cp_commit();
    issue(1, 16); cp_commit();
    issue(2, 32); cp_commit();

    const int L = K / 16;
    int s = 0;
    for (int j = 0; j < L; j++) {
        cp_wait2();
        __syncthreads();
#pragma unroll
        for (int kc = 0; kc < 16; kc += 8) {
            unsigned af[MT][4], bf[4][2];
#pragma unroll
            for (int mt = 0; mt < MT; mt++) {
                const float* ar = &Asm[(s * AR + wm + mt * 16 + g) * 20 + kc + q4];
                af[mt][0] = __float_as_uint(ar[0]);
                af[mt][1] = __float_as_uint(ar[160]);
                af[mt][2] = __float_as_uint(ar[4]);
                af[mt][3] = __float_as_uint(ar[164]);
            }
#pragma unroll
            for (int nt = 0; nt < 4; nt++) {
                const float* br = &Bsm[(s * 128 + wn + nt * 8 + g) * 20 + kc + q4];
                bf[nt][0] = __float_as_uint(br[0]);
                bf[nt][1] = __float_as_uint(br[4]);
            }
#pragma unroll
            for (int mt = 0; mt < MT; mt++)
#pragma unroll
                for (int nt = 0; nt < 4; nt++)
                    mma8(acc[mt][nt], af[mt], bf[nt]);
        }
        if (j + 3 < L) {
            int ws = s + 3; if (ws >= TS) ws -= TS;
            issue(ws, (j + 3) * 16);
        }
        cp_commit();
        s++; if (s == TS) s = 0;
    }

    const int which = m0 >> 12;

    float csA[4], csB[4];
#pragma unroll
    for (int nt = 0; nt < 4; nt++) { csA[nt] = 0.f; csB[nt] = 0.f; }

#pragma unroll
    for (int mt = 0; mt < MT; mt++) {
        const int row0 = m0 + wm + mt * 16 + g;
        float s0 = 0.f, ss0 = 0.f, s1 = 0.f, ss1 = 0.f;
#pragma unroll
        for (int nt = 0; nt < 4; nt++) {
            const int col = n0 + wn + nt * 8 + 2 * q4;
            float v0 = acc[mt][nt][0], v1 = acc[mt][nt][1];
            float v2 = acc[mt][nt][2], v3 = acc[mt][nt][3];
            if (MODE == 2 || MODE == 3) {
                float2 bv = *(const float2*)&bias[col];
                v0 += bv.x; v1 += bv.y; v2 += bv.x; v3 += bv.y;
            }
            if (MODE == 2) {
                v0 = t32f(0.5f * v0 * (1.f + erff(v0 * 0.70710678118654752f)));
                v1 = t32f(0.5f * v1 * (1.f + erff(v1 * 0.70710678118654752f)));
                v2 = t32f(0.5f * v2 * (1.f + erff(v2 * 0.70710678118654752f)));
                v3 = t32f(0.5f * v3 * (1.f + erff(v3 * 0.70710678118654752f)));
            }
            if (MODE == 3) {
                float2 r0 = *(const float2*)(res + (size_t)row0 * Nc + col);
                float2 r1 = *(const float2*)(res + (size_t)(row0 + 8) * Nc + col);
                v0 += r0.x; v1 += r0.y; v2 += r1.x; v3 += r1.y;
            }
            if (MODE == 4) {
                v0 = t32f(v0); v1 = t32f(v1); v2 = t32f(v2); v3 = t32f(v3);
                s0 += v0 + v1; ss0 += v0 * v0 + v1 * v1;
                s1 += v2 + v3; ss1 += v2 * v2 + v3 * v3;
                csA[nt] += v0 + v2;
                csB[nt] += v1 + v3;
            }
            *(float2*)(C + (size_t)row0 * Nc + col)       = make_float2(v0, v1);
            *(float2*)(C + (size_t)(row0 + 8) * Nc + col) = make_float2(v2, v3);
        }
        if (MODE == 4) {
            s0 += __shfl_xor_sync(0xffffffffu, s0, 1);  s0 += __shfl_xor_sync(0xffffffffu, s0, 2);
            ss0 += __shfl_xor_sync(0xffffffffu, ss0, 1); ss0 += __shfl_xor_sync(0xffffffffu, ss0, 2);
            s1 += __shfl_xor_sync(0xffffffffu, s1, 1);  s1 += __shfl_xor_sync(0xffffffffu, s1, 2);
            ss1 += __shfl_xor_sync(0xffffffffu, ss1, 1); ss1 += __shfl_xor_sync(0xffffffffu, ss1, 2);
            if (q4 == 0) {
                float* sp = &sred[((warp * MT + mt) * 8 + g) * 4];
                sp[0] = s0; sp[1] = ss0; sp[2] = s1; sp[3] = ss1;
            }
        }
    }

    if (MODE == 4) {
        if (which < 2) {
#pragma unroll
            for (int nt = 0; nt < 4; nt++) {
                csA[nt] += __shfl_xor_sync(0xffffffffu, csA[nt], 4);
                csA[nt] += __shfl_xor_sync(0xffffffffu, csA[nt], 8);
                csA[nt] += __shfl_xor_sync(0xffffffffu, csA[nt], 16);
                csB[nt] += __shfl_xor_sync(0xffffffffu, csB[nt], 4);
                csB[nt] += __shfl_xor_sync(0xffffffffu, csB[nt], 8);
                csB[nt] += __shfl_xor_sync(0xffffffffu, csB[nt], 16);
                if (g == 0) {
                    atomicAdd(&colsum[wn + nt * 8 + 2 * q4],     csA[nt]);
                    atomicAdd(&colsum[wn + nt * 8 + 2 * q4 + 1], csB[nt]);
                }
            }
        }
        __syncthreads();
        if (which < 2) {
            if (tid < 128) atomicAdd(&g_hg[which * 512 + n0 + tid], colsum[tid]);
            const int p   = tid >> 6;
            const int mt2 = (tid >> 4) & 3;
            const int g2  = (tid >> 1) & 7;
            const int rr  = tid & 1;
            const int w0 = 2 * p;
            const float* e0 = &sred[((w0 * MT + mt2) * 8 + g2) * 4];
            const float* e1 = &sred[(((w0 + 1) * MT + mt2) * 8 + g2) * 4];
            float sA  = e0[2 * rr]     + e1[2 * rr];
            float ssA = e0[2 * rr + 1] + e1[2 * rr + 1];
            int row = m0 + (p >> 1) * 64 + mt2 * 16 + g2 + rr * 8;
            int lr2 = row & (ROWS - 1);
            int b3 = lr2 >> 10, n3 = lr2 & 1023;
            int head = (n0 >> 6) + (p & 1);
            int idx = (head * 4 + b3) * 1024 + n3;
            float mean = sA * (1.f / 64.f);
            float var  = (ssA - sA * sA * (1.f / 64.f)) * (1.f / 63.f);
            float inv  = rsqrtf(ssA);
            if (which == 0) { g_qinv[idx] = inv; g_qmean[idx] = mean; g_qvar[idx] = var; }
            else            { g_kinv[idx] = inv; g_kmean[idx] = mean; g_kvar[idx] = var; }
        }
    }
}

// ================ mbuild: Mcat partials atomically accumulated into g_Mr ======
__global__ void __launch_bounds__(256) mbuild_kernel()
{
    __shared__ float As[2][16][136];
    __shared__ float Bs[2][16][72];
    const int tid = threadIdx.x, lane = tid & 31, warp = tid >> 5;
    const int ks = blockIdx.x, hb = blockIdx.y, h = hb >> 2, b = hb & 3;
    const int base = hb * Nn_;
    const int g = lane >> 2, q4 = lane & 3;
    const int m0 = ks * (Nn_ / KSPLIT);

    const float* fk = g_f + (size_t)ROWS * DIM;
    const float* fv = g_f + 2 * (size_t)ROWS * DIM;

    float acc[9][4];
#pragma unroll
    for (int j = 0; j < 9; j++)
#pragma unroll
        for (int c = 0; c < 4; c++) acc[j][c] = 0.f;

    const int srow = tid >> 4;
    const int dc = (tid & 15) * 4;

    {
        int m = m0 + srow;
        float ki = g_kinv[base + m];
        float4 vv = *(const float4*)(fv + (size_t)(b*Nn_ + m)*DIM + h*DH + dc);
        float4 kk = *(const float4*)(fk + (size_t)(b*Nn_ + m)*DIM + h*DH + dc);
        float* ar = &As[0][srow][2*dc];
        ar[0] = vv.x; ar[1] = t32f(ki*vv.x);
        ar[2] = vv.y; ar[3] = t32f(ki*vv.y);
        ar[4] = vv.z; ar[5] = t32f(ki*vv.z);
        ar[6] = vv.w; ar[7] = t32f(ki*vv.w);
        *(float4*)&Bs[0][srow][dc] = kk;
        if (tid < 128) {
            int r = tid >> 3, s = tid & 7;
            int mm = m0 + r;
            float v = 0.f;
            if (s == 0) v = t32f(g_kvar [base + mm]);
            else if (s == 1) v = t32f(g_kmean[base + mm]);
            Bs[0][r][64 + s] = v;
        }
    }

    int buf = 0;
    const int KC = Nn_ / KSPLIT;
    for (int k0 = 16; k0 <= KC; k0 += 16) {
        __syncthreads();
        const bool more = (k0 < KC);
        float4 vv, kk; float ki = 0.f, xv = 0.f;
        if (more) {
            int m = m0 + k0 + srow;
            vv = *(const float4*)(fv + (size_t)(b*Nn_ + m)*DIM + h*DH + dc);
            kk = *(const float4*)(fk + (size_t)(b*Nn_ + m)*DIM + h*DH + dc);
            ki = g_kinv[base + m];
            if (tid < 128) {
                int r = tid >> 3, s = tid & 7;
                int mm = m0 + k0 + r;
                if (s == 0) xv = t32f(g_kvar [base + mm]);
                else if (s == 1) xv = t32f(g_kmean[base + mm]);
            }
        }
#pragma unroll
        for (int ks8 = 0; ks8 < 16; ks8 += 8) {
            unsigned af[4];
            const int mr = warp * 16 + g;
            af[0] = __float_as_uint(As[buf][ks8 + q4][mr]);
            af[1] = __float_as_uint(As[buf][ks8 + q4][mr + 8]);
            af[2] = __float_as_uint(As[buf][ks8 + 4 + q4][mr]);
            af[3] = __float_as_uint(As[buf][ks8 + 4 + q4][mr + 8]);
#pragma unroll
            for (int nt = 0; nt < 9; nt++) {
                unsigned bf[2];
                bf[0] = __float_as_uint(Bs[buf][ks8 + q4][nt * 8 + g]);
                bf[1] = __float_as_uint(Bs[buf][ks8 + 4 + q4][nt * 8 + g]);
                mma8(acc[nt], af, bf);
            }
        }
        if (more) {
            int nb = buf ^ 1;
            float* ar = &As[nb][srow][2*dc];
            ar[0] = vv.x; ar[1] = t32f(ki*vv.x);
            ar[2] = vv.y; ar[3] = t32f(ki*vv.y);
            ar[4] = vv.z; ar[5] = t32f(ki*vv.z);
            ar[6] = vv.w; ar[7] = t32f(ki*vv.w);
            *(float4*)&Bs[nb][srow][dc] = kk;
            if (tid < 128) {
                int r = tid >> 3, s = tid & 7;
                Bs[nb][r][64 + s] = xv;
            }
        }
        buf ^= 1;
    }

    const int row0 = warp * 16 + g;
#pragma unroll
    for (int nt = 0; nt < 9; nt++) {
        const int col = nt * 8 + 2 * q4;
        atomicAdd(&g_Mr[hb][row0][col],         acc[nt][0]);
        atomicAdd(&g_Mr[hb][row0][col + 1],     acc[nt][1]);
        atomicAdd(&g_Mr[hb][row0 + 8][col],     acc[nt][2]);
        atomicAdd(&g_Mr[hb][row0 + 8][col + 1], acc[nt][3]);
    }
}

// ================ pgemm: O = combine(fq @ Mcat^T) per hb; output tf32 ========
__global__ void __launch_bounds__(256) pgemm_kernel()
{
    __shared__ float As[2][16][136];
    __shared__ float Bs[2][16][136];
    const int tid = threadIdx.x;
    const int lane = tid & 31, warp = tid >> 5;
    const int wm = (warp >> 2) * 64, wn = (warp & 3) * 32;
    const int hb = blockIdx.y, h = hb >> 2, b = hb & 3;
    const int q0 = blockIdx.x * 128;
    const int base = hb * Nn_;
    const int g = lane >> 2, q4 = lane & 3;

    const float* fq = g_f;

    float acc[4][4][4];
#pragma unroll
    for (int i = 0; i < 4; i++)
#pragma unroll
        for (int j = 0; j < 4; j++)
#pragma unroll
            for (int c = 0; c < 4; c++) acc[i][j][c] = 0.f;

    const int srow = tid >> 1, skc = (tid & 1) * 8;
    const float* Apt = fq + (size_t)(b * Nn_ + q0 + srow) * DIM + h * DH + skc;
    const float* Wpt = &g_Mr[hb][srow][skc];

    {
        float4 a0 = *(const float4*)(Apt);
        float4 a1 = *(const float4*)(Apt + 4);
        float4 w0 = *(const float4*)(Wpt);
        float4 w1 = *(const float4*)(Wpt + 4);
        As[0][skc+0][srow] = a0.x; As[0][skc+1][srow] = a0.y;
        As[0][skc+2][srow] = a0.z; As[0][skc+3][srow] = a0.w;
        As[0][skc+4][srow] = a1.x; As[0][skc+5][srow] = a1.y;
        As[0][skc+6][srow] = a1.z; As[0][skc+7][srow] = a1.w;
        Bs[0][skc+0][srow] = t32f(w0.x); Bs[0][skc+1][srow] = t32f(w0.y);
        Bs[0][skc+2][srow] = t32f(w0.z); Bs[0][skc+3][srow] = t32f(w0.w);
        Bs[0][skc+4][srow] = t32f(w1.x); Bs[0][skc+5][srow] = t32f(w1.y);
        Bs[0][skc+6][srow] = t32f(w1.z); Bs[0][skc+7][srow] = t32f(w1.w);
    }

    int buf = 0;
    for (int k0 = 16; k0 <= DH; k0 += 16) {
        __syncthreads();
        const bool more = (k0 < DH);
        float4 a0, a1, w0, w1;
        if (more) {
            a0 = *(const float4*)(Apt + k0);
            a1 = *(const float4*)(Apt + k0 + 4);
            w0 = *(const float4*)(Wpt + k0);
            w1 = *(const float4*)(Wpt + k0 + 4);
        }
#pragma unroll
        for (int ks = 0; ks < 16; ks += 8) {
            unsigned af[4][4], bf[4][2];
#pragma unroll
            for (int mt = 0; mt < 4; mt++) {
                int mr = wm + mt * 16 + g;
                af[mt][0] = __float_as_uint(As[buf][ks + q4][mr]);
                af[mt][1] = __float_as_uint(As[buf][ks + q4][mr + 8]);
                af[mt][2] = __float_as_uint(As[buf][ks + 4 + q4][mr]);
                af[mt][3] = __float_as_uint(As[buf][ks + 4 + q4][mr + 8]);
            }
#pragma unroll
            for (int nt = 0; nt < 4; nt++) {
                int nc = wn + nt * 8 + g;
                bf[nt][0] = __float_as_uint(Bs[buf][ks + q4][nc]);
                bf[nt][1] = __float_as_uint(Bs[buf][ks + 4 + q4][nc]);
            }
#pragma unroll
            for (int mt = 0; mt < 4; mt++)
#pragma unroll
                for (int nt = 0; nt < 4; nt++)
                    mma8(acc[mt][nt], af[mt], bf[nt]);
        }
        if (more) {
            int nb = buf ^ 1;
            As[nb][skc+0][srow] = a0.x; As[nb][skc+1][srow] = a0.y;
            As[nb][skc+2][srow] = a0.z; As[nb][skc+3][srow] = a0.w;
            As[nb][skc+4][srow] = a1.x; As[nb][skc+5][srow] = a1.y;
            As[nb][skc+6][srow] = a1.z; As[nb][skc+7][srow] = a1.w;
            Bs[nb][skc+0][srow] = t32f(w0.x); Bs[nb][skc+1][srow] = t32f(w0.y);
            Bs[nb][skc+2][srow] = t32f(w0.z); Bs[nb][skc+3][srow] = t32f(w0.w);
            Bs[nb][skc+4][srow] = t32f(w1.x); Bs[nb][skc+5][srow] = t32f(w1.y);
            Bs[nb][skc+6][srow] = t32f(w1.z); Bs[nb][skc+7][srow] = t32f(w1.w);
        }
        buf ^= 1;
    }

    const float cw = g_w3[h * 3 + 0], covw = g_w3[h * 3 + 1], vw = g_w3[h * 3 + 2];
#pragma unroll
    for (int mt = 0; mt < 4; mt++) {
        const int row0 = q0 + wm + mt * 16 + g;
        const float qi0 = g_qinv[base + row0],     qm0 = g_qmean[base + row0],     qv0 = g_qvar[base + row0];
        const float qi1 = g_qinv[base + row0 + 8], qm1 = g_qmean[base + row0 + 8], qv1 = g_qvar[base + row0 + 8];
#pragma unroll
        for (int nt = 0; nt < 4; nt++) {
            const int col = wn + nt * 8 + 2 * q4;
            const int d = col >> 1;
            const float Skv = g_Mr[hb][col][64];
            const float Skm = g_Mr[hb][col][65];
            float o0 = cw * qi0 * acc[mt][nt][1] + (covw / DH) * acc[mt][nt][0]
                     + (vw / DH) * qv0 * Skv - covw * qm0 * Skm;
            float o1 = cw * qi1 * acc[mt][nt][3] + (covw / DH) * acc[mt][nt][2]
                     + (vw / DH) * qv1 * Skv - covw * qm1 * Skm;
            g_ao[(size_t)(b * Nn_ + row0) * DIM + h * DH + d]     = t32f(o0);
            g_ao[(size_t)(b * Nn_ + row0 + 8) * DIM + h * DH + d] = t32f(o1);
        }
    }
}

// ---------------- gating MLP (smem-staged W1/g_hg; g_hg holds SUMS) ----------
__global__ void mlp_kernel(const float* __restrict__ W1, const float* __restrict__ b1,
                           const float* __restrict__ gg, const float* __restrict__ gb,
                           const float* __restrict__ W2, const float* __restrict__ b2)
{
    __shared__ float W1s[64 * 128];   // 32 KB
    __shared__ float hgs[1024];
    const int tid = threadIdx.x;
    // coalesced staging: W1 8192 floats, hgs 1024 floats
#pragma unroll
    for (int c = 0; c < 8; c++)
        *(float4*)&W1s[(c * 256 + tid) * 4] = *(const float4*)&W1[(c * 256 + tid) * 4];
    *(float4*)&hgs[tid * 4] = *(const float4*)&g_hg[tid * 4];
    __syncthreads();

    int h = tid >> 5;
    int lane = tid & 31;
    const float invR = 1.f / (float)ROWS;
    float h1[2];
#pragma unroll
    for (int t = 0; t < 2; t++) {
        int j = lane + t * 32;
        const float* wr = &W1s[j * 128];
        float dot = 0.f;
#pragma unroll 8
        for (int i = 0; i < 64; i++) dot += hgs[h * 64 + i] * wr[i];
#pragma unroll 8
        for (int i = 0; i < 64; i++) dot += hgs[512 + h * 64 + i] * wr[64 + i];
        h1[t] = b1[j] + dot * invR;
    }
    float s = h1[0] + h1[1], ss = h1[0] * h1[0] + h1[1] * h1[1];
#pragma unroll
    for (int off = 16; off; off >>= 1) {
        s  += __shfl_xor_sync(0xffffffffu, s, off);
        ss += __shfl_xor_sync(0xffffffffu, ss, off);
    }
    float mean = s * (1.f / 64.f);
    float var  = ss * (1.f / 64.f) - mean * mean;
    float inv  = rsqrtf(var + EPS);
    float hh[2];
#pragma unroll
    for (int t = 0; t < 2; t++) {
        int j = lane + t * 32;
        float v = (h1[t] - mean) * inv * gg[j] + gb[j];
        hh[t] = fmaxf(v, 0.f);
    }
    float lg[3];
#pragma unroll
    for (int c = 0; c < 3; c++) {
        float acc = hh[0] * W2[c * 64 + lane] + hh[1] * W2[c * 64 + lane + 32];
#pragma unroll
        for (int off = 16; off; off >>= 1) acc += __shfl_xor_sync(0xffffffffu, acc, off);
        lg[c] = acc + b2[c];
    }
    if (lane == 0) {
        float m = fmaxf(lg[0], fmaxf(lg[1], lg[2]));
        float e0 = expf(lg[0] - m), e1 = expf(lg[1] - m), e2 = expf(lg[2] - m);
        float inv_s = 1.f / (e0 + e1 + e2);
        g_w3[h * 3 + 0] = e0 * inv_s;
        g_w3[h * 3 + 1] = e1 * inv_s;
        g_w3[h * 3 + 2] = e2 * inv_s;
    }
}

// ---------------- launch ----------------
extern "C" void kernel_launch(void* const* d_in, const int* in_sizes, int n_in,
                              void* d_out, int out_size)
{
    const float* q    = (const float*)d_in[0];
    const float* k    = (const float*)d_in[1];
    const float* v    = (const float*)d_in[2];
    const float* Win  = (const float*)d_in[3];
    const float* Wout = (const float*)d_in[4];
    const float* bout = (const float*)d_in[5];
    const float* g1   = (const float*)d_in[6];
    const float* b1n  = (const float*)d_in[7];
    const float* g2   = (const float*)d_in[8];
    const float* b2n  = (const float*)d_in[9];
    const float* Wup  = (const float*)d_in[10];
    const float* bup  = (const float*)d_in[11];
    const float* Wdn  = (const float*)d_in[12];
    const float* bdn  = (const float*)d_in[13];
    const float* wpW1 = (const float*)d_in[14];
    const float* wpb1 = (const float*)d_in[15];
    const float* wpg  = (const float*)d_in[16];
    const float* wpb  = (const float*)d_in[17];
    const float* wpW2 = (const float*)d_in[18];
    const float* wpb2 = (const float*)d_in[19];
    float* out = (float*)d_out;

    float* xn;  cudaGetSymbolAddress((void**)&xn,  g_xn);
    float* f;   cudaGetSymbolAddress((void**)&f,   g_f);
    float* ao;  cudaGetSymbolAddress((void**)&ao,  g_ao);
    float* q2;  cudaGetSymbolAddress((void**)&q2,  g_q2);
    float* xn2; cudaGetSymbolAddress((void**)&xn2, g_xn2);
    float* u;   cudaGetSymbolAddress((void**)&u,   g_u);
    float* wr;  cudaGetSymbolAddress((void**)&wr,  g_wr);

    const int smem4 = TS * (128 + 128) * 20 * 4;   // 81920 B (MT=4)
    const int smem2 = TS * (64 + 128) * 20 * 4;    // 61440 B (MT=2)
    cudaFuncSetAttribute(tmm3_kernel<4,4>, cudaFuncAttributeMaxDynamicSharedMemorySize, smem4);
    cudaFuncSetAttribute(tmm3_kernel<2,4>, cudaFuncAttributeMaxDynamicSharedMemorySize, smem4);
    cudaFuncSetAttribute(tmm3_kernel<3,2>, cudaFuncAttributeMaxDynamicSharedMemorySize, smem2);

    // 0. pre-round weights to tf32
    wprep_kernel<<<2560, 256>>>(Win, Wout, Wup, Wdn);

    // 1. fused LN of q,k,v (tf32 out; also zeroes g_hg + g_Mr)
    ln3_kernel<<<3 * ROWS / 8, 256>>>(q, k, v, g1, b1n, xn);

    // 2. fused projection + per-row stats + per-head column sums
    tmm3_kernel<4, 4><<<dim3(DIM / 128, 3 * ROWS / 128), 256, smem4>>>(
        xn, wr + WR_WIN, nullptr, nullptr, f, 3 * ROWS, DIM, DIM);

    // 3. gating MLP
    mlp_kernel<<<1, 256>>>(wpW1, wpb1, wpg, wpb, wpW2, wpb2);

    // 4. attention via linear collapse (mbuild accumulates g_Mr atomically)
    mbuild_kernel<<<dim3(KSPLIT, HB), 256>>>();
    pgemm_kernel<<<dim3(Nn_ / 128, HB), 256>>>();

    // 5. attn out proj + residual -> q2
    tmm3_kernel<3, 2><<<dim3(DIM / 128, ROWS / 64), 256, smem2>>>(
        ao, wr + WR_WOUT, bout, q, q2, ROWS, DIM, DIM);

    // 6. LN2 (tf32 out)
    ln_kernel<<<ROWS / 8, 256>>>(q2, g2, b2n, xn2);

    // 7. MLP up + gelu (tf32 out)
    tmm3_kernel<2, 4><<<dim3(MLPD / 128, ROWS / 128), 256, smem4>>>(
        xn2, wr + WR_WUP, bup, nullptr, u, ROWS, MLPD, DIM);

    // 8. MLP down + residual -> out
    tmm3_kernel<3, 2><<<dim3(DIM / 128, ROWS / 64), 256, smem2>>>(
        u, wr + WR_WDN, bdn, q2, out, ROWS, DIM, MLPD);
}

// round 13
// speedup vs baseline: 1.4242x; 1.0041x over previous
#include <cuda_runtime.h>
#include <cuda_bf16.h>
#include <math.h>
#include <stdint.h>

// ---------------- problem constants ----------------
#define Bq   4
#define Nn_  1024
#define DIM  512
#define Hh   8
#define DH   64
#define MLPD 2048
#define ROWS (Bq * Nn_)            // 4096 token rows
#define HB   (Hh * Bq)             // 32 attention batches
#define EPS  1e-5f
#define MST  80
#define KSPLIT 8

// ---------------- tf32 mma helpers ----------------
__device__ __forceinline__ float t32f(float x){
    unsigned r; asm("cvt.rna.tf32.f32 %0,%1;" : "=r"(r) : "f"(x));
    return __uint_as_float(r);
}
__device__ __forceinline__ void mma8(float* c, const unsigned* a, const unsigned* b){
    asm("mma.sync.aligned.m16n8k8.row.col.f32.tf32.tf32.f32 "
        "{%0,%1,%2,%3},{%4,%5,%6,%7},{%8,%9},{%0,%1,%2,%3};"
        : "+f"(c[0]), "+f"(c[1]), "+f"(c[2]), "+f"(c[3])
        : "r"(a[0]), "r"(a[1]), "r"(a[2]), "r"(a[3]), "r"(b[0]), "r"(b[1]));
}
__device__ __forceinline__ unsigned smem_u32(const void* p){
    return (unsigned)__cvta_generic_to_shared((void*)p);
}
__device__ __forceinline__ void cpa16(unsigned dst, const float* src){
    asm volatile("cp.async.cg.shared.global [%0], [%1], 16;" :: "r"(dst), "l"(src) : "memory");
}
__device__ __forceinline__ void cp_commit(){
    asm volatile("cp.async.commit_group;" ::: "memory");
}
__device__ __forceinline__ void cp_wait2(){
    asm volatile("cp.async.wait_group 2;" ::: "memory");
}

// ---------------- device scratch (no allocs allowed) ----------------
__device__ float g_xn [3 * ROWS * DIM];
__device__ float g_f  [3 * ROWS * DIM];
__device__ float g_ao [ROWS * DIM];
__device__ float g_q2 [ROWS * DIM];
__device__ float g_xn2[ROWS * DIM];
__device__ float g_u  [ROWS * MLPD];
__device__ float g_wr [2621440];                 // tf32-rounded weights
__device__ float g_Mr [HB][128][MST];            // Mcat (atomic-accumulated)
__device__ float g_qinv [HB * Nn_];
__device__ float g_qmean[HB * Nn_];
__device__ float g_qvar [HB * Nn_];
__device__ float g_kinv [HB * Nn_];
__device__ float g_kmean[HB * Nn_];
__device__ float g_kvar [HB * Nn_];
__device__ float g_hg [2 * Hh * DH];
__device__ float g_w3 [Hh * 3];

// rounded-weight offsets (floats)
#define WR_WIN  0
#define WR_WOUT 262144
#define WR_WUP  524288
#define WR_WDN  1572864

// ---------------- LN of q,k,v + zero g_hg/g_Mr + weight pre-round ----------
__global__ void ln3_kernel(const float* __restrict__ q, const float* __restrict__ k,
                           const float* __restrict__ v, const float* __restrict__ g,
                           const float* __restrict__ bb, float* __restrict__ y,
                           const float* __restrict__ Win, const float* __restrict__ Wout,
                           const float* __restrict__ Wup, const float* __restrict__ Wdn)
{
    const int tid = threadIdx.x, lane = tid & 31, wid = tid >> 5;
    // side job A: zero g_hg / g_Mr
    if (blockIdx.x == 0) {
        *(float4*)&g_hg[tid * 4] = make_float4(0.f, 0.f, 0.f, 0.f);
    } else if (blockIdx.x <= 320) {
        float* mr = &g_Mr[0][0][0];
        *(float4*)&mr[(blockIdx.x - 1) * 1024 + tid * 4] = make_float4(0.f, 0.f, 0.f, 0.f);
    }
    // side job B: round weights to tf32 (655360 float4 over 1536x256 threads)
    {
        int i = blockIdx.x * 256 + tid;
#pragma unroll
        for (int rep = 0; rep < 2; rep++) {
            if (i < 655360) {
                const float* src; int dst;
                if (i < 65536)       { src = Win  + (size_t)i * 4;            dst = WR_WIN  + i * 4; }
                else if (i < 131072) { src = Wout + (size_t)(i - 65536) * 4;  dst = WR_WOUT + (i - 65536) * 4; }
                else if (i < 393216) { src = Wup  + (size_t)(i - 131072) * 4; dst = WR_WUP  + (i - 131072) * 4; }
                else                 { src = Wdn  + (size_t)(i - 393216) * 4; dst = WR_WDN  + (i - 393216) * 4; }
                float4 w = *(const float4*)src;
                *(float4*)&g_wr[dst] = make_float4(t32f(w.x), t32f(w.y), t32f(w.z), t32f(w.w));
            }
            i += 393216;
        }
    }
    // main job: LN row
    const int row = blockIdx.x * 8 + wid;
    const int which = row >> 12;
    const float* x = (which == 0) ? q : (which == 1) ? k : v;
    const float* xr = x + (size_t)(row & (ROWS - 1)) * DIM;
    float4 a[4];
    float s = 0.f, ss = 0.f;
#pragma unroll
    for (int c = 0; c < 4; c++) {
        a[c] = *(const float4*)(xr + c * 128 + lane * 4);
        s  += a[c].x + a[c].y + a[c].z + a[c].w;
        ss += a[c].x * a[c].x + a[c].y * a[c].y + a[c].z * a[c].z + a[c].w * a[c].w;
    }
#pragma unroll
    for (int off = 16; off; off >>= 1) {
        s  += __shfl_xor_sync(0xffffffffu, s, off);
        ss += __shfl_xor_sync(0xffffffffu, ss, off);
    }
    const float mean = s * (1.f / DIM);
    const float var  = ss * (1.f / DIM) - mean * mean;
    const float inv  = rsqrtf(var + EPS);
    float* yr = y + (size_t)row * DIM;
#pragma unroll
    for (int c = 0; c < 4; c++) {
        float4 gv = *(const float4*)(g  + c * 128 + lane * 4);
        float4 bv = *(const float4*)(bb + c * 128 + lane * 4);
        float4 o;
        o.x = t32f((a[c].x - mean) * inv * gv.x + bv.x);
        o.y = t32f((a[c].y - mean) * inv * gv.y + bv.y);
        o.z = t32f((a[c].z - mean) * inv * gv.z + bv.z);
        o.w = t32f((a[c].w - mean) * inv * gv.w + bv.w);
        *(float4*)(yr + c * 128 + lane * 4) = o;
    }
}

// ---------------- warp-per-row LN (single tensor, LN2); tf32 output ----------
__global__ void ln_kernel(const float* __restrict__ x, const float* __restrict__ g,
                          const float* __restrict__ bb, float* __restrict__ y)
{
    const int tid = threadIdx.x, lane = tid & 31, wid = tid >> 5;
    const int row = blockIdx.x * 8 + wid;
    const float* xr = x + (size_t)row * DIM;
    float4 a[4];
    float s = 0.f, ss = 0.f;
#pragma unroll
    for (int c = 0; c < 4; c++) {
        a[c] = *(const float4*)(xr + c * 128 + lane * 4);
        s  += a[c].x + a[c].y + a[c].z + a[c].w;
        ss += a[c].x * a[c].x + a[c].y * a[c].y + a[c].z * a[c].z + a[c].w * a[c].w;
    }
#pragma unroll
    for (int off = 16; off; off >>= 1) {
        s  += __shfl_xor_sync(0xffffffffu, s, off);
        ss += __shfl_xor_sync(0xffffffffu, ss, off);
    }
    const float mean = s * (1.f / DIM);
    const float var  = ss * (1.f / DIM) - mean * mean;
    const float inv  = rsqrtf(var + EPS);
    float* yr = y + (size_t)row * DIM;
#pragma unroll
    for (int c = 0; c < 4; c++) {
        float4 gv = *(const float4*)(g  + c * 128 + lane * 4);
        float4 bv = *(const float4*)(bb + c * 128 + lane * 4);
        float4 o;
        o.x = t32f((a[c].x - mean) * inv * gv.x + bv.x);
        o.y = t32f((a[c].y - mean) * inv * gv.y + bv.y);
        o.z = t32f((a[c].z - mean) * inv * gv.z + bv.z);
        o.w = t32f((a[c].w - mean) * inv * gv.w + bv.w);
        *(float4*)(yr + c * 128 + lane * 4) = o;
    }
}

// ================ tf32 mma GEMM, 4-stage cp.async pipeline ================
#define TS 4

template <int MODE, int MT>
__global__ void __launch_bounds__(256) tmm3_kernel(
    const float* __restrict__ A, const float* __restrict__ W,
    const float* __restrict__ bias, const float* __restrict__ res,
    float* __restrict__ C, int M, int Nc, int K)
{
    constexpr int AR = MT * 32;
    extern __shared__ float sm[];
    float* Asm = sm;                        // [TS][AR][20]
    float* Bsm = sm + TS * AR * 20;         // [TS][128][20]
    __shared__ float sred[(MODE == 4) ? 8 * 4 * 8 * 4 : 4];
    __shared__ float colsum[(MODE == 4) ? 128 : 4];

    const int tid = threadIdx.x;
    const int lane = tid & 31, warp = tid >> 5;
    const int wm = (warp >> 2) * (MT * 16);
    const int wn = (warp & 3) * 32;
    const int m0 = blockIdx.y * AR, n0 = blockIdx.x * 128;
    const int g = lane >> 2, q4 = lane & 3;

    if (MODE == 4 && tid < 128) colsum[tid] = 0.f;

    float acc[MT][4][4];
#pragma unroll
    for (int i = 0; i < MT; i++)
#pragma unroll
        for (int j = 0; j < 4; j++)
#pragma unroll
            for (int c = 0; c < 4; c++) acc[i][j][c] = 0.f;

    const unsigned sAu = smem_u32(Asm);
    const unsigned sBu = smem_u32(Bsm);

    const int crow = tid >> 1, cko = (tid & 1) * 8;
    const int arow2 = tid >> 2, ako2 = (tid & 3) * 4;

    auto issue = [&](int s, int k0) {
        if (MT == 4) {
            unsigned d = sAu + (unsigned)(((s * 128 + crow) * 20 + cko) * 4);
            const float* p = A + (size_t)(m0 + crow) * K + k0 + cko;
            cpa16(d, p); cpa16(d + 16, p + 4);
        } else {
            unsigned d = sAu + (unsigned)(((s * 64 + arow2) * 20 + ako2) * 4);
            cpa16(d, A + (size_t)(m0 + arow2) * K + k0 + ako2);
        }
        unsigned d = sBu + (unsigned)(((s * 128 + crow) * 20 + cko) * 4);
        const float* p = W + (size_t)(n0 + crow) * K + k0 + cko;
        cpa16(d, p); cpa16(d + 16, p + 4);
    };

    issue(0, 0);  cp_commit();
    issue(1, 16); cp_commit();
    issue(2, 32); cp_commit();

    const int L = K / 16;
    int s = 0;
    for (int j = 0; j < L; j++) {
        cp_wait2();
        __syncthreads();
#pragma unroll
        for (int kc = 0; kc < 16; kc += 8) {
            unsigned af[MT][4], bf[4][2];
#pragma unroll
            for (int mt = 0; mt < MT; mt++) {
                const float* ar = &Asm[(s * AR + wm + mt * 16 + g) * 20 + kc + q4];
                af[mt][0] = __float_as_uint(ar[0]);
                af[mt][1] = __float_as_uint(ar[160]);
                af[mt][2] = __float_as_uint(ar[4]);
                af[mt][3] = __float_as_uint(ar[164]);
            }
#pragma unroll
            for (int nt = 0; nt < 4; nt++) {
                const float* br = &Bsm[(s * 128 + wn + nt * 8 + g) * 20 + kc + q4];
                bf[nt][0] = __float_as_uint(br[0]);
                bf[nt][1] = __float_as_uint(br[4]);
            }
#pragma unroll
            for (int mt = 0; mt < MT; mt++)
#pragma unroll
                for (int nt = 0; nt < 4; nt++)
                    mma8(acc[mt][nt], af[mt], bf[nt]);
        }
        if (j + 3 < L) {
            int ws = s + 3; if (ws >= TS) ws -= TS;
            issue(ws, (j + 3) * 16);
        }
        cp_commit();
        s++; if (s == TS) s = 0;
    }

    const int which = m0 >> 12;

    float csA[4], csB[4];
#pragma unroll
    for (int nt = 0; nt < 4; nt++) { csA[nt] = 0.f; csB[nt] = 0.f; }

#pragma unroll
    for (int mt = 0; mt < MT; mt++) {
        const int row0 = m0 + wm + mt * 16 + g;
        float s0 = 0.f, ss0 = 0.f, s1 = 0.f, ss1 = 0.f;
#pragma unroll
        for (int nt = 0; nt < 4; nt++) {
            const int col = n0 + wn + nt * 8 + 2 * q4;
            float v0 = acc[mt][nt][0], v1 = acc[mt][nt][1];
            float v2 = acc[mt][nt][2], v3 = acc[mt][nt][3];
            if (MODE == 2 || MODE == 3) {
                float2 bv = *(const float2*)&bias[col];
                v0 += bv.x; v1 += bv.y; v2 += bv.x; v3 += bv.y;
            }
            if (MODE == 2) {
                v0 = t32f(0.5f * v0 * (1.f + erff(v0 * 0.70710678118654752f)));
                v1 = t32f(0.5f * v1 * (1.f + erff(v1 * 0.70710678118654752f)));
                v2 = t32f(0.5f * v2 * (1.f + erff(v2 * 0.70710678118654752f)));
                v3 = t32f(0.5f * v3 * (1.f + erff(v3 * 0.70710678118654752f)));
            }
            if (MODE == 3) {
                float2 r0 = *(const float2*)(res + (size_t)row0 * Nc + col);
                float2 r1 = *(const float2*)(res + (size_t)(row0 + 8) * Nc + col);
                v0 += r0.x; v1 += r0.y; v2 += r1.x; v3 += r1.y;
            }
            if (MODE == 4) {
                v0 = t32f(v0); v1 = t32f(v1); v2 = t32f(v2); v3 = t32f(v3);
                s0 += v0 + v1; ss0 += v0 * v0 + v1 * v1;
                s1 += v2 + v3; ss1 += v2 * v2 + v3 * v3;
                csA[nt] += v0 + v2;
                csB[nt] += v1 + v3;
            }
            *(float2*)(C + (size_t)row0 * Nc + col)       = make_float2(v0, v1);
            *(float2*)(C + (size_t)(row0 + 8) * Nc + col) = make_float2(v2, v3);
        }
        if (MODE == 4) {
            s0 += __shfl_xor_sync(0xffffffffu, s0, 1);  s0 += __shfl_xor_sync(0xffffffffu, s0, 2);
            ss0 += __shfl_xor_sync(0xffffffffu, ss0, 1); ss0 += __shfl_xor_sync(0xffffffffu, ss0, 2);
            s1 += __shfl_xor_sync(0xffffffffu, s1, 1);  s1 += __shfl_xor_sync(0xffffffffu, s1, 2);
            ss1 += __shfl_xor_sync(0xffffffffu, ss1, 1); ss1 += __shfl_xor_sync(0xffffffffu, ss1, 2);
            if (q4 == 0) {
                float* sp = &sred[((warp * MT + mt) * 8 + g) * 4];
                sp[0] = s0; sp[1] = ss0; sp[2] = s1; sp[3] = ss1;
            }
        }
    }

    if (MODE == 4) {
        if (which < 2) {
#pragma unroll
            for (int nt = 0; nt < 4; nt++) {
                csA[nt] += __shfl_xor_sync(0xffffffffu, csA[nt], 4);
                csA[nt] += __shfl_xor_sync(0xffffffffu, csA[nt], 8);
                csA[nt] += __shfl_xor_sync(0xffffffffu, csA[nt], 16);
                csB[nt] += __shfl_xor_sync(0xffffffffu, csB[nt], 4);
                csB[nt] += __shfl_xor_sync(0xffffffffu, csB[nt], 8);
                csB[nt] += __shfl_xor_sync(0xffffffffu, csB[nt], 16);
                if (g == 0) {
                    atomicAdd(&colsum[wn + nt * 8 + 2 * q4],     csA[nt]);
                    atomicAdd(&colsum[wn + nt * 8 + 2 * q4 + 1], csB[nt]);
                }
            }
        }
        __syncthreads();
        if (which < 2) {
            if (tid < 128) atomicAdd(&g_hg[which * 512 + n0 + tid], colsum[tid]);
            const int p   = tid >> 6;
            const int mt2 = (tid >> 4) & 3;
            const int g2  = (tid >> 1) & 7;
            const int rr  = tid & 1;
            const int w0 = 2 * p;
            const float* e0 = &sred[((w0 * MT + mt2) * 8 + g2) * 4];
            const float* e1 = &sred[(((w0 + 1) * MT + mt2) * 8 + g2) * 4];
            float sA  = e0[2 * rr]     + e1[2 * rr];
            float ssA = e0[2 * rr + 1] + e1[2 * rr + 1];
            int row = m0 + (p >> 1) * 64 + mt2 * 16 + g2 + rr * 8;
            int lr2 = row & (ROWS - 1);
            int b3 = lr2 >> 10, n3 = lr2 & 1023;
            int head = (n0 >> 6) + (p & 1);
            int idx = (head * 4 + b3) * 1024 + n3;
            float mean = sA * (1.f / 64.f);
            float var  = (ssA - sA * sA * (1.f / 64.f)) * (1.f / 63.f);
            float inv  = rsqrtf(ssA);
            if (which == 0) { g_qinv[idx] = inv; g_qmean[idx] = mean; g_qvar[idx] = var; }
            else            { g_kinv[idx] = inv; g_kmean[idx] = mean; g_kvar[idx] = var; }
        }
    }
}

// ================ mbuild + folded gating MLP ================
// grid (KSPLIT, HB+1): hb<HB blocks do Mcat MMA; block (0,HB) runs the MLP.
// shared pool (36 KB): mbuild uses As=pool[0..4351], Bs=pool[4352..6655];
// the MLP block uses W1s=pool[0..8191], hgs=pool[8192..9215].
__global__ void __launch_bounds__(256) mbuild_kernel(
    const float* __restrict__ W1, const float* __restrict__ b1,
    const float* __restrict__ gg, const float* __restrict__ gb,
    const float* __restrict__ W2, const float* __restrict__ b2)
{
    __shared__ float pool[9216];
    const int tid = threadIdx.x, lane = tid & 31, warp = tid >> 5;
    const int ks = blockIdx.x, hb = blockIdx.y;

    if (hb == HB) {
        // ---------------- gating MLP block ----------------
        if (ks != 0) return;
        float* W1s = pool;
        float* hgs = pool + 8192;
#pragma unroll
        for (int c = 0; c < 8; c++)
            *(float4*)&W1s[(c * 256 + tid) * 4] = *(const float4*)&W1[(c * 256 + tid) * 4];
        *(float4*)&hgs[tid * 4] = *(const float4*)&g_hg[tid * 4];
        __syncthreads();

        const int h = tid >> 5;
        const float invR = 1.f / (float)ROWS;
        float h1[2];
#pragma unroll
        for (int t = 0; t < 2; t++) {
            int j = lane + t * 32;
            const float* wrow = &W1s[j * 128];
            float dot = 0.f;
#pragma unroll 8
            for (int i = 0; i < 64; i++) dot += hgs[h * 64 + i] * wrow[i];
#pragma unroll 8
            for (int i = 0; i < 64; i++) dot += hgs[512 + h * 64 + i] * wrow[64 + i];
            h1[t] = b1[j] + dot * invR;
        }
        float s = h1[0] + h1[1], ss = h1[0] * h1[0] + h1[1] * h1[1];
#pragma unroll
        for (int off = 16; off; off >>= 1) {
            s  += __shfl_xor_sync(0xffffffffu, s, off);
            ss += __shfl_xor_sync(0xffffffffu, ss, off);
        }
        float mean = s * (1.f / 64.f);
        float var  = ss * (1.f / 64.f) - mean * mean;
        float inv  = rsqrtf(var + EPS);
        float hh[2];
#pragma unroll
        for (int t = 0; t < 2; t++) {
            int j = lane + t * 32;
            float vv = (h1[t] - mean) * inv * gg[j] + gb[j];
            hh[t] = fmaxf(vv, 0.f);
        }
        float lg[3];
#pragma unroll
        for (int c = 0; c < 3; c++) {
            float acc = hh[0] * W2[c * 64 + lane] + hh[1] * W2[c * 64 + lane + 32];
#pragma unroll
            for (int off = 16; off; off >>= 1) acc += __shfl_xor_sync(0xffffffffu, acc, off);
            lg[c] = acc + b2[c];
        }
        if (lane == 0) {
            float m = fmaxf(lg[0], fmaxf(lg[1], lg[2]));
            float e0 = expf(lg[0] - m), e1 = expf(lg[1] - m), e2 = expf(lg[2] - m);
            float inv_s = 1.f / (e0 + e1 + e2);
            g_w3[h * 3 + 0] = e0 * inv_s;
            g_w3[h * 3 + 1] = e1 * inv_s;
            g_w3[h * 3 + 2] = e2 * inv_s;
        }
        return;
    }

    // ---------------- Mcat MMA blocks ----------------
#define ASM(b, r) (&pool[((b) * 16 + (r)) * 136])
#define BSM(b, r) (&pool[4352 + ((b) * 16 + (r)) * 72])
    const int h = hb >> 2, b = hb & 3;
    const int base = hb * Nn_;
    const int g = lane >> 2, q4 = lane & 3;
    const int m0 = ks * (Nn_ / KSPLIT);

    const float* fk = g_f + (size_t)ROWS * DIM;
    const float* fv = g_f + 2 * (size_t)ROWS * DIM;

    float acc[9][4];
#pragma unroll
    for (int j = 0; j < 9; j++)
#pragma unroll
        for (int c = 0; c < 4; c++) acc[j][c] = 0.f;

    const int srow = tid >> 4;
    const int dc = (tid & 15) * 4;

    {
        int m = m0 + srow;
        float ki = g_kinv[base + m];
        float4 vv = *(const float4*)(fv + (size_t)(b*Nn_ + m)*DIM + h*DH + dc);
        float4 kk = *(const float4*)(fk + (size_t)(b*Nn_ + m)*DIM + h*DH + dc);
        float* ar = ASM(0, srow) + 2 * dc;
        ar[0] = vv.x; ar[1] = t32f(ki*vv.x);
        ar[2] = vv.y; ar[3] = t32f(ki*vv.y);
        ar[4] = vv.z; ar[5] = t32f(ki*vv.z);
        ar[6] = vv.w; ar[7] = t32f(ki*vv.w);
        *(float4*)(BSM(0, srow) + dc) = kk;
        if (tid < 128) {
            int r = tid >> 3, sx = tid & 7;
            int mm = m0 + r;
            float v = 0.f;
            if (sx == 0) v = t32f(g_kvar [base + mm]);
            else if (sx == 1) v = t32f(g_kmean[base + mm]);
            BSM(0, r)[64 + sx] = v;
        }
    }

    int buf = 0;
    const int KC = Nn_ / KSPLIT;
    for (int k0 = 16; k0 <= KC; k0 += 16) {
        __syncthreads();
        const bool more = (k0 < KC);
        float4 vv, kk; float ki = 0.f, xv = 0.f;
        if (more) {
            int m = m0 + k0 + srow;
            vv = *(const float4*)(fv + (size_t)(b*Nn_ + m)*DIM + h*DH + dc);
            kk = *(const float4*)(fk + (size_t)(b*Nn_ + m)*DIM + h*DH + dc);
            ki = g_kinv[base + m];
            if (tid < 128) {
                int r = tid >> 3, sx = tid & 7;
                int mm = m0 + k0 + r;
                if (sx == 0) xv = t32f(g_kvar [base + mm]);
                else if (sx == 1) xv = t32f(g_kmean[base + mm]);
            }
        }
#pragma unroll
        for (int ks8 = 0; ks8 < 16; ks8 += 8) {
            unsigned af[4];
            const int mr = warp * 16 + g;
            af[0] = __float_as_uint(ASM(buf, ks8 + q4)[mr]);
            af[1] = __float_as_uint(ASM(buf, ks8 + q4)[mr + 8]);
            af[2] = __float_as_uint(ASM(buf, ks8 + 4 + q4)[mr]);
            af[3] = __float_as_uint(ASM(buf, ks8 + 4 + q4)[mr + 8]);
#pragma unroll
            for (int nt = 0; nt < 9; nt++) {
                unsigned bf[2];
                bf[0] = __float_as_uint(BSM(buf, ks8 + q4)[nt * 8 + g]);
                bf[1] = __float_as_uint(BSM(buf, ks8 + 4 + q4)[nt * 8 + g]);
                mma8(acc[nt], af, bf);
            }
        }
        if (more) {
            int nb = buf ^ 1;
            float* ar = ASM(nb, srow) + 2 * dc;
            ar[0] = vv.x; ar[1] = t32f(ki*vv.x);
            ar[2] = vv.y; ar[3] = t32f(ki*vv.y);
            ar[4] = vv.z; ar[5] = t32f(ki*vv.z);
            ar[6] = vv.w; ar[7] = t32f(ki*vv.w);
            *(float4*)(BSM(nb, srow) + dc) = kk;
            if (tid < 128) {
                int r = tid >> 3, sx = tid & 7;
                BSM(nb, r)[64 + sx] = xv;
            }
        }
        buf ^= 1;
    }

    const int row0 = warp * 16 + g;
#pragma unroll
    for (int nt = 0; nt < 9; nt++) {
        const int col = nt * 8 + 2 * q4;
        atomicAdd(&g_Mr[hb][row0][col],         acc[nt][0]);
        atomicAdd(&g_Mr[hb][row0][col + 1],     acc[nt][1]);
        atomicAdd(&g_Mr[hb][row0 + 8][col],     acc[nt][2]);
        atomicAdd(&g_Mr[hb][row0 + 8][col + 1], acc[nt][3]);
    }
#undef ASM
#undef BSM
}

// ================ pgemm: O = combine(fq @ Mcat^T) per hb; output tf32 ========
__global__ void __launch_bounds__(256) pgemm_kernel()
{
    __shared__ float As[2][16][136];
    __shared__ float Bs[2][16][136];
    const int tid = threadIdx.x;
    const int lane = tid & 31, warp = tid >> 5;
    const int wm = (warp >> 2) * 64, wn = (warp & 3) * 32;
    const int hb = blockIdx.y, h = hb >> 2, b = hb & 3;
    const int q0 = blockIdx.x * 128;
    const int base = hb * Nn_;
    const int g = lane >> 2, q4 = lane & 3;

    const float* fq = g_f;

    float acc[4][4][4];
#pragma unroll
    for (int i = 0; i < 4; i++)
#pragma unroll
        for (int j = 0; j < 4; j++)
#pragma unroll
            for (int c = 0; c < 4; c++) acc[i][j][c] = 0.f;

    const int srow = tid >> 1, skc = (tid & 1) * 8;
    const float* Apt = fq + (size_t)(b * Nn_ + q0 + srow) * DIM + h * DH + skc;
    const float* Wpt = &g_Mr[hb][srow][skc];

    {
        float4 a0 = *(const float4*)(Apt);
        float4 a1 = *(const float4*)(Apt + 4);
        float4 w0 = *(const float4*)(Wpt);
        float4 w1 = *(const float4*)(Wpt + 4);
        As[0][skc+0][srow] = a0.x; As[0][skc+1][srow] = a0.y;
        As[0][skc+2][srow] = a0.z; As[0][skc+3][srow] = a0.w;
        As[0][skc+4][srow] = a1.x; As[0][skc+5][srow] = a1.y;
        As[0][skc+6][srow] = a1.z; As[0][skc+7][srow] = a1.w;
        Bs[0][skc+0][srow] = t32f(w0.x); Bs[0][skc+1][srow] = t32f(w0.y);
        Bs[0][skc+2][srow] = t32f(w0.z); Bs[0][skc+3][srow] = t32f(w0.w);
        Bs[0][skc+4][srow] = t32f(w1.x); Bs[0][skc+5][srow] = t32f(w1.y);
        Bs[0][skc+6][srow] = t32f(w1.z); Bs[0][skc+7][srow] = t32f(w1.w);
    }

    int buf = 0;
    for (int k0 = 16; k0 <= DH; k0 += 16) {
        __syncthreads();
        const bool more = (k0 < DH);
        float4 a0, a1, w0, w1;
        if (more) {
            a0 = *(const float4*)(Apt + k0);
            a1 = *(const float4*)(Apt + k0 + 4);
            w0 = *(const float4*)(Wpt + k0);
            w1 = *(const float4*)(Wpt + k0 + 4);
        }
#pragma unroll
        for (int ks = 0; ks < 16; ks += 8) {
            unsigned af[4][4], bf[4][2];
#pragma unroll
            for (int mt = 0; mt < 4; mt++) {
                int mr = wm + mt * 16 + g;
                af[mt][0] = __float_as_uint(As[buf][ks + q4][mr]);
                af[mt][1] = __float_as_uint(As[buf][ks + q4][mr + 8]);
                af[mt][2] = __float_as_uint(As[buf][ks + 4 + q4][mr]);
                af[mt][3] = __float_as_uint(As[buf][ks + 4 + q4][mr + 8]);
            }
#pragma unroll
            for (int nt = 0; nt < 4; nt++) {
                int nc = wn + nt * 8 + g;
                bf[nt][0] = __float_as_uint(Bs[buf][ks + q4][nc]);
                bf[nt][1] = __float_as_uint(Bs[buf][ks + 4 + q4][nc]);
            }
#pragma unroll
            for (int mt = 0; mt < 4; mt++)
#pragma unroll
                for (int nt = 0; nt < 4; nt++)
                    mma8(acc[mt][nt], af[mt], bf[nt]);
        }
        if (more) {
            int nb = buf ^ 1;
            As[nb][skc+0][srow] = a0.x; As[nb][skc+1][srow] = a0.y;
            As[nb][skc+2][srow] = a0.z; As[nb][skc+3][srow] = a0.w;
            As[nb][skc+4][srow] = a1.x; As[nb][skc+5][srow] = a1.y;
            As[nb][skc+6][srow] = a1.z; As[nb][skc+7][srow] = a1.w;
            Bs[nb][skc+0][srow] = t32f(w0.x); Bs[nb][skc+1][srow] = t32f(w0.y);
            Bs[nb][skc+2][srow] = t32f(w0.z); Bs[nb][skc+3][srow] = t32f(w0.w);
            Bs[nb][skc+4][srow] = t32f(w1.x); Bs[nb][skc+5][srow] = t32f(w1.y);
            Bs[nb][skc+6][srow] = t32f(w1.z); Bs[nb][skc+7][srow] = t32f(w1.w);
        }
        buf ^= 1;
    }

    const float cw = g_w3[h * 3 + 0], covw = g_w3[h * 3 + 1], vw = g_w3[h * 3 + 2];
#pragma unroll
    for (int mt = 0; mt < 4; mt++) {
        const int row0 = q0 + wm + mt * 16 + g;
        const float qi0 = g_qinv[base + row0],     qm0 = g_qmean[base + row0],     qv0 = g_qvar[base + row0];
        const float qi1 = g_qinv[base + row0 + 8], qm1 = g_qmean[base + row0 + 8], qv1 = g_qvar[base + row0 + 8];
#pragma unroll
        for (int nt = 0; nt < 4; nt++) {
            const int col = wn + nt * 8 + 2 * q4;
            const int d = col >> 1;
            const float Skv = g_Mr[hb][col][64];
            const float Skm = g_Mr[hb][col][65];
            float o0 = cw * qi0 * acc[mt][nt][1] + (covw / DH) * acc[mt][nt][0]
                     + (vw / DH) * qv0 * Skv - covw * qm0 * Skm;
            float o1 = cw * qi1 * acc[mt][nt][3] + (covw / DH) * acc[mt][nt][2]
                     + (vw / DH) * qv1 * Skv - covw * qm1 * Skm;
            g_ao[(size_t)(b * Nn_ + row0) * DIM + h * DH + d]     = t32f(o0);
            g_ao[(size_t)(b * Nn_ + row0 + 8) * DIM + h * DH + d] = t32f(o1);
        }
    }
}

// ---------------- launch ----------------
extern "C" void kernel_launch(void* const* d_in, const int* in_sizes, int n_in,
                              void* d_out, int out_size)
{
    const float* q    = (const float*)d_in[0];
    const float* k    = (const float*)d_in[1];
    const float* v    = (const float*)d_in[2];
    const float* Win  = (const float*)d_in[3];
    const float* Wout = (const float*)d_in[4];
    const float* bout = (const float*)d_in[5];
    const float* g1   = (const float*)d_in[6];
    const float* b1n  = (const float*)d_in[7];
    const float* g2   = (const float*)d_in[8];
    const float* b2n  = (const float*)d_in[9];
    const float* Wup  = (const float*)d_in[10];
    const float* bup  = (const float*)d_in[11];
    const float* Wdn  = (const float*)d_in[12];
    const float* bdn  = (const float*)d_in[13];
    const float* wpW1 = (const float*)d_in[14];
    const float* wpb1 = (const float*)d_in[15];
    const float* wpg  = (const float*)d_in[16];
    const float* wpb  = (const float*)d_in[17];
    const float* wpW2 = (const float*)d_in[18];
    const float* wpb2 = (const float*)d_in[19];
    float* out = (float*)d_out;

    float* xn;  cudaGetSymbolAddress((void**)&xn,  g_xn);
    float* f;   cudaGetSymbolAddress((void**)&f,   g_f);
    float* ao;  cudaGetSymbolAddress((void**)&ao,  g_ao);
    float* q2;  cudaGetSymbolAddress((void**)&q2,  g_q2);
    float* xn2; cudaGetSymbolAddress((void**)&xn2, g_xn2);
    float* u;   cudaGetSymbolAddress((void**)&u,   g_u);
    float* wr;  cudaGetSymbolAddress((void**)&wr,  g_wr);

    const int smem4 = TS * (128 + 128) * 20 * 4;   // 81920 B (MT=4)
    const int smem2 = TS * (64 + 128) * 20 * 4;    // 61440 B (MT=2)
    cudaFuncSetAttribute(tmm3_kernel<4,4>, cudaFuncAttributeMaxDynamicSharedMemorySize, smem4);
    cudaFuncSetAttribute(tmm3_kernel<2,4>, cudaFuncAttributeMaxDynamicSharedMemorySize, smem4);
    cudaFuncSetAttribute(tmm3_kernel<3,2>, cudaFuncAttributeMaxDynamicSharedMemorySize, smem2);

    // 1. fused LN of q,k,v (tf32 out; also zeroes g_hg/g_Mr + rounds weights)
    ln3_kernel<<<3 * ROWS / 8, 256>>>(q, k, v, g1, b1n, xn, Win, Wout, Wup, Wdn);

    // 2. fused projection + per-row stats + per-head column sums
    tmm3_kernel<4, 4><<<dim3(DIM / 128, 3 * ROWS / 128), 256, smem4>>>(
        xn, wr + WR_WIN, nullptr, nullptr, f, 3 * ROWS, DIM, DIM);

    // 3. attention: Mcat build (+ folded gating MLP block) -> pgemm
    mbuild_kernel<<<dim3(KSPLIT, HB + 1), 256>>>(wpW1, wpb1, wpg, wpb, wpW2, wpb2);
    pgemm_kernel<<<dim3(Nn_ / 128, HB), 256>>>();

    // 4. attn out proj + residual -> q2
    tmm3_kernel<3, 2><<<dim3(DIM / 128, ROWS / 64), 256, smem2>>>(
        ao, wr + WR_WOUT, bout, q, q2, ROWS, DIM, DIM);

    // 5. LN2 (tf32 out)
    ln_kernel<<<ROWS / 8, 256>>>(q2, g2, b2n, xn2);

    // 6. MLP up + gelu (tf32 out)
    tmm3_kernel<2, 4><<<dim3(MLPD / 128, ROWS / 128), 256, smem4>>>(
        xn2, wr + WR_WUP, bup, nullptr, u, ROWS, MLPD, DIM);

    // 7. MLP down + residual -> out
    tmm3_kernel<3, 2><<<dim3(DIM / 128, ROWS / 64), 256, smem2>>>(
        u, wr + WR_WDN, bdn, q2, out, ROWS, DIM, MLPD);
}

// round 14
// speedup vs baseline: 1.4254x; 1.0009x over previous
#include <cuda_runtime.h>
#include <cuda_bf16.h>
#include <math.h>
#include <stdint.h>

// ---------------- problem constants ----------------
#define Bq   4
#define Nn_  1024
#define DIM  512
#define Hh   8
#define DH   64
#define MLPD 2048
#define ROWS (Bq * Nn_)            // 4096 token rows
#define HB   (Hh * Bq)             // 32 attention batches
#define EPS  1e-5f
#define MST  80
#define KSPLIT 8

// ---------------- tf32 mma helpers ----------------
__device__ __forceinline__ float t32f(float x){
    unsigned r; asm("cvt.rna.tf32.f32 %0,%1;" : "=r"(r) : "f"(x));
    return __uint_as_float(r);
}
__device__ __forceinline__ void mma8(float* c, const unsigned* a, const unsigned* b){
    asm("mma.sync.aligned.m16n8k8.row.col.f32.tf32.tf32.f32 "
        "{%0,%1,%2,%3},{%4,%5,%6,%7},{%8,%9},{%0,%1,%2,%3};"
        : "+f"(c[0]), "+f"(c[1]), "+f"(c[2]), "+f"(c[3])
        : "r"(a[0]), "r"(a[1]), "r"(a[2]), "r"(a[3]), "r"(b[0]), "r"(b[1]));
}
__device__ __forceinline__ unsigned smem_u32(const void* p){
    return (unsigned)__cvta_generic_to_shared((void*)p);
}
__device__ __forceinline__ void cpa16(unsigned dst, const float* src){
    asm volatile("cp.async.cg.shared.global [%0], [%1], 16;" :: "r"(dst), "l"(src) : "memory");
}
__device__ __forceinline__ void cp_commit(){
    asm volatile("cp.async.commit_group;" ::: "memory");
}
__device__ __forceinline__ void cp_wait2(){
    asm volatile("cp.async.wait_group 2;" ::: "memory");
}

// ---------------- device scratch (no allocs allowed) ----------------
__device__ float g_xn [3 * ROWS * DIM];
__device__ float g_f  [3 * ROWS * DIM];
__device__ float g_ao [ROWS * DIM];
__device__ float g_q2 [ROWS * DIM];
__device__ float g_xn2[ROWS * DIM];
__device__ float g_u  [ROWS * MLPD];
__device__ float g_wr [2621440];                 // tf32-rounded weights
__device__ float g_Mr [HB][128][MST];            // Mcat (atomic-accumulated)
__device__ float g_qinv [HB * Nn_];
__device__ float g_qmean[HB * Nn_];
__device__ float g_qvar [HB * Nn_];
__device__ float g_kinv [HB * Nn_];
__device__ float g_kmean[HB * Nn_];
__device__ float g_kvar [HB * Nn_];
__device__ float g_hg [2 * Hh * DH];
__device__ float g_w3 [Hh * 3];

// rounded-weight offsets (floats)
#define WR_WIN  0
#define WR_WOUT 262144
#define WR_WUP  524288
#define WR_WDN  1572864

// ---------------- LN of q,k,v + zero g_hg/g_Mr + weight pre-round ----------
__global__ void ln3_kernel(const float* __restrict__ q, const float* __restrict__ k,
                           const float* __restrict__ v, const float* __restrict__ g,
                           const float* __restrict__ bb, float* __restrict__ y,
                           const float* __restrict__ Win, const float* __restrict__ Wout,
                           const float* __restrict__ Wup, const float* __restrict__ Wdn)
{
    const int tid = threadIdx.x, lane = tid & 31, wid = tid >> 5;
    if (blockIdx.x == 0) {
        *(float4*)&g_hg[tid * 4] = make_float4(0.f, 0.f, 0.f, 0.f);
    } else if (blockIdx.x <= 320) {
        float* mr = &g_Mr[0][0][0];
        *(float4*)&mr[(blockIdx.x - 1) * 1024 + tid * 4] = make_float4(0.f, 0.f, 0.f, 0.f);
    }
    {
        int i = blockIdx.x * 256 + tid;
#pragma unroll
        for (int rep = 0; rep < 2; rep++) {
            if (i < 655360) {
                const float* src; int dst;
                if (i < 65536)       { src = Win  + (size_t)i * 4;            dst = WR_WIN  + i * 4; }
                else if (i < 131072) { src = Wout + (size_t)(i - 65536) * 4;  dst = WR_WOUT + (i - 65536) * 4; }
                else if (i < 393216) { src = Wup  + (size_t)(i - 131072) * 4; dst = WR_WUP  + (i - 131072) * 4; }
                else                 { src = Wdn  + (size_t)(i - 393216) * 4; dst = WR_WDN  + (i - 393216) * 4; }
                float4 w = *(const float4*)src;
                *(float4*)&g_wr[dst] = make_float4(t32f(w.x), t32f(w.y), t32f(w.z), t32f(w.w));
            }
            i += 393216;
        }
    }
    const int row = blockIdx.x * 8 + wid;
    const int which = row >> 12;
    const float* x = (which == 0) ? q : (which == 1) ? k : v;
    const float* xr = x + (size_t)(row & (ROWS - 1)) * DIM;
    float4 a[4];
    float s = 0.f, ss = 0.f;
#pragma unroll
    for (int c = 0; c < 4; c++) {
        a[c] = *(const float4*)(xr + c * 128 + lane * 4);
        s  += a[c].x + a[c].y + a[c].z + a[c].w;
        ss += a[c].x * a[c].x + a[c].y * a[c].y + a[c].z * a[c].z + a[c].w * a[c].w;
    }
#pragma unroll
    for (int off = 16; off; off >>= 1) {
        s  += __shfl_xor_sync(0xffffffffu, s, off);
        ss += __shfl_xor_sync(0xffffffffu, ss, off);
    }
    const float mean = s * (1.f / DIM);
    const float var  = ss * (1.f / DIM) - mean * mean;
    const float inv  = rsqrtf(var + EPS);
    float* yr = y + (size_t)row * DIM;
#pragma unroll
    for (int c = 0; c < 4; c++) {
        float4 gv = *(const float4*)(g  + c * 128 + lane * 4);
        float4 bv = *(const float4*)(bb + c * 128 + lane * 4);
        float4 o;
        o.x = t32f((a[c].x - mean) * inv * gv.x + bv.x);
        o.y = t32f((a[c].y - mean) * inv * gv.y + bv.y);
        o.z = t32f((a[c].z - mean) * inv * gv.z + bv.z);
        o.w = t32f((a[c].w - mean) * inv * gv.w + bv.w);
        *(float4*)(yr + c * 128 + lane * 4) = o;
    }
}

// ---------------- warp-per-row LN (single tensor, LN2); tf32 output ----------
__global__ void ln_kernel(const float* __restrict__ x, const float* __restrict__ g,
                          const float* __restrict__ bb, float* __restrict__ y)
{
    const int tid = threadIdx.x, lane = tid & 31, wid = tid >> 5;
    const int row = blockIdx.x * 8 + wid;
    const float* xr = x + (size_t)row * DIM;
    float4 a[4];
    float s = 0.f, ss = 0.f;
#pragma unroll
    for (int c = 0; c < 4; c++) {
        a[c] = *(const float4*)(xr + c * 128 + lane * 4);
        s  += a[c].x + a[c].y + a[c].z + a[c].w;
        ss += a[c].x * a[c].x + a[c].y * a[c].y + a[c].z * a[c].z + a[c].w * a[c].w;
    }
#pragma unroll
    for (int off = 16; off; off >>= 1) {
        s  += __shfl_xor_sync(0xffffffffu, s, off);
        ss += __shfl_xor_sync(0xffffffffu, ss, off);
    }
    const float mean = s * (1.f / DIM);
    const float var  = ss * (1.f / DIM) - mean * mean;
    const float inv  = rsqrtf(var + EPS);
    float* yr = y + (size_t)row * DIM;
#pragma unroll
    for (int c = 0; c < 4; c++) {
        float4 gv = *(const float4*)(g  + c * 128 + lane * 4);
        float4 bv = *(const float4*)(bb + c * 128 + lane * 4);
        float4 o;
        o.x = t32f((a[c].x - mean) * inv * gv.x + bv.x);
        o.y = t32f((a[c].y - mean) * inv * gv.y + bv.y);
        o.z = t32f((a[c].z - mean) * inv * gv.z + bv.z);
        o.w = t32f((a[c].w - mean) * inv * gv.w + bv.w);
        *(float4*)(yr + c * 128 + lane * 4) = o;
    }
}

// ================ tf32 mma GEMM, 4-stage cp.async pipeline ================
#define TS 4

template <int MODE, int MT>
__global__ void __launch_bounds__(256) tmm3_kernel(
    const float* __restrict__ A, const float* __restrict__ W,
    const float* __restrict__ bias, const float* __restrict__ res,
    float* __restrict__ C, int M, int Nc, int K)
{
    constexpr int AR = MT * 32;
    extern __shared__ float sm[];
    float* Asm = sm;                        // [TS][AR][20]
    float* Bsm = sm + TS * AR * 20;         // [TS][128][20]
    __shared__ float sred[(MODE == 4) ? 8 * 4 * 8 * 4 : 4];
    __shared__ float colsum[(MODE == 4) ? 128 : 4];

    const int tid = threadIdx.x;
    const int lane = tid & 31, warp = tid >> 5;
    const int wm = (warp >> 2) * (MT * 16);
    const int wn = (warp & 3) * 32;
    const int m0 = blockIdx.y * AR, n0 = blockIdx.x * 128;
    const int g = lane >> 2, q4 = lane & 3;

    if (MODE == 4 && tid < 128) colsum[tid] = 0.f;

    float acc[MT][4][4];
#pragma unroll
    for (int i = 0; i < MT; i++)
#pragma unroll
        for (int j = 0; j < 4; j++)
#pragma unroll
            for (int c = 0; c < 4; c++) acc[i][j][c] = 0.f;

    const unsigned sAu = smem_u32(Asm);
    const unsigned sBu = smem_u32(Bsm);

    const int crow = tid >> 1, cko = (tid & 1) * 8;
    const int arow2 = tid >> 2, ako2 = (tid & 3) * 4;

    auto issue = [&](int s, int k0) {
        if (MT == 4) {
            unsigned d = sAu + (unsigned)(((s * 128 + crow) * 20 + cko) * 4);
            const float* p = A + (size_t)(m0 + crow) * K + k0 + cko;
            cpa16(d, p); cpa16(d + 16, p + 4);
        } else {
            unsigned d = sAu + (unsigned)(((s * 64 + arow2) * 20 + ako2) * 4);
            cpa16(d, A + (size_t)(m0 + arow2) * K + k0 + ako2);
        }
        unsigned d = sBu + (unsigned)(((s * 128 + crow) * 20 + cko) * 4);
        const float* p = W + (size_t)(n0 + crow) * K + k0 + cko;
        cpa16(d, p); cpa16(d + 16, p + 4);
    };

    issue(0, 0);  cp_commit();
    issue(1, 16); cp_commit();
    issue(2, 32); cp_commit();

    const int L = K / 16;
    int s = 0;
    for (int j = 0; j < L; j++) {
        cp_wait2();
        __syncthreads();
#pragma unroll
        for (int kc = 0; kc < 16; kc += 8) {
            unsigned af[MT][4], bf[4][2];
#pragma unroll
            for (int mt = 0; mt < MT; mt++) {
                const float* ar = &Asm[(s * AR + wm + mt * 16 + g) * 20 + kc + q4];
                af[mt][0] = __float_as_uint(ar[0]);
                af[mt][1] = __float_as_uint(ar[160]);
                af[mt][2] = __float_as_uint(ar[4]);
                af[mt][3] = __float_as_uint(ar[164]);
            }
#pragma unroll
            for (int nt = 0; nt < 4; nt++) {
                const float* br = &Bsm[(s * 128 + wn + nt * 8 + g) * 20 + kc + q4];
                bf[nt][0] = __float_as_uint(br[0]);
                bf[nt][1] = __float_as_uint(br[4]);
            }
#pragma unroll
            for (int mt = 0; mt < MT; mt++)
#pragma unroll
                for (int nt = 0; nt < 4; nt++)
                    mma8(acc[mt][nt], af[mt], bf[nt]);
        }
        if (j + 3 < L) {
            int ws = s + 3; if (ws >= TS) ws -= TS;
            issue(ws, (j + 3) * 16);
        }
        cp_commit();
        s++; if (s == TS) s = 0;
    }

    const int which = m0 >> 12;

    float csA[4], csB[4];
#pragma unroll
    for (int nt = 0; nt < 4; nt++) { csA[nt] = 0.f; csB[nt] = 0.f; }

#pragma unroll
    for (int mt = 0; mt < MT; mt++) {
        const int row0 = m0 + wm + mt * 16 + g;
        float s0 = 0.f, ss0 = 0.f, s1 = 0.f, ss1 = 0.f;
#pragma unroll
        for (int nt = 0; nt < 4; nt++) {
            const int col = n0 + wn + nt * 8 + 2 * q4;
            float v0 = acc[mt][nt][0], v1 = acc[mt][nt][1];
            float v2 = acc[mt][nt][2], v3 = acc[mt][nt][3];
            if (MODE == 2 || MODE == 3) {
                float2 bv = *(const float2*)&bias[col];
                v0 += bv.x; v1 += bv.y; v2 += bv.x; v3 += bv.y;
            }
            if (MODE == 2) {
                v0 = t32f(0.5f * v0 * (1.f + erff(v0 * 0.70710678118654752f)));
                v1 = t32f(0.5f * v1 * (1.f + erff(v1 * 0.70710678118654752f)));
                v2 = t32f(0.5f * v2 * (1.f + erff(v2 * 0.70710678118654752f)));
                v3 = t32f(0.5f * v3 * (1.f + erff(v3 * 0.70710678118654752f)));
            }
            if (MODE == 3) {
                float2 r0 = *(const float2*)(res + (size_t)row0 * Nc + col);
                float2 r1 = *(const float2*)(res + (size_t)(row0 + 8) * Nc + col);
                v0 += r0.x; v1 += r0.y; v2 += r1.x; v3 += r1.y;
            }
            if (MODE == 4) {
                v0 = t32f(v0); v1 = t32f(v1); v2 = t32f(v2); v3 = t32f(v3);
                s0 += v0 + v1; ss0 += v0 * v0 + v1 * v1;
                s1 += v2 + v3; ss1 += v2 * v2 + v3 * v3;
                csA[nt] += v0 + v2;
                csB[nt] += v1 + v3;
            }
            *(float2*)(C + (size_t)row0 * Nc + col)       = make_float2(v0, v1);
            *(float2*)(C + (size_t)(row0 + 8) * Nc + col) = make_float2(v2, v3);
        }
        if (MODE == 4) {
            s0 += __shfl_xor_sync(0xffffffffu, s0, 1);  s0 += __shfl_xor_sync(0xffffffffu, s0, 2);
            ss0 += __shfl_xor_sync(0xffffffffu, ss0, 1); ss0 += __shfl_xor_sync(0xffffffffu, ss0, 2);
            s1 += __shfl_xor_sync(0xffffffffu, s1, 1);  s1 += __shfl_xor_sync(0xffffffffu, s1, 2);
            ss1 += __shfl_xor_sync(0xffffffffu, ss1, 1); ss1 += __shfl_xor_sync(0xffffffffu, ss1, 2);
            if (q4 == 0) {
                float* sp = &sred[((warp * MT + mt) * 8 + g) * 4];
                sp[0] = s0; sp[1] = ss0; sp[2] = s1; sp[3] = ss1;
            }
        }
    }

    if (MODE == 4) {
        if (which < 2) {
#pragma unroll
            for (int nt = 0; nt < 4; nt++) {
                csA[nt] += __shfl_xor_sync(0xffffffffu, csA[nt], 4);
                csA[nt] += __shfl_xor_sync(0xffffffffu, csA[nt], 8);
                csA[nt] += __shfl_xor_sync(0xffffffffu, csA[nt], 16);
                csB[nt] += __shfl_xor_sync(0xffffffffu, csB[nt], 4);
                csB[nt] += __shfl_xor_sync(0xffffffffu, csB[nt], 8);
                csB[nt] += __shfl_xor_sync(0xffffffffu, csB[nt], 16);
                if (g == 0) {
                    atomicAdd(&colsum[wn + nt * 8 + 2 * q4],     csA[nt]);
                    atomicAdd(&colsum[wn + nt * 8 + 2 * q4 + 1], csB[nt]);
                }
            }
        }
        __syncthreads();
        if (which < 2) {
            if (tid < 128) atomicAdd(&g_hg[which * 512 + n0 + tid], colsum[tid]);
            const int p   = tid >> 6;
            const int mt2 = (tid >> 4) & 3;
            const int g2  = (tid >> 1) & 7;
            const int rr  = tid & 1;
            const int w0 = 2 * p;
            const float* e0 = &sred[((w0 * MT + mt2) * 8 + g2) * 4];
            const float* e1 = &sred[(((w0 + 1) * MT + mt2) * 8 + g2) * 4];
            float sA  = e0[2 * rr]     + e1[2 * rr];
            float ssA = e0[2 * rr + 1] + e1[2 * rr + 1];
            int row = m0 + (p >> 1) * 64 + mt2 * 16 + g2 + rr * 8;
            int lr2 = row & (ROWS - 1);
            int b3 = lr2 >> 10, n3 = lr2 & 1023;
            int head = (n0 >> 6) + (p & 1);
            int idx = (head * 4 + b3) * 1024 + n3;
            float mean = sA * (1.f / 64.f);
            float var  = (ssA - sA * sA * (1.f / 64.f)) * (1.f / 63.f);
            float inv  = rsqrtf(ssA);
            if (which == 0) { g_qinv[idx] = inv; g_qmean[idx] = mean; g_qvar[idx] = var; }
            else            { g_kinv[idx] = inv; g_kmean[idx] = mean; g_kvar[idx] = var; }
        }
    }
}

// ================ mbuild + folded gating MLP ================
// grid (KSPLIT, HB+1). 3-stage smem + distance-2 register prefetch.
// pool: mbuild As = pool[0..6527] (3x16x136), Bs = pool[6528..9983] (3x16x72);
// MLP block: W1s = pool[0..8191], hgs = pool[8192..9215].
__global__ void __launch_bounds__(256) mbuild_kernel(
    const float* __restrict__ W1, const float* __restrict__ b1,
    const float* __restrict__ gg, const float* __restrict__ gb,
    const float* __restrict__ W2, const float* __restrict__ b2)
{
    __shared__ float pool[9984];
    const int tid = threadIdx.x, lane = tid & 31, warp = tid >> 5;
    const int ks = blockIdx.x, hb = blockIdx.y;

    if (hb == HB) {
        if (ks != 0) return;
        float* W1s = pool;
        float* hgs = pool + 8192;
#pragma unroll
        for (int c = 0; c < 8; c++)
            *(float4*)&W1s[(c * 256 + tid) * 4] = *(const float4*)&W1[(c * 256 + tid) * 4];
        *(float4*)&hgs[tid * 4] = *(const float4*)&g_hg[tid * 4];
        __syncthreads();

        const int h = tid >> 5;
        const float invR = 1.f / (float)ROWS;
        float h1[2];
#pragma unroll
        for (int t = 0; t < 2; t++) {
            int j = lane + t * 32;
            const float* wrow = &W1s[j * 128];
            float dot = 0.f;
#pragma unroll 8
            for (int i = 0; i < 64; i++) dot += hgs[h * 64 + i] * wrow[i];
#pragma unroll 8
            for (int i = 0; i < 64; i++) dot += hgs[512 + h * 64 + i] * wrow[64 + i];
            h1[t] = b1[j] + dot * invR;
        }
        float s = h1[0] + h1[1], ss = h1[0] * h1[0] + h1[1] * h1[1];
#pragma unroll
        for (int off = 16; off; off >>= 1) {
            s  += __shfl_xor_sync(0xffffffffu, s, off);
            ss += __shfl_xor_sync(0xffffffffu, ss, off);
        }
        float mean = s * (1.f / 64.f);
        float var  = ss * (1.f / 64.f) - mean * mean;
        float inv  = rsqrtf(var + EPS);
        float hh[2];
#pragma unroll
        for (int t = 0; t < 2; t++) {
            int j = lane + t * 32;
            float vv = (h1[t] - mean) * inv * gg[j] + gb[j];
            hh[t] = fmaxf(vv, 0.f);
        }
        float lg[3];
#pragma unroll
        for (int c = 0; c < 3; c++) {
            float acc = hh[0] * W2[c * 64 + lane] + hh[1] * W2[c * 64 + lane + 32];
#pragma unroll
            for (int off = 16; off; off >>= 1) acc += __shfl_xor_sync(0xffffffffu, acc, off);
            lg[c] = acc + b2[c];
        }
        if (lane == 0) {
            float m = fmaxf(lg[0], fmaxf(lg[1], lg[2]));
            float e0 = expf(lg[0] - m), e1 = expf(lg[1] - m), e2 = expf(lg[2] - m);
            float inv_s = 1.f / (e0 + e1 + e2);
            g_w3[h * 3 + 0] = e0 * inv_s;
            g_w3[h * 3 + 1] = e1 * inv_s;
            g_w3[h * 3 + 2] = e2 * inv_s;
        }
        return;
    }

#define ASM(b, r) (&pool[((b) * 16 + (r)) * 136])
#define BSM(b, r) (&pool[6528 + ((b) * 16 + (r)) * 72])
    const int h = hb >> 2, b = hb & 3;
    const int base = hb * Nn_;
    const int g = lane >> 2, q4 = lane & 3;
    const int m0 = ks * (Nn_ / KSPLIT);

    const float* fk = g_f + (size_t)ROWS * DIM;
    const float* fv = g_f + 2 * (size_t)ROWS * DIM;

    float acc[9][4];
#pragma unroll
    for (int j = 0; j < 9; j++)
#pragma unroll
        for (int c = 0; c < 4; c++) acc[j][c] = 0.f;

    const int srow = tid >> 4;
    const int dc = (tid & 15) * 4;
    const int auxr = tid >> 3, auxs = tid & 7;   // aux row loaders (tid<128)

    auto store_chunk = [&](int sb, float4 vv, float4 kk, float ki, float xv) {
        float* ar = ASM(sb, srow) + 2 * dc;
        ar[0] = vv.x; ar[1] = t32f(ki*vv.x);
        ar[2] = vv.y; ar[3] = t32f(ki*vv.y);
        ar[4] = vv.z; ar[5] = t32f(ki*vv.z);
        ar[6] = vv.w; ar[7] = t32f(ki*vv.w);
        *(float4*)(BSM(sb, srow) + dc) = kk;
        if (tid < 128) BSM(sb, auxr)[64 + auxs] = xv;
    };
    auto load_chunk = [&](int k0, float4& vv, float4& kk, float& ki, float& xv) {
        int m = m0 + k0 + srow;
        vv = *(const float4*)(fv + (size_t)(b*Nn_ + m)*DIM + h*DH + dc);
        kk = *(const float4*)(fk + (size_t)(b*Nn_ + m)*DIM + h*DH + dc);
        ki = g_kinv[base + m];
        xv = 0.f;
        if (tid < 128) {
            int mm = m0 + k0 + auxr;
            if (auxs == 0) xv = t32f(g_kvar [base + mm]);
            else if (auxs == 1) xv = t32f(g_kmean[base + mm]);
        }
    };

    const int L = (Nn_ / KSPLIT) / 16;   // 8 chunks

    // prologue: chunk0 -> smem[0]; Rcur = chunk1
    {
        float4 vv, kk; float ki, xv;
        load_chunk(0, vv, kk, ki, xv);
        store_chunk(0, vv, kk, ki, xv);
    }
    float4 vvC, kkC; float kiC = 0.f, xvC = 0.f;
    load_chunk(16, vvC, kkC, kiC, xvC);
    __syncthreads();

    for (int j = 0; j < L; j++) {
        // issue chunk j+2 loads (in flight across this and next compute)
        float4 vvN, kkN; float kiN = 0.f, xvN = 0.f;
        if (j + 2 < L) load_chunk((j + 2) * 16, vvN, kkN, kiN, xvN);
        // compute chunk j
        const int cb = j % 3;
#pragma unroll
        for (int ks8 = 0; ks8 < 16; ks8 += 8) {
            unsigned af[4];
            const int mr = warp * 16 + g;
            af[0] = __float_as_uint(ASM(cb, ks8 + q4)[mr]);
            af[1] = __float_as_uint(ASM(cb, ks8 + q4)[mr + 8]);
            af[2] = __float_as_uint(ASM(cb, ks8 + 4 + q4)[mr]);
            af[3] = __float_as_uint(ASM(cb, ks8 + 4 + q4)[mr + 8]);
#pragma unroll
            for (int nt = 0; nt < 9; nt++) {
                unsigned bf[2];
                bf[0] = __float_as_uint(BSM(cb, ks8 + q4)[nt * 8 + g]);
                bf[1] = __float_as_uint(BSM(cb, ks8 + 4 + q4)[nt * 8 + g]);
                mma8(acc[nt], af, bf);
            }
        }
        // store chunk j+1 (Rcur)
        if (j + 1 < L) store_chunk((j + 1) % 3, vvC, kkC, kiC, xvC);
        __syncthreads();
        vvC = vvN; kkC = kkN; kiC = kiN; xvC = xvN;
    }

    const int row0 = warp * 16 + g;
#pragma unroll
    for (int nt = 0; nt < 9; nt++) {
        const int col = nt * 8 + 2 * q4;
        atomicAdd(&g_Mr[hb][row0][col],         acc[nt][0]);
        atomicAdd(&g_Mr[hb][row0][col + 1],     acc[nt][1]);
        atomicAdd(&g_Mr[hb][row0 + 8][col],     acc[nt][2]);
        atomicAdd(&g_Mr[hb][row0 + 8][col + 1], acc[nt][3]);
    }
#undef ASM
#undef BSM
}

// ================ pgemm: single smem fill (K=64), one barrier ================
__global__ void __launch_bounds__(256) pgemm_kernel()
{
    extern __shared__ float psm[];
    float* As = psm;                 // [64][136] (k-major, row minor)
    float* Bs = psm + 64 * 136;      // [64][136]
    const int tid = threadIdx.x;
    const int lane = tid & 31, warp = tid >> 5;
    const int wm = (warp >> 2) * 64, wn = (warp & 3) * 32;
    const int hb = blockIdx.y, h = hb >> 2, b = hb & 3;
    const int q0 = blockIdx.x * 128;
    const int base = hb * Nn_;
    const int g = lane >> 2, q4 = lane & 3;

    const float* fq = g_f;

    float acc[4][4][4];
#pragma unroll
    for (int i = 0; i < 4; i++)
#pragma unroll
        for (int j = 0; j < 4; j++)
#pragma unroll
            for (int c = 0; c < 4; c++) acc[i][j][c] = 0.f;

    const int srow = tid >> 1, skc = (tid & 1) * 8;
    const float* Apt = fq + (size_t)(b * Nn_ + q0 + srow) * DIM + h * DH + skc;
    const float* Wpt = &g_Mr[hb][srow][skc];

    // ---- single fill: all K=64 (all loads independent, one latency exposure)
#pragma unroll
    for (int k0 = 0; k0 < DH; k0 += 16) {
        float4 a0 = *(const float4*)(Apt + k0);
        float4 a1 = *(const float4*)(Apt + k0 + 4);
        float4 w0 = *(const float4*)(Wpt + k0);
        float4 w1 = *(const float4*)(Wpt + k0 + 4);
        float* ac = &As[(k0 + skc) * 136 + srow];
        ac[0*136] = a0.x; ac[1*136] = a0.y; ac[2*136] = a0.z; ac[3*136] = a0.w;
        ac[4*136] = a1.x; ac[5*136] = a1.y; ac[6*136] = a1.z; ac[7*136] = a1.w;
        float* bc = &Bs[(k0 + skc) * 136 + srow];
        bc[0*136] = t32f(w0.x); bc[1*136] = t32f(w0.y); bc[2*136] = t32f(w0.z); bc[3*136] = t32f(w0.w);
        bc[4*136] = t32f(w1.x); bc[5*136] = t32f(w1.y); bc[6*136] = t32f(w1.z); bc[7*136] = t32f(w1.w);
    }
    __syncthreads();

#pragma unroll
    for (int ks = 0; ks < DH; ks += 8) {
        unsigned af[4][4], bf[4][2];
#pragma unroll
        for (int mt = 0; mt < 4; mt++) {
            int mr = wm + mt * 16 + g;
            af[mt][0] = __float_as_uint(As[(ks + q4) * 136 + mr]);
            af[mt][1] = __float_as_uint(As[(ks + q4) * 136 + mr + 8]);
            af[mt][2] = __float_as_uint(As[(ks + 4 + q4) * 136 + mr]);
            af[mt][3] = __float_as_uint(As[(ks + 4 + q4) * 136 + mr + 8]);
        }
#pragma unroll
        for (int nt = 0; nt < 4; nt++) {
            int nc = wn + nt * 8 + g;
            bf[nt][0] = __float_as_uint(Bs[(ks + q4) * 136 + nc]);
            bf[nt][1] = __float_as_uint(Bs[(ks + 4 + q4) * 136 + nc]);
        }
#pragma unroll
        for (int mt = 0; mt < 4; mt++)
#pragma unroll
            for (int nt = 0; nt < 4; nt++)
                mma8(acc[mt][nt], af[mt], bf[nt]);
    }

    const float cw = g_w3[h * 3 + 0], covw = g_w3[h * 3 + 1], vw = g_w3[h * 3 + 2];
#pragma unroll
    for (int mt = 0; mt < 4; mt++) {
        const int row0 = q0 + wm + mt * 16 + g;
        const float qi0 = g_qinv[base + row0],     qm0 = g_qmean[base + row0],     qv0 = g_qvar[base + row0];
        const float qi1 = g_qinv[base + row0 + 8], qm1 = g_qmean[base + row0 + 8], qv1 = g_qvar[base + row0 + 8];
#pragma unroll
        for (int nt = 0; nt < 4; nt++) {
            const int col = wn + nt * 8 + 2 * q4;
            const int d = col >> 1;
            const float Skv = g_Mr[hb][col][64];
            const float Skm = g_Mr[hb][col][65];
            float o0 = cw * qi0 * acc[mt][nt][1] + (covw / DH) * acc[mt][nt][0]
                     + (vw / DH) * qv0 * Skv - covw * qm0 * Skm;
            float o1 = cw * qi1 * acc[mt][nt][3] + (covw / DH) * acc[mt][nt][2]
                     + (vw / DH) * qv1 * Skv - covw * qm1 * Skm;
            g_ao[(size_t)(b * Nn_ + row0) * DIM + h * DH + d]     = t32f(o0);
            g_ao[(size_t)(b * Nn_ + row0 + 8) * DIM + h * DH + d] = t32f(o1);
        }
    }
}

// ---------------- launch ----------------
extern "C" void kernel_launch(void* const* d_in, const int* in_sizes, int n_in,
                              void* d_out, int out_size)
{
    const float* q    = (const float*)d_in[0];
    const float* k    = (const float*)d_in[1];
    const float* v    = (const float*)d_in[2];
    const float* Win  = (const float*)d_in[3];
    const float* Wout = (const float*)d_in[4];
    const float* bout = (const float*)d_in[5];
    const float* g1   = (const float*)d_in[6];
    const float* b1n  = (const float*)d_in[7];
    const float* g2   = (const float*)d_in[8];
    const float* b2n  = (const float*)d_in[9];
    const float* Wup  = (const float*)d_in[10];
    const float* bup  = (const float*)d_in[11];
    const float* Wdn  = (const float*)d_in[12];
    const float* bdn  = (const float*)d_in[13];
    const float* wpW1 = (const float*)d_in[14];
    const float* wpb1 = (const float*)d_in[15];
    const float* wpg  = (const float*)d_in[16];
    const float* wpb  = (const float*)d_in[17];
    const float* wpW2 = (const float*)d_in[18];
    const float* wpb2 = (const float*)d_in[19];
    float* out = (float*)d_out;

    float* xn;  cudaGetSymbolAddress((void**)&xn,  g_xn);
    float* f;   cudaGetSymbolAddress((void**)&f,   g_f);
    float* ao;  cudaGetSymbolAddress((void**)&ao,  g_ao);
    float* q2;  cudaGetSymbolAddress((void**)&q2,  g_q2);
    float* xn2; cudaGetSymbolAddress((void**)&xn2, g_xn2);
    float* u;   cudaGetSymbolAddress((void**)&u,   g_u);
    float* wr;  cudaGetSymbolAddress((void**)&wr,  g_wr);

    const int smem4 = TS * (128 + 128) * 20 * 4;   // 81920 B (MT=4)
    const int smem2 = TS * (64 + 128) * 20 * 4;    // 61440 B (MT=2)
    const int psmem = 2 * 64 * 136 * 4;            // 69632 B (pgemm)
    cudaFuncSetAttribute(tmm3_kernel<4,4>, cudaFuncAttributeMaxDynamicSharedMemorySize, smem4);
    cudaFuncSetAttribute(tmm3_kernel<2,4>, cudaFuncAttributeMaxDynamicSharedMemorySize, smem4);
    cudaFuncSetAttribute(tmm3_kernel<3,2>, cudaFuncAttributeMaxDynamicSharedMemorySize, smem2);
    cudaFuncSetAttribute(pgemm_kernel,     cudaFuncAttributeMaxDynamicSharedMemorySize, psmem);

    // 1. fused LN of q,k,v (tf32 out; also zeroes g_hg/g_Mr + rounds weights)
    ln3_kernel<<<3 * ROWS / 8, 256>>>(q, k, v, g1, b1n, xn, Win, Wout, Wup, Wdn);

    // 2. fused projection + per-row stats + per-head column sums
    tmm3_kernel<4, 4><<<dim3(DIM / 128, 3 * ROWS / 128), 256, smem4>>>(
        xn, wr + WR_WIN, nullptr, nullptr, f, 3 * ROWS, DIM, DIM);

    // 3. attention: Mcat build (+ folded gating MLP block) -> pgemm
    mbuild_kernel<<<dim3(KSPLIT, HB + 1), 256>>>(wpW1, wpb1, wpg, wpb, wpW2, wpb2);
    pgemm_kernel<<<dim3(Nn_ / 128, HB), 256, psmem>>>();

    // 4. attn out proj + residual -> q2
    tmm3_kernel<3, 2><<<dim3(DIM / 128, ROWS / 64), 256, smem2>>>(
        ao, wr + WR_WOUT, bout, q, q2, ROWS, DIM, DIM);

    // 5. LN2 (tf32 out)
    ln_kernel<<<ROWS / 8, 256>>>(q2, g2, b2n, xn2);

    // 6. MLP up + gelu (tf32 out)
    tmm3_kernel<2, 4><<<dim3(MLPD / 128, ROWS / 128), 256, smem4>>>(
        xn2, wr + WR_WUP, bup, nullptr, u, ROWS, MLPD, DIM);

    // 7. MLP down + residual -> out
    tmm3_kernel<3, 2><<<dim3(DIM / 128, ROWS / 64), 256, smem2>>>(
        u, wr + WR_WDN, bdn, q2, out, ROWS, DIM, MLPD);
}